// round 1
// baseline (speedup 1.0000x reference)
#include <cuda_runtime.h>
#include <math.h>
#include <stdint.h>

// Problem constants
#define BB   4
#define NN_  1024
#define KD_  512
#define HH   8
#define MEMN 4096
#define BWN  1024
// rows of "flattened" query space
#define RQ   (BB*HH*NN_)          // 32768
#define RB   (BB*NN_)             // 4096

// ---------------- scratch (device globals; no allocation allowed) ----------------
__device__ float g_Q [(size_t)RQ * KD_];        // q projected+scaled, layout [(b,h,n), d]
__device__ float g_S [(size_t)RQ * MEMN];       // scores -> attn (512 MB)
__device__ float g_RV[(size_t)RB * (HH*KD_)];   // rv, layout [(b,n), h*VD+v]
__device__ float g_KN[(size_t)BWN * KD_];       // normalized write keys
__device__ float g_MN[(size_t)MEMN * KD_];      // normalized mem keys
__device__ float g_SIM[(size_t)BWN * MEMN];     // similarity matrix
__device__ float g_A [(size_t)BWN * KD_];       // write_keys @ Wg_top + bg
__device__ int   g_idx[BWN];

// ---------------- generic tiled SGEMM: C[M,N] = A[M,K] @ B(K,N or N,K^T) ----------------
// MODE 0: plain row-major out (optional bias over columns, then *scale)
// MODE 1: q-proj epilogue: r=b*1024+n, c=h*512+d  ->  ((b*8+h)*1024+n)*512+d
// MODE 2: AV epilogue:     r=(b*8+h)*1024+n, c=v  ->  (b*1024+n)*4096 + h*512 + v
#define BM 128
#define BN 128
#define BKK 8
#define LDT 132

template<int MODE, bool TB>
__global__ void __launch_bounds__(256)
sgemm(const float* __restrict__ A, const float* __restrict__ Bm,
      const float* __restrict__ bias, float* __restrict__ C,
      int M, int N, int K, float scale)
{
    __shared__ float As[BKK][LDT];
    __shared__ float Bs[BKK][LDT];
    const int tid = threadIdx.x;
    const int bm = blockIdx.y * BM;
    const int bn = blockIdx.x * BN;
    const int tx = tid & 15;
    const int ty = tid >> 4;

    float acc[8][8];
#pragma unroll
    for (int i = 0; i < 8; i++)
#pragma unroll
        for (int j = 0; j < 8; j++) acc[i][j] = 0.0f;

    const int arow  = tid >> 1;          // 0..127
    const int apart = (tid & 1) * 4;     // 0 or 4
    const int bnn   = (tid & 31) * 4;    // NN B load
    const int bkk   = tid >> 5;          // 0..7

    for (int k0 = 0; k0 < K; k0 += BKK) {
        // load A tile (transposed into As[k][m])
        float4 av = *reinterpret_cast<const float4*>(&A[(size_t)(bm + arow) * K + k0 + apart]);
        As[apart + 0][arow] = av.x;
        As[apart + 1][arow] = av.y;
        As[apart + 2][arow] = av.z;
        As[apart + 3][arow] = av.w;
        if (!TB) {
            float4 bv = *reinterpret_cast<const float4*>(&Bm[(size_t)(k0 + bkk) * N + bn + bnn]);
            *reinterpret_cast<float4*>(&Bs[bkk][bnn]) = bv;
        } else {
            float4 bv = *reinterpret_cast<const float4*>(&Bm[(size_t)(bn + arow) * K + k0 + apart]);
            Bs[apart + 0][arow] = bv.x;
            Bs[apart + 1][arow] = bv.y;
            Bs[apart + 2][arow] = bv.z;
            Bs[apart + 3][arow] = bv.w;
        }
        __syncthreads();
#pragma unroll
        for (int kk = 0; kk < BKK; kk++) {
            float4 a0 = *reinterpret_cast<const float4*>(&As[kk][ty * 8]);
            float4 a1 = *reinterpret_cast<const float4*>(&As[kk][ty * 8 + 4]);
            float4 b0 = *reinterpret_cast<const float4*>(&Bs[kk][tx * 8]);
            float4 b1 = *reinterpret_cast<const float4*>(&Bs[kk][tx * 8 + 4]);
            float a[8] = {a0.x, a0.y, a0.z, a0.w, a1.x, a1.y, a1.z, a1.w};
            float b[8] = {b0.x, b0.y, b0.z, b0.w, b1.x, b1.y, b1.z, b1.w};
#pragma unroll
            for (int i = 0; i < 8; i++)
#pragma unroll
                for (int j = 0; j < 8; j++) acc[i][j] += a[i] * b[j];
        }
        __syncthreads();
    }

    const int r0 = bm + ty * 8;
    const int c0 = bn + tx * 8;
#pragma unroll
    for (int i = 0; i < 8; i++) {
        const int r = r0 + i;
#pragma unroll
        for (int j = 0; j < 8; j++) {
            const int c = c0 + j;
            float v = acc[i][j];
            if (bias) v += bias[c];
            v *= scale;
            size_t dst;
            if (MODE == 0) {
                dst = (size_t)r * N + c;
            } else if (MODE == 1) {
                const int b_ = r >> 10, n_ = r & 1023;
                const int h_ = c >> 9,  d_ = c & 511;
                dst = ((size_t)((b_ * 8 + h_) * 1024 + n_) << 9) + d_;
            } else {
                const int b_ = r >> 13, h_ = (r >> 10) & 7, n_ = r & 1023;
                dst = ((size_t)(b_ * 1024 + n_) << 12) + ((size_t)h_ << 9) + c;
            }
            C[dst] = v;
        }
    }
}

// ---------------- softmax over rows of 4096 ----------------
__global__ void __launch_bounds__(256) softmax_rows(float* __restrict__ S)
{
    __shared__ float row[MEMN];
    __shared__ float red[256];
    const size_t r = blockIdx.x;
    float* p = S + r * MEMN;
    const int tid = threadIdx.x;

    float mx = -1e30f;
    for (int i = tid; i < MEMN; i += 256) { float v = p[i]; row[i] = v; mx = fmaxf(mx, v); }
    red[tid] = mx; __syncthreads();
    for (int s = 128; s > 0; s >>= 1) { if (tid < s) red[tid] = fmaxf(red[tid], red[tid + s]); __syncthreads(); }
    mx = red[0]; __syncthreads();

    float sum = 0.0f;
    for (int i = tid; i < MEMN; i += 256) { float e = expf(row[i] - mx); row[i] = e; sum += e; }
    red[tid] = sum; __syncthreads();
    for (int s = 128; s > 0; s >>= 1) { if (tid < s) red[tid] += red[tid + s]; __syncthreads(); }
    const float inv = 1.0f / red[0];
    __syncthreads();
    for (int i = tid; i < MEMN; i += 256) p[i] = row[i] * inv;
}

// ---------------- row L2-normalize (x / max(||x||, eps)) ----------------
__global__ void __launch_bounds__(256) normalize_rows(const float* __restrict__ X,
                                                      float* __restrict__ Xn)
{
    __shared__ float red[256];
    const int r = blockIdx.x, tid = threadIdx.x;
    const float* p = X + (size_t)r * KD_;
    float ss = 0.0f;
    for (int i = tid; i < KD_; i += 256) { float v = p[i]; ss += v * v; }
    red[tid] = ss; __syncthreads();
    for (int s = 128; s > 0; s >>= 1) { if (tid < s) red[tid] += red[tid + s]; __syncthreads(); }
    const float inv = 1.0f / fmaxf(sqrtf(red[0]), 1e-8f);
    for (int i = tid; i < KD_; i += 256) Xn[(size_t)r * KD_ + i] = p[i] * inv;
}

// ---------------- argmax over rows of 4096 (first-max tie-break) ----------------
__global__ void __launch_bounds__(256) argmax_rows(const float* __restrict__ S,
                                                   int* __restrict__ idx)
{
    __shared__ float rv[256];
    __shared__ int   ri[256];
    const int r = blockIdx.x, tid = threadIdx.x;
    const float* p = S + (size_t)r * MEMN;
    float bv = -1e30f; int bi = 0;
    for (int i = tid; i < MEMN; i += 256) { float v = p[i]; if (v > bv) { bv = v; bi = i; } }
    rv[tid] = bv; ri[tid] = bi; __syncthreads();
    for (int s = 128; s > 0; s >>= 1) {
        if (tid < s) {
            if (rv[tid + s] > rv[tid] || (rv[tid + s] == rv[tid] && ri[tid + s] < ri[tid])) {
                rv[tid] = rv[tid + s]; ri[tid] = ri[tid + s];
            }
        }
        __syncthreads();
    }
    if (tid == 0) idx[r] = ri[0];
}

// ---------------- per-slot sequential gated update chains ----------------
__global__ void __launch_bounds__(256) chain_update(
    const float* __restrict__ wk, const float* __restrict__ wv,
    const float* __restrict__ Wg, const float* __restrict__ Aw,
    const int*   __restrict__ idx,
    const float* __restrict__ mk, const float* __restrict__ mv,
    float* __restrict__ outK, float* __restrict__ outV)
{
    __shared__ float sK[KD_], sV[KD_];
    __shared__ int   list[BWN];
    __shared__ int   cnt;
    const int s = blockIdx.x, tid = threadIdx.x;
    if (tid == 0) cnt = 0;
    __syncthreads();
    for (int t = tid; t < BWN; t += 256)
        if (idx[t] == s) { int p = atomicAdd(&cnt, 1); list[p] = t; }
    __syncthreads();
    const int n = cnt;
    if (n == 0) return;   // copy kernel already wrote identity
    if (tid == 0) {       // small insertion sort: writes must apply in scan order
        for (int i = 1; i < n; i++) {
            int v = list[i], j = i - 1;
            while (j >= 0 && list[j] > v) { list[j + 1] = list[j]; j--; }
            list[j + 1] = v;
        }
    }
    for (int i = tid; i < KD_; i += 256) {
        sK[i] = mk[(size_t)s * KD_ + i];
        sV[i] = mv[(size_t)s * KD_ + i];
    }
    __syncthreads();

    for (int e = 0; e < n; e++) {
        const int t = list[e];
        const int j0 = tid, j1 = tid + 256;
        float a0 = Aw[(size_t)t * KD_ + j0];
        float a1 = Aw[(size_t)t * KD_ + j1];
#pragma unroll 8
        for (int r = 0; r < KD_; r++) {
            const float v = sV[r];
            const float* wrow = Wg + (size_t)(KD_ + r) * KD_;
            a0 += v * wrow[j0];
            a1 += v * wrow[j1];
        }
        const float g0 = 1.0f / (1.0f + expf(-a0));
        const float g1 = 1.0f / (1.0f + expf(-a1));
        __syncthreads();  // everyone done reading old sV
        sK[j0] = g0 * wk[(size_t)t * KD_ + j0] + (1.0f - g0) * sK[j0];
        sK[j1] = g1 * wk[(size_t)t * KD_ + j1] + (1.0f - g1) * sK[j1];
        sV[j0] = g0 * wv[(size_t)t * KD_ + j0] + (1.0f - g0) * sV[j0];
        sV[j1] = g1 * wv[(size_t)t * KD_ + j1] + (1.0f - g1) * sV[j1];
        __syncthreads();
    }
    for (int i = tid; i < KD_; i += 256) {
        outK[(size_t)s * KD_ + i] = sK[i];
        outV[(size_t)s * KD_ + i] = sV[i];
    }
}

// ---------------- launcher ----------------
extern "C" void kernel_launch(void* const* d_in, const int* in_sizes, int n_in,
                              void* d_out, int out_size)
{
    const float* queries     = (const float*)d_in[0];
    const float* write_keys  = (const float*)d_in[1];
    const float* write_vals  = (const float*)d_in[2];
    const float* mem_keys    = (const float*)d_in[3];
    const float* mem_values  = (const float*)d_in[4];
    const float* Wq          = (const float*)d_in[5];
    const float* bq          = (const float*)d_in[6];
    const float* Wvp         = (const float*)d_in[7];
    const float* bvp         = (const float*)d_in[8];
    const float* Wg          = (const float*)d_in[9];
    const float* bg          = (const float*)d_in[10];

    float* out_read = (float*)d_out;                       // [4,1024,512]
    float* out_k    = out_read + (size_t)RB * KD_;         // [4096,512]
    float* out_v    = out_k    + (size_t)MEMN * KD_;       // [4096,512]

    void *pQ, *pS, *pRV, *pKN, *pMN, *pSIM, *pA, *pIdx;
    cudaGetSymbolAddress(&pQ,  g_Q);
    cudaGetSymbolAddress(&pS,  g_S);
    cudaGetSymbolAddress(&pRV, g_RV);
    cudaGetSymbolAddress(&pKN, g_KN);
    cudaGetSymbolAddress(&pMN, g_MN);
    cudaGetSymbolAddress(&pSIM, g_SIM);
    cudaGetSymbolAddress(&pA,  g_A);
    cudaGetSymbolAddress(&pIdx, g_idx);

    const float qscale = 0.044194173824159216f;  // 1/sqrt(512)/TEMP

    // ---- write path ----
    normalize_rows<<<MEMN, 256>>>(mem_keys, (float*)pMN);
    normalize_rows<<<BWN,  256>>>(write_keys, (float*)pKN);
    sgemm<0, true ><<<dim3(MEMN / BN, BWN / BM), 256>>>((float*)pKN, (float*)pMN, nullptr,
                                                        (float*)pSIM, BWN, MEMN, KD_, 1.0f);
    argmax_rows<<<BWN, 256>>>((float*)pSIM, (int*)pIdx);
    // A = write_keys @ Wg[0:512,:] + bg   (K=512 limits B to the top rows)
    sgemm<0, false><<<dim3(KD_ / BN, BWN / BM), 256>>>(write_keys, Wg, bg,
                                                       (float*)pA, BWN, KD_, KD_, 1.0f);
    cudaMemcpyAsync(out_k, mem_keys,   (size_t)MEMN * KD_ * sizeof(float), cudaMemcpyDeviceToDevice);
    cudaMemcpyAsync(out_v, mem_values, (size_t)MEMN * KD_ * sizeof(float), cudaMemcpyDeviceToDevice);
    chain_update<<<MEMN, 256>>>(write_keys, write_vals, Wg, (float*)pA, (int*)pIdx,
                                mem_keys, mem_values, out_k, out_v);

    // ---- read path ----
    // q-proj (+bias, *1/sqrt(512)), remapped to [(b,h,n), d]
    sgemm<1, false><<<dim3((HH * KD_) / BN, RB / BM), 256>>>(queries, Wq, bq,
                                                             (float*)pQ, RB, HH * KD_, KD_, qscale);
    // scores = Q @ mem_keys^T
    sgemm<0, true ><<<dim3(MEMN / BN, RQ / BM), 256>>>((float*)pQ, mem_keys, nullptr,
                                                       (float*)pS, RQ, MEMN, KD_, 1.0f);
    softmax_rows<<<RQ, 256>>>((float*)pS);
    // rv = attn @ mem_values, remapped to [(b,n), h*512+v]
    sgemm<2, false><<<dim3(KD_ / BN, RQ / BM), 256>>>((float*)pS, mem_values, nullptr,
                                                      (float*)pRV, RQ, KD_, MEMN, 1.0f);
    // read_out = rv @ Wvp + bvp
    sgemm<0, false><<<dim3(KD_ / BN, RB / BM), 256>>>((float*)pRV, Wvp, bvp,
                                                      out_read, RB, KD_, HH * KD_, 1.0f);
}

// round 3
// speedup vs baseline: 1.8676x; 1.8676x over previous
#include <cuda_runtime.h>
#include <cuda_bf16.h>
#include <math.h>
#include <stdint.h>

// ---------------- problem constants ----------------
#define BB   4
#define NN_  1024
#define KD_  512
#define HH   8
#define MEMN 4096
#define BWN  1024
#define RQ   (BB*HH*NN_)          // 32768
#define RB   (BB*NN_)             // 4096

// ---------------- scratch (device globals) ----------------
__device__ float g_Q  [(size_t)RQ * KD_];
__device__ float g_S  [(size_t)RQ * MEMN];       // 512 MB scores->attn
__device__ float g_RV [(size_t)RB * (HH*KD_)];
__device__ float g_KN [(size_t)BWN * KD_];
__device__ float g_MN [(size_t)MEMN * KD_];
__device__ float g_SIM[(size_t)BWN * MEMN];
__device__ float g_A  [(size_t)BWN * KD_];
__device__ int   g_idx[BWN];
__device__ float g_WqT [(size_t)(HH*KD_) * KD_];   // Wq^T  [4096,512]
__device__ float g_MVT [(size_t)KD_ * MEMN];       // mem_values^T [512,4096]
__device__ float g_WvpT[(size_t)KD_ * (HH*KD_)];   // Wvp^T [512,4096]
__device__ float g_WgT [(size_t)KD_ * KD_];        // (Wg top)^T [512,512]

// ---------------- mma / ldmatrix helpers (portable PTX, sm_80+) ----------------
__device__ __forceinline__ uint32_t smem_to_u32(const void* p) {
    uint32_t a;
    asm("{ .reg .u64 t; cvta.to.shared.u64 t, %1; cvt.u32.u64 %0, t; }" : "=r"(a) : "l"(p));
    return a;
}
__device__ __forceinline__ void ldsm4(uint32_t* r, uint32_t addr) {
    asm volatile("ldmatrix.sync.aligned.m8n8.x4.shared.b16 {%0,%1,%2,%3}, [%4];"
                 : "=r"(r[0]), "=r"(r[1]), "=r"(r[2]), "=r"(r[3]) : "r"(addr));
}
__device__ __forceinline__ void mma16816(float* c, const uint32_t* a, const uint32_t* b) {
    asm volatile(
        "mma.sync.aligned.m16n8k16.row.col.f32.bf16.bf16.f32 "
        "{%0,%1,%2,%3}, {%4,%5,%6,%7}, {%8,%9}, {%0,%1,%2,%3};"
        : "+f"(c[0]), "+f"(c[1]), "+f"(c[2]), "+f"(c[3])
        : "r"(a[0]), "r"(a[1]), "r"(a[2]), "r"(a[3]), "r"(b[0]), "r"(b[1]));
}

__device__ __forceinline__ void splitpack(float x, float y, uint32_t& h, uint32_t& l) {
    __nv_bfloat16 hx = __float2bfloat16(x), hy = __float2bfloat16(y);
    float rx = x - __bfloat162float(hx), ry = y - __bfloat162float(hy);
    __nv_bfloat16 lx = __float2bfloat16(rx), ly = __float2bfloat16(ry);
    h = (uint32_t)__bfloat16_as_ushort(hx) | ((uint32_t)__bfloat16_as_ushort(hy) << 16);
    l = (uint32_t)__bfloat16_as_ushort(lx) | ((uint32_t)__bfloat16_as_ushort(ly) << 16);
}

// ---------------- tensor GEMM: C[M,N] = A[M,K] @ B[N,K]^T (fp32 in/out) ----------------
// split-bf16 3-term:  acc = Ahi*Bhi + Ahi*Blo + Alo*Bhi   (fp32 accumulate in regs)
// smem row layout per matrix row: [ hi(32 bf16) | lo(32 bf16) | pad(8) ] = 144 bytes
#define TM 128
#define TN 128
#define KC 32
#define ROWB 144                          // bytes per smem row
#define STAGE_HALF (TM * ROWB)            // 18432 B  (A plane or B plane)
#define STAGE_BYTES (2 * STAGE_HALF)      // 36864 B
#define DYN_BYTES  (2 * STAGE_BYTES)      // 73728 B

template<int MODE>
__device__ __forceinline__ size_t dst_of(int r, int c, int N) {
    if (MODE == 0) return (size_t)r * N + c;
    if (MODE == 1) {   // qproj: r=b*1024+n, c=h*512+d -> ((b*8+h)*1024+n)*512+d
        const int b_ = r >> 10, n_ = r & 1023, h_ = c >> 9, d_ = c & 511;
        return ((size_t)((b_ * 8 + h_) * 1024 + n_) << 9) + d_;
    }
    // MODE 2: AV: r=(b*8+h)*1024+n, c=v -> (b*1024+n)*4096 + h*512 + v
    const int b_ = r >> 13, h_ = (r >> 10) & 7, n_ = r & 1023;
    return ((size_t)(b_ * 1024 + n_) << 12) + ((size_t)h_ << 9) + c;
}

__device__ __forceinline__ void sts16(char* plane, int row, int half, const float4* r) {
    uint32_t h[8], l[8];
#pragma unroll
    for (int i = 0; i < 4; i++) {
        splitpack(r[i].x, r[i].y, h[2*i],   l[2*i]);
        splitpack(r[i].z, r[i].w, h[2*i+1], l[2*i+1]);
    }
    char* rp = plane + row * ROWB + half * 32;
    *reinterpret_cast<uint4*>(rp)      = make_uint4(h[0], h[1], h[2], h[3]);
    *reinterpret_cast<uint4*>(rp + 16) = make_uint4(h[4], h[5], h[6], h[7]);
    *reinterpret_cast<uint4*>(rp + 64) = make_uint4(l[0], l[1], l[2], l[3]);
    *reinterpret_cast<uint4*>(rp + 80) = make_uint4(l[4], l[5], l[6], l[7]);
}

template<int MODE>
__global__ void __launch_bounds__(256, 1)
mgemm(const float* __restrict__ A, const float* __restrict__ B,
      const float* __restrict__ bias, float* __restrict__ C,
      int M, int N, int K, float scale)
{
    extern __shared__ char sm[];
    const uint32_t smem_u = smem_to_u32(sm);
    const int tid = threadIdx.x;
    const int lane = tid & 31, wid = tid >> 5;
    const int bm = blockIdx.y * TM, bn = blockIdx.x * TN;
    const int wm = (wid >> 1) * 32;     // 4 warps along M
    const int wn = (wid & 1) * 64;      // 2 warps along N

    float acc[2][8][4];
#pragma unroll
    for (int i = 0; i < 2; i++)
#pragma unroll
        for (int j = 0; j < 8; j++)
#pragma unroll
            for (int k = 0; k < 4; k++) acc[i][j][k] = 0.0f;

    // global-load assignment: 256 threads; thread -> (row 0..127, half 0/1 of 32 floats)
    const int lr = tid >> 1;
    const int lh = tid & 1;
    const float* aptr = A + (size_t)(bm + lr) * K + lh * 16;
    const float* bptr = B + (size_t)(bn + lr) * K + lh * 16;

    float4 ra[4], rb[4];
    const int NC = K / KC;

    // prologue: chunk 0
#pragma unroll
    for (int i = 0; i < 4; i++) {
        ra[i] = reinterpret_cast<const float4*>(aptr)[i];
        rb[i] = reinterpret_cast<const float4*>(bptr)[i];
    }
    sts16(sm,              lr, lh, ra);
    sts16(sm + STAGE_HALF, lr, lh, rb);
    __syncthreads();

    const int mr = lane & 7, msel = lane >> 3;

    for (int c = 0; c < NC; c++) {
        if (c + 1 < NC) {
            const float* ap = aptr + (c + 1) * KC;
            const float* bp = bptr + (c + 1) * KC;
#pragma unroll
            for (int i = 0; i < 4; i++) {
                ra[i] = reinterpret_cast<const float4*>(ap)[i];
                rb[i] = reinterpret_cast<const float4*>(bp)[i];
            }
        }
        const uint32_t abase = smem_u + (c & 1) * STAGE_BYTES;
        const uint32_t bbase = abase + STAGE_HALF;
#pragma unroll
        for (int p = 0; p < 3; p++) {
            const int pa = (p == 2) ? 32 : 0;   // A plane: hi,hi,lo
            const int pb = (p == 1) ? 32 : 0;   // B plane: hi,lo,hi
#pragma unroll
            for (int ks = 0; ks < 32; ks += 16) {
                uint32_t af[2][4], bf[8][2];
#pragma unroll
                for (int mi = 0; mi < 2; mi++) {
                    const int row = wm + mi * 16 + ((msel & 1) << 3) + mr;
                    const int col = pa + ks + ((msel >> 1) << 3);
                    ldsm4(af[mi], abase + row * ROWB + col * 2);
                }
#pragma unroll
                for (int g = 0; g < 4; g++) {
                    const int nrow = wn + g * 16 + ((msel >> 1) << 3) + mr;
                    const int col  = pb + ks + ((msel & 1) << 3);
                    uint32_t t[4];
                    ldsm4(t, bbase + nrow * ROWB + col * 2);
                    bf[2*g][0] = t[0]; bf[2*g][1] = t[1];
                    bf[2*g+1][0] = t[2]; bf[2*g+1][1] = t[3];
                }
#pragma unroll
                for (int mi = 0; mi < 2; mi++)
#pragma unroll
                    for (int nb = 0; nb < 8; nb++)
                        mma16816(acc[mi][nb], af[mi], bf[nb]);
            }
        }
        if (c + 1 < NC) {
            char* st = sm + ((c + 1) & 1) * STAGE_BYTES;
            sts16(st,              lr, lh, ra);
            sts16(st + STAGE_HALF, lr, lh, rb);
        }
        __syncthreads();
    }

    // epilogue: write fragments directly (float2 per pair; 32B sectors fully used)
    const int group = lane >> 2, tig = lane & 3;
#pragma unroll
    for (int mi = 0; mi < 2; mi++) {
        const int r_lo = bm + wm + mi * 16 + group;
#pragma unroll
        for (int nb = 0; nb < 8; nb++) {
            const int col = bn + wn + nb * 8 + tig * 2;
            float b0 = 0.0f, b1 = 0.0f;
            if (bias) { b0 = bias[col]; b1 = bias[col + 1]; }
            float2 v0, v1;
            v0.x = (acc[mi][nb][0] + b0) * scale;
            v0.y = (acc[mi][nb][1] + b1) * scale;
            v1.x = (acc[mi][nb][2] + b0) * scale;
            v1.y = (acc[mi][nb][3] + b1) * scale;
            *reinterpret_cast<float2*>(&C[dst_of<MODE>(r_lo,     col, N)]) = v0;
            *reinterpret_cast<float2*>(&C[dst_of<MODE>(r_lo + 8, col, N)]) = v1;
        }
    }
}

// ---------------- transpose: out[c][r] = in[r][c] ----------------
__global__ void __launch_bounds__(256) transpose_k(const float* __restrict__ in,
                                                   float* __restrict__ out, int R, int C)
{
    __shared__ float t[32][33];
    const int c0 = blockIdx.x * 32, r0 = blockIdx.y * 32;
    const int x = threadIdx.x & 31, y = threadIdx.x >> 5;
#pragma unroll
    for (int i = 0; i < 32; i += 8) t[y + i][x] = in[(size_t)(r0 + y + i) * C + c0 + x];
    __syncthreads();
#pragma unroll
    for (int i = 0; i < 32; i += 8) out[(size_t)(c0 + y + i) * R + r0 + x] = t[x][y + i];
}

// ---------------- softmax over rows of 4096 ----------------
__global__ void __launch_bounds__(256) softmax_rows(float* __restrict__ S)
{
    __shared__ float row[MEMN];
    __shared__ float red[256];
    const size_t r = blockIdx.x;
    float* p = S + r * MEMN;
    const int tid = threadIdx.x;
    float mx = -1e30f;
    for (int i = tid; i < MEMN; i += 256) { float v = p[i]; row[i] = v; mx = fmaxf(mx, v); }
    red[tid] = mx; __syncthreads();
    for (int s = 128; s > 0; s >>= 1) { if (tid < s) red[tid] = fmaxf(red[tid], red[tid + s]); __syncthreads(); }
    mx = red[0]; __syncthreads();
    float sum = 0.0f;
    for (int i = tid; i < MEMN; i += 256) { float e = expf(row[i] - mx); row[i] = e; sum += e; }
    red[tid] = sum; __syncthreads();
    for (int s = 128; s > 0; s >>= 1) { if (tid < s) red[tid] += red[tid + s]; __syncthreads(); }
    const float inv = 1.0f / red[0];
    __syncthreads();
    for (int i = tid; i < MEMN; i += 256) p[i] = row[i] * inv;
}

// ---------------- row L2-normalize ----------------
__global__ void __launch_bounds__(256) normalize_rows(const float* __restrict__ X,
                                                      float* __restrict__ Xn)
{
    __shared__ float red[256];
    const int r = blockIdx.x, tid = threadIdx.x;
    const float* p = X + (size_t)r * KD_;
    float ss = 0.0f;
    for (int i = tid; i < KD_; i += 256) { float v = p[i]; ss += v * v; }
    red[tid] = ss; __syncthreads();
    for (int s = 128; s > 0; s >>= 1) { if (tid < s) red[tid] += red[tid + s]; __syncthreads(); }
    const float inv = 1.0f / fmaxf(sqrtf(red[0]), 1e-8f);
    for (int i = tid; i < KD_; i += 256) Xn[(size_t)r * KD_ + i] = p[i] * inv;
}

// ---------------- argmax over rows of 4096 ----------------
__global__ void __launch_bounds__(256) argmax_rows(const float* __restrict__ S,
                                                   int* __restrict__ idx)
{
    __shared__ float rv[256];
    __shared__ int   ri[256];
    const int r = blockIdx.x, tid = threadIdx.x;
    const float* p = S + (size_t)r * MEMN;
    float bv = -1e30f; int bi = 0;
    for (int i = tid; i < MEMN; i += 256) { float v = p[i]; if (v > bv) { bv = v; bi = i; } }
    rv[tid] = bv; ri[tid] = bi; __syncthreads();
    for (int s = 128; s > 0; s >>= 1) {
        if (tid < s) {
            if (rv[tid + s] > rv[tid] || (rv[tid + s] == rv[tid] && ri[tid + s] < ri[tid])) {
                rv[tid] = rv[tid + s]; ri[tid] = ri[tid + s];
            }
        }
        __syncthreads();
    }
    if (tid == 0) idx[r] = ri[0];
}

// ---------------- per-slot sequential gated update chains ----------------
__global__ void __launch_bounds__(256) chain_update(
    const float* __restrict__ wk, const float* __restrict__ wv,
    const float* __restrict__ Wg, const float* __restrict__ Aw,
    const int*   __restrict__ idx,
    const float* __restrict__ mk, const float* __restrict__ mv,
    float* __restrict__ outK, float* __restrict__ outV)
{
    __shared__ float sK[KD_], sV[KD_];
    __shared__ int   list[BWN];
    __shared__ int   cnt;
    const int s = blockIdx.x, tid = threadIdx.x;
    if (tid == 0) cnt = 0;
    __syncthreads();
    for (int t = tid; t < BWN; t += 256)
        if (idx[t] == s) { int p = atomicAdd(&cnt, 1); list[p] = t; }
    __syncthreads();
    const int n = cnt;
    if (n == 0) return;
    if (tid == 0) {
        for (int i = 1; i < n; i++) {
            int v = list[i], j = i - 1;
            while (j >= 0 && list[j] > v) { list[j + 1] = list[j]; j--; }
            list[j + 1] = v;
        }
    }
    for (int i = tid; i < KD_; i += 256) {
        sK[i] = mk[(size_t)s * KD_ + i];
        sV[i] = mv[(size_t)s * KD_ + i];
    }
    __syncthreads();
    for (int e = 0; e < n; e++) {
        const int t = list[e];
        const int j0 = tid, j1 = tid + 256;
        float a0 = Aw[(size_t)t * KD_ + j0];
        float a1 = Aw[(size_t)t * KD_ + j1];
#pragma unroll 8
        for (int r = 0; r < KD_; r++) {
            const float v = sV[r];
            const float* wrow = Wg + (size_t)(KD_ + r) * KD_;
            a0 += v * wrow[j0];
            a1 += v * wrow[j1];
        }
        const float g0 = 1.0f / (1.0f + expf(-a0));
        const float g1 = 1.0f / (1.0f + expf(-a1));
        __syncthreads();
        sK[j0] = g0 * wk[(size_t)t * KD_ + j0] + (1.0f - g0) * sK[j0];
        sK[j1] = g1 * wk[(size_t)t * KD_ + j1] + (1.0f - g1) * sK[j1];
        sV[j0] = g0 * wv[(size_t)t * KD_ + j0] + (1.0f - g0) * sV[j0];
        sV[j1] = g1 * wv[(size_t)t * KD_ + j1] + (1.0f - g1) * sV[j1];
        __syncthreads();
    }
    for (int i = tid; i < KD_; i += 256) {
        outK[(size_t)s * KD_ + i] = sK[i];
        outV[(size_t)s * KD_ + i] = sV[i];
    }
}

// ---------------- launcher ----------------
extern "C" void kernel_launch(void* const* d_in, const int* in_sizes, int n_in,
                              void* d_out, int out_size)
{
    const float* queries    = (const float*)d_in[0];
    const float* write_keys = (const float*)d_in[1];
    const float* write_vals = (const float*)d_in[2];
    const float* mem_keys   = (const float*)d_in[3];
    const float* mem_values = (const float*)d_in[4];
    const float* Wq         = (const float*)d_in[5];
    const float* bq         = (const float*)d_in[6];
    const float* Wvp        = (const float*)d_in[7];
    const float* bvp        = (const float*)d_in[8];
    const float* Wg         = (const float*)d_in[9];
    const float* bg         = (const float*)d_in[10];

    float* out_read = (float*)d_out;
    float* out_k    = out_read + (size_t)RB * KD_;
    float* out_v    = out_k    + (size_t)MEMN * KD_;

    void *pQ, *pS, *pRV, *pKN, *pMN, *pSIM, *pA, *pIdx, *pWqT, *pMVT, *pWvpT, *pWgT;
    cudaGetSymbolAddress(&pQ,   g_Q);
    cudaGetSymbolAddress(&pS,   g_S);
    cudaGetSymbolAddress(&pRV,  g_RV);
    cudaGetSymbolAddress(&pKN,  g_KN);
    cudaGetSymbolAddress(&pMN,  g_MN);
    cudaGetSymbolAddress(&pSIM, g_SIM);
    cudaGetSymbolAddress(&pA,   g_A);
    cudaGetSymbolAddress(&pIdx, g_idx);
    cudaGetSymbolAddress(&pWqT, g_WqT);
    cudaGetSymbolAddress(&pMVT, g_MVT);
    cudaGetSymbolAddress(&pWvpT, g_WvpT);
    cudaGetSymbolAddress(&pWgT, g_WgT);

    cudaFuncSetAttribute(mgemm<0>, cudaFuncAttributeMaxDynamicSharedMemorySize, DYN_BYTES);
    cudaFuncSetAttribute(mgemm<1>, cudaFuncAttributeMaxDynamicSharedMemorySize, DYN_BYTES);
    cudaFuncSetAttribute(mgemm<2>, cudaFuncAttributeMaxDynamicSharedMemorySize, DYN_BYTES);

    const float qscale = 0.044194173824159216f;  // 1/sqrt(512)/TEMP

    // transposes to put second operands in [N,K]
    transpose_k<<<dim3((HH*KD_)/32, KD_/32), 256>>>(Wq, (float*)pWqT, KD_, HH*KD_);
    transpose_k<<<dim3(KD_/32, MEMN/32),     256>>>(mem_values, (float*)pMVT, MEMN, KD_);
    transpose_k<<<dim3(KD_/32, (HH*KD_)/32), 256>>>(Wvp, (float*)pWvpT, HH*KD_, KD_);
    transpose_k<<<dim3(KD_/32, KD_/32),      256>>>(Wg, (float*)pWgT, KD_, KD_);

    // ---- write path ----
    normalize_rows<<<MEMN, 256>>>(mem_keys, (float*)pMN);
    normalize_rows<<<BWN,  256>>>(write_keys, (float*)pKN);
    mgemm<0><<<dim3(MEMN/TN, BWN/TM), 256, DYN_BYTES>>>((float*)pKN, (float*)pMN, nullptr,
                                                        (float*)pSIM, BWN, MEMN, KD_, 1.0f);
    argmax_rows<<<BWN, 256>>>((float*)pSIM, (int*)pIdx);
    mgemm<0><<<dim3(KD_/TN, BWN/TM), 256, DYN_BYTES>>>(write_keys, (float*)pWgT, bg,
                                                       (float*)pA, BWN, KD_, KD_, 1.0f);
    cudaMemcpyAsync(out_k, mem_keys,   (size_t)MEMN * KD_ * sizeof(float), cudaMemcpyDeviceToDevice);
    cudaMemcpyAsync(out_v, mem_values, (size_t)MEMN * KD_ * sizeof(float), cudaMemcpyDeviceToDevice);
    chain_update<<<MEMN, 256>>>(write_keys, write_vals, Wg, (float*)pA, (int*)pIdx,
                                mem_keys, mem_values, out_k, out_v);

    // ---- read path ----
    mgemm<1><<<dim3((HH*KD_)/TN, RB/TM), 256, DYN_BYTES>>>(queries, (float*)pWqT, bq,
                                                           (float*)pQ, RB, HH*KD_, KD_, qscale);
    mgemm<0><<<dim3(MEMN/TN, RQ/TM), 256, DYN_BYTES>>>((float*)pQ, mem_keys, nullptr,
                                                       (float*)pS, RQ, MEMN, KD_, 1.0f);
    softmax_rows<<<RQ, 256>>>((float*)pS);
    mgemm<2><<<dim3(KD_/TN, RQ/TM), 256, DYN_BYTES>>>((float*)pS, (float*)pMVT, nullptr,
                                                      (float*)pRV, RQ, KD_, MEMN, 1.0f);
    mgemm<0><<<dim3(KD_/TN, RB/TM), 256, DYN_BYTES>>>((float*)pRV, (float*)pWvpT, bvp,
                                                      out_read, RB, KD_, HH*KD_, 1.0f);
}

// round 4
// speedup vs baseline: 1.8994x; 1.0170x over previous
#include <cuda_runtime.h>
#include <cuda_bf16.h>
#include <math.h>
#include <stdint.h>

#define BB   4
#define NN_  1024
#define KD_  512
#define HH   8
#define MEMN 4096
#define BWN  1024
#define RQ   (BB*HH*NN_)
#define RB   (BB*NN_)

typedef __nv_bfloat16 bf16;

__device__ float g_S  [(size_t)RQ * MEMN];
__device__ float g_SIM[(size_t)BWN * MEMN];
__device__ float g_A  [(size_t)BWN * KD_];
__device__ int   g_idx[BWN];
__device__ bf16 g_QIh[(size_t)RB * KD_],        g_QIl[(size_t)RB * KD_];   // queries split
__device__ bf16 g_Qh [(size_t)RQ * KD_],        g_Ql [(size_t)RQ * KD_];   // projected q planes
__device__ bf16 g_Ph [(size_t)RQ * MEMN],       g_Pl [(size_t)RQ * MEMN];
__device__ bf16 g_RVh[(size_t)RB * (HH*KD_)],   g_RVl[(size_t)RB * (HH*KD_)];
__device__ bf16 g_KNh[(size_t)BWN * KD_],       g_KNl[(size_t)BWN * KD_];
__device__ bf16 g_MNh[(size_t)MEMN * KD_],      g_MNl[(size_t)MEMN * KD_];
__device__ bf16 g_MKh[(size_t)MEMN * KD_],      g_MKl[(size_t)MEMN * KD_];
__device__ bf16 g_WKh[(size_t)BWN * KD_],       g_WKl[(size_t)BWN * KD_];
__device__ bf16 g_WqTh[(size_t)(HH*KD_) * KD_], g_WqTl[(size_t)(HH*KD_) * KD_];
__device__ bf16 g_MVTh[(size_t)KD_ * MEMN],     g_MVTl[(size_t)KD_ * MEMN];
__device__ bf16 g_WvpTh[(size_t)KD_ * (HH*KD_)],g_WvpTl[(size_t)KD_ * (HH*KD_)];
__device__ bf16 g_WgTh[(size_t)KD_ * KD_],      g_WgTl[(size_t)KD_ * KD_];

__device__ __forceinline__ uint32_t smem_to_u32(const void* p) {
    uint32_t a;
    asm("{ .reg .u64 t; cvta.to.shared.u64 t, %1; cvt.u32.u64 %0, t; }" : "=r"(a) : "l"(p));
    return a;
}
__device__ __forceinline__ void ldsm4(uint32_t* r, uint32_t addr) {
    asm volatile("ldmatrix.sync.aligned.m8n8.x4.shared.b16 {%0,%1,%2,%3}, [%4];"
                 : "=r"(r[0]), "=r"(r[1]), "=r"(r[2]), "=r"(r[3]) : "r"(addr));
}
__device__ __forceinline__ void mma16816(float* c, const uint32_t* a, const uint32_t* b) {
    asm volatile(
        "mma.sync.aligned.m16n8k16.row.col.f32.bf16.bf16.f32 "
        "{%0,%1,%2,%3}, {%4,%5,%6,%7}, {%8,%9}, {%0,%1,%2,%3};"
        : "+f"(c[0]), "+f"(c[1]), "+f"(c[2]), "+f"(c[3])
        : "r"(a[0]), "r"(a[1]), "r"(a[2]), "r"(a[3]), "r"(b[0]), "r"(b[1]));
}
__device__ __forceinline__ void cp16(uint32_t dst, const void* src) {
    asm volatile("cp.async.cg.shared.global [%0], [%1], 16;" :: "r"(dst), "l"(src));
}
#define CP_COMMIT() asm volatile("cp.async.commit_group;" ::: "memory")
#define CP_WAIT1()  asm volatile("cp.async.wait_group 1;" ::: "memory")

__device__ __forceinline__ void splitpack(float x, float y, uint32_t& h, uint32_t& l) {
    bf16 hx = __float2bfloat16(x), hy = __float2bfloat16(y);
    float rx = x - __bfloat162float(hx), ry = y - __bfloat162float(hy);
    bf16 lx = __float2bfloat16(rx), ly = __float2bfloat16(ry);
    h = (uint32_t)__bfloat16_as_ushort(hx) | ((uint32_t)__bfloat16_as_ushort(hy) << 16);
    l = (uint32_t)__bfloat16_as_ushort(lx) | ((uint32_t)__bfloat16_as_ushort(ly) << 16);
}

#define TM 256
#define TN 128
#define KC 32
#define ROWB 144
#define STAGE ((TM + TN) * ROWB)
#define DYN_BYTES (2 * STAGE)

template<int MODE>
__device__ __forceinline__ size_t dst_of(int r, int c, int N) {
    if (MODE == 0) return (size_t)r * N + c;
    if (MODE == 1) {
        const int b_ = r >> 10, n_ = r & 1023, h_ = c >> 9, d_ = c & 511;
        return ((size_t)((b_ * 8 + h_) * 1024 + n_) << 9) + d_;
    }
    const int b_ = r >> 13, h_ = (r >> 10) & 7, n_ = r & 1023;
    return ((size_t)(b_ * 1024 + n_) << 12) + ((size_t)h_ << 9) + c;
}

template<int MODE>
__global__ void __launch_bounds__(256, 1)
bgemm(const bf16* __restrict__ Ah, const bf16* __restrict__ Al,
      const bf16* __restrict__ Bh, const bf16* __restrict__ Bl,
      const float* __restrict__ bias, float* __restrict__ C,
      bf16* __restrict__ Ch, bf16* __restrict__ Cl,
      int M, int N, int K, float scale)
{
    extern __shared__ char sm[];
    const uint32_t smem_u = smem_to_u32(sm);
    const int tid = threadIdx.x;
    const int lane = tid & 31, wid = tid >> 5;
    const int bm = blockIdx.y * TM, bn = blockIdx.x * TN;
    const int wm = (wid >> 1) * 64, wn = (wid & 1) * 64;

    float acc[4][8][4];
#pragma unroll
    for (int i = 0; i < 4; i++)
#pragma unroll
        for (int j = 0; j < 8; j++)
#pragma unroll
            for (int k = 0; k < 4; k++) acc[i][j][k] = 0.0f;

    const int NC = K / KC;

    auto load_chunk = [&](int c, int st) {
        const int k0 = c * KC;
        const uint32_t sb = smem_u + st * STAGE;
#pragma unroll
        for (int u = 0; u < 3; u++) {
            const int unit = tid + u * 256;
            const int r = (unit & 511) >> 1, pl = unit & 1;
            const bf16* src;
            uint32_t dst;
            if (unit < 512) {
                src = (pl ? Al : Ah) + (size_t)(bm + r) * K + k0;
                dst = sb + r * ROWB + pl * 64;
            } else {
                src = (pl ? Bl : Bh) + (size_t)(bn + r) * K + k0;
                dst = sb + (TM + r) * ROWB + pl * 64;
            }
#pragma unroll
            for (int i = 0; i < 4; i++) cp16(dst + i * 16, src + i * 8);
        }
    };

    load_chunk(0, 0); CP_COMMIT();
    load_chunk(1, 1); CP_COMMIT();

    const int mr = lane & 7, msel = lane >> 3;
    const int aro = ((msel & 1) << 3) + mr;
    const int aco = (msel >> 1) << 3;
    const int bro = ((msel >> 1) << 3) + mr;
    const int bco = (msel & 1) << 3;

    for (int c = 0; c < NC; c++) {
        CP_WAIT1();
        __syncthreads();
        const uint32_t base = smem_u + (c & 1) * STAGE;
#pragma unroll
        for (int ks = 0; ks < 2; ks++) {
            uint32_t ah[4][4], al[4][4], bh[8][2], bl[8][2];
            const int colA = (ks * 16 + aco) * 2;
            const int colB = (ks * 16 + bco) * 2;
#pragma unroll
            for (int mi = 0; mi < 4; mi++) {
                const uint32_t ad = base + (wm + mi * 16 + aro) * ROWB + colA;
                ldsm4(ah[mi], ad);
                ldsm4(al[mi], ad + 64);
            }
#pragma unroll
            for (int g = 0; g < 4; g++) {
                const uint32_t bd = base + (TM + wn + g * 16 + bro) * ROWB + colB;
                uint32_t t[4];
                ldsm4(t, bd);
                bh[2*g][0] = t[0]; bh[2*g][1] = t[1];
                bh[2*g+1][0] = t[2]; bh[2*g+1][1] = t[3];
                ldsm4(t, bd + 64);
                bl[2*g][0] = t[0]; bl[2*g][1] = t[1];
                bl[2*g+1][0] = t[2]; bl[2*g+1][1] = t[3];
            }
#pragma unroll
            for (int mi = 0; mi < 4; mi++)
#pragma unroll
                for (int nb = 0; nb < 8; nb++) {
                    mma16816(acc[mi][nb], ah[mi], bh[nb]);
                    mma16816(acc[mi][nb], ah[mi], bl[nb]);
                    mma16816(acc[mi][nb], al[mi], bh[nb]);
                }
        }
        __syncthreads();
        if (c + 2 < NC) load_chunk(c + 2, c & 1);
        CP_COMMIT();
    }

    const int group = lane >> 2, tig = lane & 3;
#pragma unroll
    for (int mi = 0; mi < 4; mi++) {
        const int r_lo = bm + wm + mi * 16 + group;
#pragma unroll
        for (int nb = 0; nb < 8; nb++) {
            const int col = bn + wn + nb * 8 + tig * 2;
            float b0 = 0.0f, b1 = 0.0f;
            if (bias) { b0 = bias[col]; b1 = bias[col + 1]; }
            float v00 = (acc[mi][nb][0] + b0) * scale;
            float v01 = (acc[mi][nb][1] + b1) * scale;
            float v10 = (acc[mi][nb][2] + b0) * scale;
            float v11 = (acc[mi][nb][3] + b1) * scale;
            if (MODE == 0) {
                *reinterpret_cast<float2*>(&C[dst_of<0>(r_lo,     col, N)]) = make_float2(v00, v01);
                *reinterpret_cast<float2*>(&C[dst_of<0>(r_lo + 8, col, N)]) = make_float2(v10, v11);
            } else {
                uint32_t h0, l0, h1, l1;
                splitpack(v00, v01, h0, l0);
                splitpack(v10, v11, h1, l1);
                const size_t d0 = dst_of<MODE>(r_lo, col, N);
                const size_t d1 = dst_of<MODE>(r_lo + 8, col, N);
                *reinterpret_cast<uint32_t*>(&Ch[d0]) = h0;
                *reinterpret_cast<uint32_t*>(&Cl[d0]) = l0;
                *reinterpret_cast<uint32_t*>(&Ch[d1]) = h1;
                *reinterpret_cast<uint32_t*>(&Cl[d1]) = l1;
            }
        }
    }
}

__global__ void __launch_bounds__(256) transpose_split(const float* __restrict__ in,
                                                       bf16* __restrict__ oh, bf16* __restrict__ ol,
                                                       int R, int C)
{
    __shared__ float t[32][33];
    const int c0 = blockIdx.x * 32, r0 = blockIdx.y * 32;
    const int x = threadIdx.x & 31, y = threadIdx.x >> 5;
#pragma unroll
    for (int i = 0; i < 32; i += 8) t[y + i][x] = in[(size_t)(r0 + y + i) * C + c0 + x];
    __syncthreads();
#pragma unroll
    for (int i = 0; i < 32; i += 8) {
        float v = t[x][y + i];
        bf16 h = __float2bfloat16(v);
        bf16 l = __float2bfloat16(v - __bfloat162float(h));
        const size_t d = (size_t)(c0 + y + i) * R + r0 + x;
        oh[d] = h; ol[d] = l;
    }
}

__global__ void __launch_bounds__(256) split_f32(const float* __restrict__ in,
                                                 bf16* __restrict__ oh, bf16* __restrict__ ol, int n2)
{
    int i = (blockIdx.x * 256 + threadIdx.x) * 2;
    if (i < n2) {
        float2 v = *reinterpret_cast<const float2*>(&in[i]);
        uint32_t h, l;
        splitpack(v.x, v.y, h, l);
        *reinterpret_cast<uint32_t*>(&oh[i]) = h;
        *reinterpret_cast<uint32_t*>(&ol[i]) = l;
    }
}

__global__ void __launch_bounds__(256) softmax_split(const float* __restrict__ S,
                                                     bf16* __restrict__ Ph, bf16* __restrict__ Pl)
{
    __shared__ float row[MEMN];
    __shared__ float red[256];
    const size_t r = blockIdx.x;
    const float* p = S + r * MEMN;
    const int tid = threadIdx.x;
    float mx = -1e30f;
    for (int i = tid * 2; i < MEMN; i += 512) {
        float2 v = *reinterpret_cast<const float2*>(&p[i]);
        row[i] = v.x; row[i+1] = v.y;
        mx = fmaxf(mx, fmaxf(v.x, v.y));
    }
    red[tid] = mx; __syncthreads();
    for (int s = 128; s > 0; s >>= 1) { if (tid < s) red[tid] = fmaxf(red[tid], red[tid + s]); __syncthreads(); }
    mx = red[0]; __syncthreads();
    float sum = 0.0f;
    for (int i = tid; i < MEMN; i += 256) { float e = expf(row[i] - mx); row[i] = e; sum += e; }
    red[tid] = sum; __syncthreads();
    for (int s = 128; s > 0; s >>= 1) { if (tid < s) red[tid] += red[tid + s]; __syncthreads(); }
    const float inv = 1.0f / red[0];
    __syncthreads();
    for (int i = tid * 2; i < MEMN; i += 512) {
        uint32_t h, l;
        splitpack(row[i] * inv, row[i+1] * inv, h, l);
        *reinterpret_cast<uint32_t*>(&Ph[r * MEMN + i]) = h;
        *reinterpret_cast<uint32_t*>(&Pl[r * MEMN + i]) = l;
    }
}

__global__ void __launch_bounds__(256) normalize_split(const float* __restrict__ X,
                                                       bf16* __restrict__ oh, bf16* __restrict__ ol)
{
    __shared__ float red[256];
    const int r = blockIdx.x, tid = threadIdx.x;
    const float* p = X + (size_t)r * KD_;
    float ss = 0.0f;
    for (int i = tid; i < KD_; i += 256) { float v = p[i]; ss += v * v; }
    red[tid] = ss; __syncthreads();
    for (int s = 128; s > 0; s >>= 1) { if (tid < s) red[tid] += red[tid + s]; __syncthreads(); }
    const float inv = 1.0f / fmaxf(sqrtf(red[0]), 1e-8f);
    for (int i = tid * 2; i < KD_; i += 512) {
        uint32_t h, l;
        splitpack(p[i] * inv, p[i+1] * inv, h, l);
        *reinterpret_cast<uint32_t*>(&oh[(size_t)r * KD_ + i]) = h;
        *reinterpret_cast<uint32_t*>(&ol[(size_t)r * KD_ + i]) = l;
    }
}

__global__ void __launch_bounds__(256) argmax_rows(const float* __restrict__ S,
                                                   int* __restrict__ idx)
{
    __shared__ float rv[256];
    __shared__ int   ri[256];
    const int r = blockIdx.x, tid = threadIdx.x;
    const float* p = S + (size_t)r * MEMN;
    float bv = -1e30f; int bi = 0;
    for (int i = tid; i < MEMN; i += 256) { float v = p[i]; if (v > bv) { bv = v; bi = i; } }
    rv[tid] = bv; ri[tid] = bi; __syncthreads();
    for (int s = 128; s > 0; s >>= 1) {
        if (tid < s) {
            if (rv[tid + s] > rv[tid] || (rv[tid + s] == rv[tid] && ri[tid + s] < ri[tid])) {
                rv[tid] = rv[tid + s]; ri[tid] = ri[tid + s];
            }
        }
        __syncthreads();
    }
    if (tid == 0) idx[r] = ri[0];
}

__global__ void __launch_bounds__(256) chain_update(
    const float* __restrict__ wk, const float* __restrict__ wv,
    const float* __restrict__ Wg, const float* __restrict__ Aw,
    const int*   __restrict__ idx,
    const float* __restrict__ mk, const float* __restrict__ mv,
    float* __restrict__ outK, float* __restrict__ outV)
{
    __shared__ float sK[KD_], sV[KD_];
    __shared__ int   list[BWN];
    __shared__ int   cnt;
    const int s = blockIdx.x, tid = threadIdx.x;
    if (tid == 0) cnt = 0;
    __syncthreads();
    for (int t = tid; t < BWN; t += 256)
        if (idx[t] == s) { int p = atomicAdd(&cnt, 1); list[p] = t; }
    __syncthreads();
    const int n = cnt;
    if (n == 0) return;
    if (tid == 0) {
        for (int i = 1; i < n; i++) {
            int v = list[i], j = i - 1;
            while (j >= 0 && list[j] > v) { list[j + 1] = list[j]; j--; }
            list[j + 1] = v;
        }
    }
    for (int i = tid; i < KD_; i += 256) {
        sK[i] = mk[(size_t)s * KD_ + i];
        sV[i] = mv[(size_t)s * KD_ + i];
    }
    __syncthreads();
    for (int e = 0; e < n; e++) {
        const int t = list[e];
        const int j0 = tid, j1 = tid + 256;
        float a0 = Aw[(size_t)t * KD_ + j0];
        float a1 = Aw[(size_t)t * KD_ + j1];
#pragma unroll 8
        for (int r = 0; r < KD_; r++) {
            const float v = sV[r];
            const float* wrow = Wg + (size_t)(KD_ + r) * KD_;
            a0 += v * wrow[j0];
            a1 += v * wrow[j1];
        }
        const float g0 = 1.0f / (1.0f + expf(-a0));
        const float g1 = 1.0f / (1.0f + expf(-a1));
        __syncthreads();
        sK[j0] = g0 * wk[(size_t)t * KD_ + j0] + (1.0f - g0) * sK[j0];
        sK[j1] = g1 * wk[(size_t)t * KD_ + j1] + (1.0f - g1) * sK[j1];
        sV[j0] = g0 * wv[(size_t)t * KD_ + j0] + (1.0f - g0) * sV[j0];
        sV[j1] = g1 * wv[(size_t)t * KD_ + j1] + (1.0f - g1) * sV[j1];
        __syncthreads();
    }
    for (int i = tid; i < KD_; i += 256) {
        outK[(size_t)s * KD_ + i] = sK[i];
        outV[(size_t)s * KD_ + i] = sV[i];
    }
}

extern "C" void kernel_launch(void* const* d_in, const int* in_sizes, int n_in,
                              void* d_out, int out_size)
{
    const float* queries    = (const float*)d_in[0];
    const float* write_keys = (const float*)d_in[1];
    const float* write_vals = (const float*)d_in[2];
    const float* mem_keys   = (const float*)d_in[3];
    const float* mem_values = (const float*)d_in[4];
    const float* Wq         = (const float*)d_in[5];
    const float* bq         = (const float*)d_in[6];
    const float* Wvp        = (const float*)d_in[7];
    const float* bvp        = (const float*)d_in[8];
    const float* Wg         = (const float*)d_in[9];
    const float* bg         = (const float*)d_in[10];

    float* out_read = (float*)d_out;
    float* out_k    = out_read + (size_t)RB * KD_;
    float* out_v    = out_k    + (size_t)MEMN * KD_;

    void *pS, *pSIM, *pA, *pIdx, *pQIh, *pQIl, *pQh, *pQl, *pPh, *pPl, *pRVh, *pRVl;
    void *pKNh, *pKNl, *pMNh, *pMNl, *pMKh, *pMKl, *pWKh, *pWKl;
    void *pWqTh, *pWqTl, *pMVTh, *pMVTl, *pWvpTh, *pWvpTl, *pWgTh, *pWgTl;
    cudaGetSymbolAddress(&pS, g_S);       cudaGetSymbolAddress(&pSIM, g_SIM);
    cudaGetSymbolAddress(&pA, g_A);       cudaGetSymbolAddress(&pIdx, g_idx);
    cudaGetSymbolAddress(&pQIh, g_QIh);   cudaGetSymbolAddress(&pQIl, g_QIl);
    cudaGetSymbolAddress(&pQh, g_Qh);     cudaGetSymbolAddress(&pQl, g_Ql);
    cudaGetSymbolAddress(&pPh, g_Ph);     cudaGetSymbolAddress(&pPl, g_Pl);
    cudaGetSymbolAddress(&pRVh, g_RVh);   cudaGetSymbolAddress(&pRVl, g_RVl);
    cudaGetSymbolAddress(&pKNh, g_KNh);   cudaGetSymbolAddress(&pKNl, g_KNl);
    cudaGetSymbolAddress(&pMNh, g_MNh);   cudaGetSymbolAddress(&pMNl, g_MNl);
    cudaGetSymbolAddress(&pMKh, g_MKh);   cudaGetSymbolAddress(&pMKl, g_MKl);
    cudaGetSymbolAddress(&pWKh, g_WKh);   cudaGetSymbolAddress(&pWKl, g_WKl);
    cudaGetSymbolAddress(&pWqTh, g_WqTh); cudaGetSymbolAddress(&pWqTl, g_WqTl);
    cudaGetSymbolAddress(&pMVTh, g_MVTh); cudaGetSymbolAddress(&pMVTl, g_MVTl);
    cudaGetSymbolAddress(&pWvpTh, g_WvpTh); cudaGetSymbolAddress(&pWvpTl, g_WvpTl);
    cudaGetSymbolAddress(&pWgTh, g_WgTh); cudaGetSymbolAddress(&pWgTl, g_WgTl);

    cudaFuncSetAttribute(bgemm<0>, cudaFuncAttributeMaxDynamicSharedMemorySize, DYN_BYTES);
    cudaFuncSetAttribute(bgemm<1>, cudaFuncAttributeMaxDynamicSharedMemorySize, DYN_BYTES);
    cudaFuncSetAttribute(bgemm<2>, cudaFuncAttributeMaxDynamicSharedMemorySize, DYN_BYTES);

    const float qscale = 0.044194173824159216f;

    transpose_split<<<dim3((HH*KD_)/32, KD_/32), 256>>>(Wq, (bf16*)pWqTh, (bf16*)pWqTl, KD_, HH*KD_);
    transpose_split<<<dim3(KD_/32, MEMN/32),     256>>>(mem_values, (bf16*)pMVTh, (bf16*)pMVTl, MEMN, KD_);
    transpose_split<<<dim3(KD_/32, (HH*KD_)/32), 256>>>(Wvp, (bf16*)pWvpTh, (bf16*)pWvpTl, HH*KD_, KD_);
    transpose_split<<<dim3(KD_/32, KD_/32),      256>>>(Wg, (bf16*)pWgTh, (bf16*)pWgTl, KD_, KD_);
    split_f32<<<(MEMN*KD_/2 + 255)/256, 256>>>(mem_keys,   (bf16*)pMKh, (bf16*)pMKl, MEMN*KD_);
    split_f32<<<(BWN*KD_/2 + 255)/256,  256>>>(write_keys, (bf16*)pWKh, (bf16*)pWKl, BWN*KD_);
    split_f32<<<(RB*KD_/2 + 255)/256,   256>>>(queries,    (bf16*)pQIh, (bf16*)pQIl, RB*KD_);
    normalize_split<<<MEMN, 256>>>(mem_keys,   (bf16*)pMNh, (bf16*)pMNl);
    normalize_split<<<BWN,  256>>>(write_keys, (bf16*)pKNh, (bf16*)pKNl);

    // ---- write path ----
    bgemm<0><<<dim3(MEMN/TN, BWN/TM), 256, DYN_BYTES>>>(
        (bf16*)pKNh, (bf16*)pKNl, (bf16*)pMNh, (bf16*)pMNl,
        nullptr, (float*)pSIM, nullptr, nullptr, BWN, MEMN, KD_, 1.0f);
    argmax_rows<<<BWN, 256>>>((float*)pSIM, (int*)pIdx);
    bgemm<0><<<dim3(KD_/TN, BWN/TM), 256, DYN_BYTES>>>(
        (bf16*)pWKh, (bf16*)pWKl, (bf16*)pWgTh, (bf16*)pWgTl,
        bg, (float*)pA, nullptr, nullptr, BWN, KD_, KD_, 1.0f);
    cudaMemcpyAsync(out_k, mem_keys,   (size_t)MEMN * KD_ * sizeof(float), cudaMemcpyDeviceToDevice);
    cudaMemcpyAsync(out_v, mem_values, (size_t)MEMN * KD_ * sizeof(float), cudaMemcpyDeviceToDevice);
    chain_update<<<MEMN, 256>>>(write_keys, write_vals, Wg, (float*)pA, (int*)pIdx,
                                mem_keys, mem_values, out_k, out_v);

    // ---- read path ----
    bgemm<1><<<dim3((HH*KD_)/TN, RB/TM), 256, DYN_BYTES>>>(
        (bf16*)pQIh, (bf16*)pQIl, (bf16*)pWqTh, (bf16*)pWqTl,
        bq, nullptr, (bf16*)pQh, (bf16*)pQl, RB, HH*KD_, KD_, qscale);
    bgemm<0><<<dim3(MEMN/TN, RQ/TM), 256, DYN_BYTES>>>(
        (bf16*)pQh, (bf16*)pQl, (bf16*)pMKh, (bf16*)pMKl,
        nullptr, (float*)pS, nullptr, nullptr, RQ, MEMN, KD_, 1.0f);
    softmax_split<<<RQ, 256>>>((float*)pS, (bf16*)pPh, (bf16*)pPl);
    bgemm<2><<<dim3(KD_/TN, RQ/TM), 256, DYN_BYTES>>>(
        (bf16*)pPh, (bf16*)pPl, (bf16*)pMVTh, (bf16*)pMVTl,
        nullptr, nullptr, (bf16*)pRVh, (bf16*)pRVl, RQ, KD_, MEMN, 1.0f);
    bgemm<0><<<dim3(KD_/TN, RB/TM), 256, DYN_BYTES>>>(
        (bf16*)pRVh, (bf16*)pRVl, (bf16*)pWvpTh, (bf16*)pWvpTl,
        bvp, out_read, nullptr, nullptr, RB, KD_, HH*KD_, 1.0f);
}

// round 5
// speedup vs baseline: 3.9561x; 2.0828x over previous
#include <cuda_runtime.h>
#include <cuda_bf16.h>
#include <cuda_fp16.h>
#include <math.h>
#include <stdint.h>

#define BB   4
#define NN_  1024
#define KD_  512
#define HH   8
#define MEMN 4096
#define BWN  1024
#define RQ   (BB*HH*NN_)
#define RB   (BB*NN_)

typedef __nv_bfloat16 bf16;

// ---------------- scratch ----------------
__device__ float  g_S  [(size_t)RQ * MEMN];          // scores fp32
__device__ float  g_SIM[(size_t)BWN * MEMN];
__device__ float  g_A  [(size_t)BWN * KD_];
__device__ int    g_idx[BWN];
__device__ __half g_Q16[(size_t)RQ * KD_];           // projected q (fp16)
__device__ __half g_P16[(size_t)RQ * MEMN];          // attn*512 (fp16)
__device__ __half g_MK16[(size_t)MEMN * KD_];        // mem_keys fp16
__device__ __half g_MVT16[(size_t)KD_ * MEMN];       // mem_values^T fp16
__device__ bf16 g_QIh[(size_t)RB * KD_],        g_QIl[(size_t)RB * KD_];
__device__ bf16 g_RVh[(size_t)RB * (HH*KD_)],   g_RVl[(size_t)RB * (HH*KD_)];
__device__ bf16 g_KNh[(size_t)BWN * KD_],       g_KNl[(size_t)BWN * KD_];
__device__ bf16 g_MNh[(size_t)MEMN * KD_],      g_MNl[(size_t)MEMN * KD_];
__device__ bf16 g_WKh[(size_t)BWN * KD_],       g_WKl[(size_t)BWN * KD_];
__device__ bf16 g_WqTh[(size_t)(HH*KD_) * KD_], g_WqTl[(size_t)(HH*KD_) * KD_];
__device__ bf16 g_WvpTh[(size_t)KD_ * (HH*KD_)],g_WvpTl[(size_t)KD_ * (HH*KD_)];
__device__ bf16 g_WgTh[(size_t)KD_ * KD_],      g_WgTl[(size_t)KD_ * KD_];

// ---------------- helpers ----------------
__device__ __forceinline__ uint32_t smem_to_u32(const void* p) {
    uint32_t a;
    asm("{ .reg .u64 t; cvta.to.shared.u64 t, %1; cvt.u32.u64 %0, t; }" : "=r"(a) : "l"(p));
    return a;
}
__device__ __forceinline__ void ldsm4(uint32_t* r, uint32_t addr) {
    asm volatile("ldmatrix.sync.aligned.m8n8.x4.shared.b16 {%0,%1,%2,%3}, [%4];"
                 : "=r"(r[0]), "=r"(r[1]), "=r"(r[2]), "=r"(r[3]) : "r"(addr));
}
__device__ __forceinline__ void mma_bf(float* c, const uint32_t* a, const uint32_t* b) {
    asm volatile(
        "mma.sync.aligned.m16n8k16.row.col.f32.bf16.bf16.f32 "
        "{%0,%1,%2,%3}, {%4,%5,%6,%7}, {%8,%9}, {%0,%1,%2,%3};"
        : "+f"(c[0]), "+f"(c[1]), "+f"(c[2]), "+f"(c[3])
        : "r"(a[0]), "r"(a[1]), "r"(a[2]), "r"(a[3]), "r"(b[0]), "r"(b[1]));
}
__device__ __forceinline__ void mma_fp(float* c, const uint32_t* a, const uint32_t* b) {
    asm volatile(
        "mma.sync.aligned.m16n8k16.row.col.f32.f16.f16.f32 "
        "{%0,%1,%2,%3}, {%4,%5,%6,%7}, {%8,%9}, {%0,%1,%2,%3};"
        : "+f"(c[0]), "+f"(c[1]), "+f"(c[2]), "+f"(c[3])
        : "r"(a[0]), "r"(a[1]), "r"(a[2]), "r"(a[3]), "r"(b[0]), "r"(b[1]));
}
__device__ __forceinline__ void cp16(uint32_t dst, const void* src) {
    asm volatile("cp.async.cg.shared.global [%0], [%1], 16;" :: "r"(dst), "l"(src));
}
#define CP_COMMIT() asm volatile("cp.async.commit_group;" ::: "memory")
#define CP_WAIT1()  asm volatile("cp.async.wait_group 1;" ::: "memory")

__device__ __forceinline__ void splitpack(float x, float y, uint32_t& h, uint32_t& l) {
    bf16 hx = __float2bfloat16(x), hy = __float2bfloat16(y);
    float rx = x - __bfloat162float(hx), ry = y - __bfloat162float(hy);
    bf16 lx = __float2bfloat16(rx), ly = __float2bfloat16(ry);
    h = (uint32_t)__bfloat16_as_ushort(hx) | ((uint32_t)__bfloat16_as_ushort(hy) << 16);
    l = (uint32_t)__bfloat16_as_ushort(lx) | ((uint32_t)__bfloat16_as_ushort(ly) << 16);
}

#define TM 256
#define TN 128
#define ROWB 144

template<int MODE>
__device__ __forceinline__ size_t dst_of(int r, int c, int N) {
    if (MODE == 0) return (size_t)r * N + c;
    if (MODE == 1) {
        const int b_ = r >> 10, n_ = r & 1023, h_ = c >> 9, d_ = c & 511;
        return ((size_t)((b_ * 8 + h_) * 1024 + n_) << 9) + d_;
    }
    const int b_ = r >> 13, h_ = (r >> 10) & 7, n_ = r & 1023;
    return ((size_t)(b_ * 1024 + n_) << 12) + ((size_t)h_ << 9) + c;
}

// ================= 3-term split-bf16 GEMM (KC=32) =================
// MODE 0 -> fp32 C ; MODE 1 -> fp16 C16 with qproj remap
#define KC3 32
#define STAGE3 ((TM + TN) * ROWB)
#define DYN3 (2 * STAGE3)

template<int MODE>
__global__ void __launch_bounds__(256, 1)
bgemm3(const bf16* __restrict__ Ah, const bf16* __restrict__ Al,
       const bf16* __restrict__ Bh, const bf16* __restrict__ Bl,
       const float* __restrict__ bias, float* __restrict__ C,
       __half* __restrict__ C16, int M, int N, int K, float scale)
{
    extern __shared__ char sm[];
    const uint32_t smem_u = smem_to_u32(sm);
    const int tid = threadIdx.x;
    const int lane = tid & 31, wid = tid >> 5;
    const int bm = blockIdx.y * TM, bn = blockIdx.x * TN;
    const int wm = (wid >> 1) * 64, wn = (wid & 1) * 64;

    float acc[4][8][4];
#pragma unroll
    for (int i = 0; i < 4; i++)
#pragma unroll
        for (int j = 0; j < 8; j++)
#pragma unroll
            for (int k = 0; k < 4; k++) acc[i][j][k] = 0.0f;

    const int NC = K / KC3;

    auto load_chunk = [&](int c, int st) {
        const int k0 = c * KC3;
        const uint32_t sb = smem_u + st * STAGE3;
#pragma unroll
        for (int u = 0; u < 3; u++) {
            const int unit = tid + u * 256;
            const int r = (unit & 511) >> 1, pl = unit & 1;
            const bf16* src;
            uint32_t dst;
            if (unit < 512) {
                src = (pl ? Al : Ah) + (size_t)(bm + r) * K + k0;
                dst = sb + r * ROWB + pl * 64;
            } else {
                src = (pl ? Bl : Bh) + (size_t)(bn + r) * K + k0;
                dst = sb + (TM + r) * ROWB + pl * 64;
            }
#pragma unroll
            for (int i = 0; i < 4; i++) cp16(dst + i * 16, src + i * 8);
        }
    };

    load_chunk(0, 0); CP_COMMIT();
    load_chunk(1, 1); CP_COMMIT();

    const int mr = lane & 7, msel = lane >> 3;
    const int aro = ((msel & 1) << 3) + mr;
    const int aco = (msel >> 1) << 3;
    const int bro = ((msel >> 1) << 3) + mr;
    const int bco = (msel & 1) << 3;

    for (int c = 0; c < NC; c++) {
        CP_WAIT1();
        __syncthreads();
        const uint32_t base = smem_u + (c & 1) * STAGE3;
#pragma unroll
        for (int ks = 0; ks < 2; ks++) {
            uint32_t ah[4][4], al[4][4], bh[8][2], bl[8][2];
            const int colA = (ks * 16 + aco) * 2;
            const int colB = (ks * 16 + bco) * 2;
#pragma unroll
            for (int mi = 0; mi < 4; mi++) {
                const uint32_t ad = base + (wm + mi * 16 + aro) * ROWB + colA;
                ldsm4(ah[mi], ad);
                ldsm4(al[mi], ad + 64);
            }
#pragma unroll
            for (int g = 0; g < 4; g++) {
                const uint32_t bd = base + (TM + wn + g * 16 + bro) * ROWB + colB;
                uint32_t t[4];
                ldsm4(t, bd);
                bh[2*g][0] = t[0]; bh[2*g][1] = t[1];
                bh[2*g+1][0] = t[2]; bh[2*g+1][1] = t[3];
                ldsm4(t, bd + 64);
                bl[2*g][0] = t[0]; bl[2*g][1] = t[1];
                bl[2*g+1][0] = t[2]; bl[2*g+1][1] = t[3];
            }
#pragma unroll
            for (int mi = 0; mi < 4; mi++)
#pragma unroll
                for (int nb = 0; nb < 8; nb++) {
                    mma_bf(acc[mi][nb], ah[mi], bh[nb]);
                    mma_bf(acc[mi][nb], ah[mi], bl[nb]);
                    mma_bf(acc[mi][nb], al[mi], bh[nb]);
                }
        }
        __syncthreads();
        if (c + 2 < NC) load_chunk(c + 2, c & 1);
        CP_COMMIT();
    }

    const int group = lane >> 2, tig = lane & 3;
#pragma unroll
    for (int mi = 0; mi < 4; mi++) {
        const int r_lo = bm + wm + mi * 16 + group;
#pragma unroll
        for (int nb = 0; nb < 8; nb++) {
            const int col = bn + wn + nb * 8 + tig * 2;
            float b0 = 0.0f, b1 = 0.0f;
            if (bias) { b0 = bias[col]; b1 = bias[col + 1]; }
            float v00 = (acc[mi][nb][0] + b0) * scale;
            float v01 = (acc[mi][nb][1] + b1) * scale;
            float v10 = (acc[mi][nb][2] + b0) * scale;
            float v11 = (acc[mi][nb][3] + b1) * scale;
            if (MODE == 0) {
                *reinterpret_cast<float2*>(&C[dst_of<0>(r_lo,     col, N)]) = make_float2(v00, v01);
                *reinterpret_cast<float2*>(&C[dst_of<0>(r_lo + 8, col, N)]) = make_float2(v10, v11);
            } else {
                *reinterpret_cast<__half2*>(&C16[dst_of<1>(r_lo,     col, N)]) = __floats2half2_rn(v00, v01);
                *reinterpret_cast<__half2*>(&C16[dst_of<1>(r_lo + 8, col, N)]) = __floats2half2_rn(v10, v11);
            }
        }
    }
}

// ================= single-term fp16 GEMM (KC=64) =================
// MODE 0 -> fp32 C ; MODE 2 -> split-bf16 planes with AV remap
#define KC1 64
#define STAGE1 ((TM + TN) * ROWB)
#define DYN1 (2 * STAGE1)

template<int MODE>
__global__ void __launch_bounds__(256, 1)
hgemm1(const __half* __restrict__ A, const __half* __restrict__ B,
       float* __restrict__ C, bf16* __restrict__ Ch, bf16* __restrict__ Cl,
       int M, int N, int K, float scale)
{
    extern __shared__ char sm[];
    const uint32_t smem_u = smem_to_u32(sm);
    const int tid = threadIdx.x;
    const int lane = tid & 31, wid = tid >> 5;
    const int bm = blockIdx.y * TM, bn = blockIdx.x * TN;
    const int wm = (wid >> 1) * 64, wn = (wid & 1) * 64;

    float acc[4][8][4];
#pragma unroll
    for (int i = 0; i < 4; i++)
#pragma unroll
        for (int j = 0; j < 8; j++)
#pragma unroll
            for (int k = 0; k < 4; k++) acc[i][j][k] = 0.0f;

    const int NC = K / KC1;

    auto load_chunk = [&](int c, int st) {
        const int k0 = c * KC1;
        const uint32_t sb = smem_u + st * STAGE1;
#pragma unroll
        for (int u = 0; u < 12; u++) {
            const int unit = tid + u * 256;        // 0..3071
            const int r = unit >> 3, seg = unit & 7;
            const __half* src;
            uint32_t dst = sb + r * ROWB + seg * 16;
            if (r < TM) src = A + (size_t)(bm + r) * K + k0 + seg * 8;
            else        src = B + (size_t)(bn + (r - TM)) * K + k0 + seg * 8;
            cp16(dst, src);
        }
    };

    load_chunk(0, 0); CP_COMMIT();
    load_chunk(1, 1); CP_COMMIT();

    const int mr = lane & 7, msel = lane >> 3;
    const int aro = ((msel & 1) << 3) + mr;
    const int aco = (msel >> 1) << 3;
    const int bro = ((msel >> 1) << 3) + mr;
    const int bco = (msel & 1) << 3;

    for (int c = 0; c < NC; c++) {
        CP_WAIT1();
        __syncthreads();
        const uint32_t base = smem_u + (c & 1) * STAGE1;
#pragma unroll
        for (int ks = 0; ks < 4; ks++) {
            uint32_t ah[4][4], bh[8][2];
            const int colA = (ks * 16 + aco) * 2;
            const int colB = (ks * 16 + bco) * 2;
#pragma unroll
            for (int mi = 0; mi < 4; mi++)
                ldsm4(ah[mi], base + (wm + mi * 16 + aro) * ROWB + colA);
#pragma unroll
            for (int g = 0; g < 4; g++) {
                uint32_t t[4];
                ldsm4(t, base + (TM + wn + g * 16 + bro) * ROWB + colB);
                bh[2*g][0] = t[0]; bh[2*g][1] = t[1];
                bh[2*g+1][0] = t[2]; bh[2*g+1][1] = t[3];
            }
#pragma unroll
            for (int mi = 0; mi < 4; mi++)
#pragma unroll
                for (int nb = 0; nb < 8; nb++)
                    mma_fp(acc[mi][nb], ah[mi], bh[nb]);
        }
        __syncthreads();
        if (c + 2 < NC) load_chunk(c + 2, c & 1);
        CP_COMMIT();
    }

    const int group = lane >> 2, tig = lane & 3;
#pragma unroll
    for (int mi = 0; mi < 4; mi++) {
        const int r_lo = bm + wm + mi * 16 + group;
#pragma unroll
        for (int nb = 0; nb < 8; nb++) {
            const int col = bn + wn + nb * 8 + tig * 2;
            float v00 = acc[mi][nb][0] * scale;
            float v01 = acc[mi][nb][1] * scale;
            float v10 = acc[mi][nb][2] * scale;
            float v11 = acc[mi][nb][3] * scale;
            if (MODE == 0) {
                *reinterpret_cast<float2*>(&C[dst_of<0>(r_lo,     col, N)]) = make_float2(v00, v01);
                *reinterpret_cast<float2*>(&C[dst_of<0>(r_lo + 8, col, N)]) = make_float2(v10, v11);
            } else {
                uint32_t h0, l0, h1, l1;
                splitpack(v00, v01, h0, l0);
                splitpack(v10, v11, h1, l1);
                const size_t d0 = dst_of<2>(r_lo, col, N);
                const size_t d1 = dst_of<2>(r_lo + 8, col, N);
                *reinterpret_cast<uint32_t*>(&Ch[d0]) = h0;
                *reinterpret_cast<uint32_t*>(&Cl[d0]) = l0;
                *reinterpret_cast<uint32_t*>(&Ch[d1]) = h1;
                *reinterpret_cast<uint32_t*>(&Cl[d1]) = l1;
            }
        }
    }
}

// ---------------- prep kernels ----------------
__global__ void __launch_bounds__(256) transpose_split(const float* __restrict__ in,
                                                       bf16* __restrict__ oh, bf16* __restrict__ ol,
                                                       int R, int C)
{
    __shared__ float t[32][33];
    const int c0 = blockIdx.x * 32, r0 = blockIdx.y * 32;
    const int x = threadIdx.x & 31, y = threadIdx.x >> 5;
#pragma unroll
    for (int i = 0; i < 32; i += 8) t[y + i][x] = in[(size_t)(r0 + y + i) * C + c0 + x];
    __syncthreads();
#pragma unroll
    for (int i = 0; i < 32; i += 8) {
        float v = t[x][y + i];
        bf16 h = __float2bfloat16(v);
        bf16 l = __float2bfloat16(v - __bfloat162float(h));
        const size_t d = (size_t)(c0 + y + i) * R + r0 + x;
        oh[d] = h; ol[d] = l;
    }
}

__global__ void __launch_bounds__(256) transpose_half(const float* __restrict__ in,
                                                      __half* __restrict__ out, int R, int C)
{
    __shared__ float t[32][33];
    const int c0 = blockIdx.x * 32, r0 = blockIdx.y * 32;
    const int x = threadIdx.x & 31, y = threadIdx.x >> 5;
#pragma unroll
    for (int i = 0; i < 32; i += 8) t[y + i][x] = in[(size_t)(r0 + y + i) * C + c0 + x];
    __syncthreads();
#pragma unroll
    for (int i = 0; i < 32; i += 8)
        out[(size_t)(c0 + y + i) * R + r0 + x] = __float2half(t[x][y + i]);
}

__global__ void __launch_bounds__(256) split_f32(const float* __restrict__ in,
                                                 bf16* __restrict__ oh, bf16* __restrict__ ol, int n2)
{
    int i = (blockIdx.x * 256 + threadIdx.x) * 2;
    if (i < n2) {
        float2 v = *reinterpret_cast<const float2*>(&in[i]);
        uint32_t h, l;
        splitpack(v.x, v.y, h, l);
        *reinterpret_cast<uint32_t*>(&oh[i]) = h;
        *reinterpret_cast<uint32_t*>(&ol[i]) = l;
    }
}

__global__ void __launch_bounds__(256) cvt_half(const float* __restrict__ in,
                                                __half* __restrict__ out, int n2)
{
    int i = (blockIdx.x * 256 + threadIdx.x) * 2;
    if (i < n2) {
        float2 v = *reinterpret_cast<const float2*>(&in[i]);
        *reinterpret_cast<__half2*>(&out[i]) = __floats2half2_rn(v.x, v.y);
    }
}

// softmax: fp32 scores -> fp16 attn*512
__global__ void __launch_bounds__(256) softmax_h(const float* __restrict__ S,
                                                 __half* __restrict__ P16)
{
    __shared__ float row[MEMN];
    __shared__ float red[256];
    const size_t r = blockIdx.x;
    const float* p = S + r * MEMN;
    const int tid = threadIdx.x;
    float mx = -1e30f;
    for (int i = tid * 2; i < MEMN; i += 512) {
        float2 v = *reinterpret_cast<const float2*>(&p[i]);
        row[i] = v.x; row[i+1] = v.y;
        mx = fmaxf(mx, fmaxf(v.x, v.y));
    }
    red[tid] = mx; __syncthreads();
    for (int s = 128; s > 0; s >>= 1) { if (tid < s) red[tid] = fmaxf(red[tid], red[tid + s]); __syncthreads(); }
    mx = red[0]; __syncthreads();
    float sum = 0.0f;
    for (int i = tid; i < MEMN; i += 256) { float e = expf(row[i] - mx); row[i] = e; sum += e; }
    red[tid] = sum; __syncthreads();
    for (int s = 128; s > 0; s >>= 1) { if (tid < s) red[tid] += red[tid + s]; __syncthreads(); }
    const float inv = 512.0f / red[0];
    __syncthreads();
    for (int i = tid * 2; i < MEMN; i += 512)
        *reinterpret_cast<__half2*>(&P16[r * MEMN + i]) =
            __floats2half2_rn(row[i] * inv, row[i+1] * inv);
}

__global__ void __launch_bounds__(256) normalize_split(const float* __restrict__ X,
                                                       bf16* __restrict__ oh, bf16* __restrict__ ol)
{
    __shared__ float red[256];
    const int r = blockIdx.x, tid = threadIdx.x;
    const float* p = X + (size_t)r * KD_;
    float ss = 0.0f;
    for (int i = tid; i < KD_; i += 256) { float v = p[i]; ss += v * v; }
    red[tid] = ss; __syncthreads();
    for (int s = 128; s > 0; s >>= 1) { if (tid < s) red[tid] += red[tid + s]; __syncthreads(); }
    const float inv = 1.0f / fmaxf(sqrtf(red[0]), 1e-8f);
    for (int i = tid * 2; i < KD_; i += 512) {
        uint32_t h, l;
        splitpack(p[i] * inv, p[i+1] * inv, h, l);
        *reinterpret_cast<uint32_t*>(&oh[(size_t)r * KD_ + i]) = h;
        *reinterpret_cast<uint32_t*>(&ol[(size_t)r * KD_ + i]) = l;
    }
}

__global__ void __launch_bounds__(256) argmax_rows(const float* __restrict__ S,
                                                   int* __restrict__ idx)
{
    __shared__ float rv[256];
    __shared__ int   ri[256];
    const int r = blockIdx.x, tid = threadIdx.x;
    const float* p = S + (size_t)r * MEMN;
    float bv = -1e30f; int bi = 0;
    for (int i = tid; i < MEMN; i += 256) { float v = p[i]; if (v > bv) { bv = v; bi = i; } }
    rv[tid] = bv; ri[tid] = bi; __syncthreads();
    for (int s = 128; s > 0; s >>= 1) {
        if (tid < s) {
            if (rv[tid + s] > rv[tid] || (rv[tid + s] == rv[tid] && ri[tid + s] < ri[tid])) {
                rv[tid] = rv[tid + s]; ri[tid] = ri[tid + s];
            }
        }
        __syncthreads();
    }
    if (tid == 0) idx[r] = ri[0];
}

__global__ void __launch_bounds__(256) chain_update(
    const float* __restrict__ wk, const float* __restrict__ wv,
    const float* __restrict__ Wg, const float* __restrict__ Aw,
    const int*   __restrict__ idx,
    const float* __restrict__ mk, const float* __restrict__ mv,
    float* __restrict__ outK, float* __restrict__ outV)
{
    __shared__ float sK[KD_], sV[KD_];
    __shared__ int   list[BWN];
    __shared__ int   cnt;
    const int s = blockIdx.x, tid = threadIdx.x;
    if (tid == 0) cnt = 0;
    __syncthreads();
    for (int t = tid; t < BWN; t += 256)
        if (idx[t] == s) { int p = atomicAdd(&cnt, 1); list[p] = t; }
    __syncthreads();
    const int n = cnt;
    if (n == 0) return;
    if (tid == 0) {
        for (int i = 1; i < n; i++) {
            int v = list[i], j = i - 1;
            while (j >= 0 && list[j] > v) { list[j + 1] = list[j]; j--; }
            list[j + 1] = v;
        }
    }
    for (int i = tid; i < KD_; i += 256) {
        sK[i] = mk[(size_t)s * KD_ + i];
        sV[i] = mv[(size_t)s * KD_ + i];
    }
    __syncthreads();
    for (int e = 0; e < n; e++) {
        const int t = list[e];
        const int j0 = tid, j1 = tid + 256;
        float a0 = Aw[(size_t)t * KD_ + j0];
        float a1 = Aw[(size_t)t * KD_ + j1];
#pragma unroll 8
        for (int r = 0; r < KD_; r++) {
            const float v = sV[r];
            const float* wrow = Wg + (size_t)(KD_ + r) * KD_;
            a0 += v * wrow[j0];
            a1 += v * wrow[j1];
        }
        const float g0 = 1.0f / (1.0f + expf(-a0));
        const float g1 = 1.0f / (1.0f + expf(-a1));
        __syncthreads();
        sK[j0] = g0 * wk[(size_t)t * KD_ + j0] + (1.0f - g0) * sK[j0];
        sK[j1] = g1 * wk[(size_t)t * KD_ + j1] + (1.0f - g1) * sK[j1];
        sV[j0] = g0 * wv[(size_t)t * KD_ + j0] + (1.0f - g0) * sV[j0];
        sV[j1] = g1 * wv[(size_t)t * KD_ + j1] + (1.0f - g1) * sV[j1];
        __syncthreads();
    }
    for (int i = tid; i < KD_; i += 256) {
        outK[(size_t)s * KD_ + i] = sK[i];
        outV[(size_t)s * KD_ + i] = sV[i];
    }
}

// ---------------- launcher ----------------
extern "C" void kernel_launch(void* const* d_in, const int* in_sizes, int n_in,
                              void* d_out, int out_size)
{
    const float* queries    = (const float*)d_in[0];
    const float* write_keys = (const float*)d_in[1];
    const float* write_vals = (const float*)d_in[2];
    const float* mem_keys   = (const float*)d_in[3];
    const float* mem_values = (const float*)d_in[4];
    const float* Wq         = (const float*)d_in[5];
    const float* bq         = (const float*)d_in[6];
    const float* Wvp        = (const float*)d_in[7];
    const float* bvp        = (const float*)d_in[8];
    const float* Wg         = (const float*)d_in[9];
    const float* bg         = (const float*)d_in[10];

    float* out_read = (float*)d_out;
    float* out_k    = out_read + (size_t)RB * KD_;
    float* out_v    = out_k    + (size_t)MEMN * KD_;

    void *pS, *pSIM, *pA, *pIdx, *pQ16, *pP16, *pMK16, *pMVT16;
    void *pQIh, *pQIl, *pRVh, *pRVl, *pKNh, *pKNl, *pMNh, *pMNl, *pWKh, *pWKl;
    void *pWqTh, *pWqTl, *pWvpTh, *pWvpTl, *pWgTh, *pWgTl;
    cudaGetSymbolAddress(&pS, g_S);       cudaGetSymbolAddress(&pSIM, g_SIM);
    cudaGetSymbolAddress(&pA, g_A);       cudaGetSymbolAddress(&pIdx, g_idx);
    cudaGetSymbolAddress(&pQ16, g_Q16);   cudaGetSymbolAddress(&pP16, g_P16);
    cudaGetSymbolAddress(&pMK16, g_MK16); cudaGetSymbolAddress(&pMVT16, g_MVT16);
    cudaGetSymbolAddress(&pQIh, g_QIh);   cudaGetSymbolAddress(&pQIl, g_QIl);
    cudaGetSymbolAddress(&pRVh, g_RVh);   cudaGetSymbolAddress(&pRVl, g_RVl);
    cudaGetSymbolAddress(&pKNh, g_KNh);   cudaGetSymbolAddress(&pKNl, g_KNl);
    cudaGetSymbolAddress(&pMNh, g_MNh);   cudaGetSymbolAddress(&pMNl, g_MNl);
    cudaGetSymbolAddress(&pWKh, g_WKh);   cudaGetSymbolAddress(&pWKl, g_WKl);
    cudaGetSymbolAddress(&pWqTh, g_WqTh); cudaGetSymbolAddress(&pWqTl, g_WqTl);
    cudaGetSymbolAddress(&pWvpTh, g_WvpTh); cudaGetSymbolAddress(&pWvpTl, g_WvpTl);
    cudaGetSymbolAddress(&pWgTh, g_WgTh); cudaGetSymbolAddress(&pWgTl, g_WgTl);

    cudaFuncSetAttribute(bgemm3<0>, cudaFuncAttributeMaxDynamicSharedMemorySize, DYN3);
    cudaFuncSetAttribute(bgemm3<1>, cudaFuncAttributeMaxDynamicSharedMemorySize, DYN3);
    cudaFuncSetAttribute(hgemm1<0>, cudaFuncAttributeMaxDynamicSharedMemorySize, DYN1);
    cudaFuncSetAttribute(hgemm1<2>, cudaFuncAttributeMaxDynamicSharedMemorySize, DYN1);

    const float qscale = 0.044194173824159216f;  // 1/sqrt(512)/TEMP

    // ---- prep ----
    transpose_split<<<dim3((HH*KD_)/32, KD_/32), 256>>>(Wq, (bf16*)pWqTh, (bf16*)pWqTl, KD_, HH*KD_);
    transpose_split<<<dim3(KD_/32, (HH*KD_)/32), 256>>>(Wvp, (bf16*)pWvpTh, (bf16*)pWvpTl, HH*KD_, KD_);
    transpose_split<<<dim3(KD_/32, KD_/32),      256>>>(Wg, (bf16*)pWgTh, (bf16*)pWgTl, KD_, KD_);
    transpose_half<<<dim3(KD_/32, MEMN/32),      256>>>(mem_values, (__half*)pMVT16, MEMN, KD_);
    cvt_half<<<(MEMN*KD_/2 + 255)/256, 256>>>(mem_keys, (__half*)pMK16, MEMN*KD_);
    split_f32<<<(BWN*KD_/2 + 255)/256,  256>>>(write_keys, (bf16*)pWKh, (bf16*)pWKl, BWN*KD_);
    split_f32<<<(RB*KD_/2 + 255)/256,   256>>>(queries,    (bf16*)pQIh, (bf16*)pQIl, RB*KD_);
    normalize_split<<<MEMN, 256>>>(mem_keys,   (bf16*)pMNh, (bf16*)pMNl);
    normalize_split<<<BWN,  256>>>(write_keys, (bf16*)pKNh, (bf16*)pKNl);

    // ---- write path ----
    bgemm3<0><<<dim3(MEMN/TN, BWN/TM), 256, DYN3>>>(
        (bf16*)pKNh, (bf16*)pKNl, (bf16*)pMNh, (bf16*)pMNl,
        nullptr, (float*)pSIM, nullptr, BWN, MEMN, KD_, 1.0f);
    argmax_rows<<<BWN, 256>>>((float*)pSIM, (int*)pIdx);
    bgemm3<0><<<dim3(KD_/TN, BWN/TM), 256, DYN3>>>(
        (bf16*)pWKh, (bf16*)pWKl, (bf16*)pWgTh, (bf16*)pWgTl,
        bg, (float*)pA, nullptr, BWN, KD_, KD_, 1.0f);
    cudaMemcpyAsync(out_k, mem_keys,   (size_t)MEMN * KD_ * sizeof(float), cudaMemcpyDeviceToDevice);
    cudaMemcpyAsync(out_v, mem_values, (size_t)MEMN * KD_ * sizeof(float), cudaMemcpyDeviceToDevice);
    chain_update<<<MEMN, 256>>>(write_keys, write_vals, Wg, (float*)pA, (int*)pIdx,
                                mem_keys, mem_values, out_k, out_v);

    // ---- read path ----
    bgemm3<1><<<dim3((HH*KD_)/TN, RB/TM), 256, DYN3>>>(
        (bf16*)pQIh, (bf16*)pQIl, (bf16*)pWqTh, (bf16*)pWqTl,
        bq, nullptr, (__half*)pQ16, RB, HH*KD_, KD_, qscale);
    hgemm1<0><<<dim3(MEMN/TN, RQ/TM), 256, DYN1>>>(
        (__half*)pQ16, (__half*)pMK16, (float*)pS, nullptr, nullptr, RQ, MEMN, KD_, 1.0f);
    softmax_h<<<RQ, 256>>>((float*)pS, (__half*)pP16);
    hgemm1<2><<<dim3(KD_/TN, RQ/TM), 256, DYN1>>>(
        (__half*)pP16, (__half*)pMVT16, nullptr, (bf16*)pRVh, (bf16*)pRVl,
        RQ, KD_, MEMN, 1.0f / 512.0f);
    bgemm3<0><<<dim3(KD_/TN, RB/TM), 256, DYN3>>>(
        (bf16*)pRVh, (bf16*)pRVl, (bf16*)pWvpTh, (bf16*)pWvpTl,
        bvp, out_read, nullptr, RB, KD_, HH*KD_, 1.0f);
}

// round 6
// speedup vs baseline: 5.3492x; 1.3521x over previous
#include <cuda_runtime.h>
#include <cuda_bf16.h>
#include <cuda_fp16.h>
#include <math.h>
#include <stdint.h>

#define BB   4
#define NN_  1024
#define KD_  512
#define HH   8
#define MEMN 4096
#define BWN  1024
#define RQ   (BB*HH*NN_)
#define RB   (BB*NN_)

typedef __nv_bfloat16 bf16;

__device__ float  g_S  [(size_t)RQ * MEMN];
__device__ float  g_SIM[(size_t)BWN * MEMN];
__device__ float  g_A  [(size_t)BWN * KD_];
__device__ float  g_BV [(size_t)BWN * KD_];
__device__ int    g_idx[BWN];
__device__ __half g_QI16[(size_t)RB * KD_];
__device__ __half g_Q16[(size_t)RQ * KD_];
__device__ __half g_P16[(size_t)RQ * MEMN];
__device__ __half g_RV16[(size_t)RB * (HH*KD_)];
__device__ __half g_MK16[(size_t)MEMN * KD_];
__device__ __half g_MVT16[(size_t)KD_ * MEMN];
__device__ __half g_WqT16[(size_t)(HH*KD_) * KD_];
__device__ __half g_WvpT16[(size_t)KD_ * (HH*KD_)];
__device__ bf16 g_KNh[(size_t)BWN * KD_],  g_KNl[(size_t)BWN * KD_];
__device__ bf16 g_MNh[(size_t)MEMN * KD_], g_MNl[(size_t)MEMN * KD_];
__device__ bf16 g_WKh[(size_t)BWN * KD_],  g_WKl[(size_t)BWN * KD_];
__device__ bf16 g_WgTh[(size_t)KD_ * KD_], g_WgTl[(size_t)KD_ * KD_];
__device__ bf16 g_WgBh[(size_t)KD_ * KD_], g_WgBl[(size_t)KD_ * KD_];
__device__ bf16 g_GVh[(size_t)BWN * KD_],  g_GVl[(size_t)BWN * KD_];

__device__ __forceinline__ uint32_t smem_to_u32(const void* p) {
    uint32_t a;
    asm("{ .reg .u64 t; cvta.to.shared.u64 t, %1; cvt.u32.u64 %0, t; }" : "=r"(a) : "l"(p));
    return a;
}
__device__ __forceinline__ void ldsm4(uint32_t* r, uint32_t addr) {
    asm volatile("ldmatrix.sync.aligned.m8n8.x4.shared.b16 {%0,%1,%2,%3}, [%4];"
                 : "=r"(r[0]), "=r"(r[1]), "=r"(r[2]), "=r"(r[3]) : "r"(addr));
}
__device__ __forceinline__ void mma_bf(float* c, const uint32_t* a, const uint32_t* b) {
    asm volatile(
        "mma.sync.aligned.m16n8k16.row.col.f32.bf16.bf16.f32 "
        "{%0,%1,%2,%3}, {%4,%5,%6,%7}, {%8,%9}, {%0,%1,%2,%3};"
        : "+f"(c[0]), "+f"(c[1]), "+f"(c[2]), "+f"(c[3])
        : "r"(a[0]), "r"(a[1]), "r"(a[2]), "r"(a[3]), "r"(b[0]), "r"(b[1]));
}
__device__ __forceinline__ void mma_fp(float* c, const uint32_t* a, const uint32_t* b) {
    asm volatile(
        "mma.sync.aligned.m16n8k16.row.col.f32.f16.f16.f32 "
        "{%0,%1,%2,%3}, {%4,%5,%6,%7}, {%8,%9}, {%0,%1,%2,%3};"
        : "+f"(c[0]), "+f"(c[1]), "+f"(c[2]), "+f"(c[3])
        : "r"(a[0]), "r"(a[1]), "r"(a[2]), "r"(a[3]), "r"(b[0]), "r"(b[1]));
}
__device__ __forceinline__ void cp16(uint32_t dst, const void* src) {
    asm volatile("cp.async.cg.shared.global [%0], [%1], 16;" :: "r"(dst), "l"(src));
}
#define CP_COMMIT() asm volatile("cp.async.commit_group;" ::: "memory")
#define CP_WAIT1()  asm volatile("cp.async.wait_group 1;" ::: "memory")

__device__ __forceinline__ void splitpack(float x, float y, uint32_t& h, uint32_t& l) {
    bf16 hx = __float2bfloat16(x), hy = __float2bfloat16(y);
    float rx = x - __bfloat162float(hx), ry = y - __bfloat162float(hy);
    bf16 lx = __float2bfloat16(rx), ly = __float2bfloat16(ry);
    h = (uint32_t)__bfloat16_as_ushort(hx) | ((uint32_t)__bfloat16_as_ushort(hy) << 16);
    l = (uint32_t)__bfloat16_as_ushort(lx) | ((uint32_t)__bfloat16_as_ushort(ly) << 16);
}

#define TN 128
#define ROWB 144

template<int MODE>
__device__ __forceinline__ size_t dst_of(int r, int c, int N) {
    if (MODE == 0) return (size_t)r * N + c;
    if (MODE == 1) {
        const int b_ = r >> 10, n_ = r & 1023, h_ = c >> 9, d_ = c & 511;
        return ((size_t)((b_ * 8 + h_) * 1024 + n_) << 9) + d_;
    }
    const int b_ = r >> 13, h_ = (r >> 10) & 7, n_ = r & 1023;
    return ((size_t)(b_ * 1024 + n_) << 12) + ((size_t)h_ << 9) + c;
}

// ================= 3-term split-bf16 GEMM (KC=32), TM=256, fp32 out =================
#define TM3 256
#define KC3 32
#define STAGE3 ((TM3 + TN) * ROWB)
#define DYN3 (2 * STAGE3)

__global__ void __launch_bounds__(256, 1)
bgemm3(const bf16* __restrict__ Ah, const bf16* __restrict__ Al,
       const bf16* __restrict__ Bh, const bf16* __restrict__ Bl,
       const float* __restrict__ bias, float* __restrict__ C,
       int M, int N, int K, float scale)
{
    extern __shared__ char sm[];
    const uint32_t smem_u = smem_to_u32(sm);
    const int tid = threadIdx.x;
    const int lane = tid & 31, wid = tid >> 5;
    const int bm = blockIdx.y * TM3, bn = blockIdx.x * TN;
    const int wm = (wid >> 1) * 64, wn = (wid & 1) * 64;

    float acc[4][8][4];
#pragma unroll
    for (int i = 0; i < 4; i++)
#pragma unroll
        for (int j = 0; j < 8; j++)
#pragma unroll
            for (int k = 0; k < 4; k++) acc[i][j][k] = 0.0f;

    const int NC = K / KC3;

    auto load_chunk = [&](int c, int st) {
        const int k0 = c * KC3;
        const uint32_t sb = smem_u + st * STAGE3;
#pragma unroll
        for (int u = 0; u < 3; u++) {
            const int unit = tid + u * 256;
            const int r = (unit & 511) >> 1, pl = unit & 1;
            const bf16* src;
            uint32_t dst;
            if (unit < 512) {
                src = (pl ? Al : Ah) + (size_t)(bm + r) * K + k0;
                dst = sb + r * ROWB + pl * 64;
            } else {
                src = (pl ? Bl : Bh) + (size_t)(bn + r) * K + k0;
                dst = sb + (TM3 + r) * ROWB + pl * 64;
            }
#pragma unroll
            for (int i = 0; i < 4; i++) cp16(dst + i * 16, src + i * 8);
        }
    };

    load_chunk(0, 0); CP_COMMIT();
    load_chunk(1, 1); CP_COMMIT();

    const int mr = lane & 7, msel = lane >> 3;
    const int aro = ((msel & 1) << 3) + mr;
    const int aco = (msel >> 1) << 3;
    const int bro = ((msel >> 1) << 3) + mr;
    const int bco = (msel & 1) << 3;

    for (int c = 0; c < NC; c++) {
        CP_WAIT1();
        __syncthreads();
        const uint32_t base = smem_u + (c & 1) * STAGE3;
#pragma unroll
        for (int ks = 0; ks < 2; ks++) {
            uint32_t ah[4][4], al[4][4], bh[8][2], bl[8][2];
            const int colA = (ks * 16 + aco) * 2;
            const int colB = (ks * 16 + bco) * 2;
#pragma unroll
            for (int mi = 0; mi < 4; mi++) {
                const uint32_t ad = base + (wm + mi * 16 + aro) * ROWB + colA;
                ldsm4(ah[mi], ad);
                ldsm4(al[mi], ad + 64);
            }
#pragma unroll
            for (int g = 0; g < 4; g++) {
                const uint32_t bd = base + (TM3 + wn + g * 16 + bro) * ROWB + colB;
                uint32_t t[4];
                ldsm4(t, bd);
                bh[2*g][0] = t[0]; bh[2*g][1] = t[1];
                bh[2*g+1][0] = t[2]; bh[2*g+1][1] = t[3];
                ldsm4(t, bd + 64);
                bl[2*g][0] = t[0]; bl[2*g][1] = t[1];
                bl[2*g+1][0] = t[2]; bl[2*g+1][1] = t[3];
            }
#pragma unroll
            for (int mi = 0; mi < 4; mi++)
#pragma unroll
                for (int nb = 0; nb < 8; nb++) {
                    mma_bf(acc[mi][nb], ah[mi], bh[nb]);
                    mma_bf(acc[mi][nb], ah[mi], bl[nb]);
                    mma_bf(acc[mi][nb], al[mi], bh[nb]);
                }
        }
        __syncthreads();
        if (c + 2 < NC) load_chunk(c + 2, c & 1);
        CP_COMMIT();
    }

    const int group = lane >> 2, tig = lane & 3;
#pragma unroll
    for (int mi = 0; mi < 4; mi++) {
        const int r_lo = bm + wm + mi * 16 + group;
#pragma unroll
        for (int nb = 0; nb < 8; nb++) {
            const int col = bn + wn + nb * 8 + tig * 2;
            float b0 = 0.0f, b1 = 0.0f;
            if (bias) { b0 = bias[col]; b1 = bias[col + 1]; }
            *reinterpret_cast<float2*>(&C[(size_t)r_lo * N + col]) =
                make_float2((acc[mi][nb][0] + b0) * scale, (acc[mi][nb][1] + b1) * scale);
            *reinterpret_cast<float2*>(&C[(size_t)(r_lo + 8) * N + col]) =
                make_float2((acc[mi][nb][2] + b0) * scale, (acc[mi][nb][3] + b1) * scale);
        }
    }
}

// ================= single-term fp16 GEMM (KC=64), TM = WM*64 =================
#define KC1 64

template<int MODE, int WM>
__global__ void __launch_bounds__(WM*64, 1)
hgemm1(const __half* __restrict__ A, const __half* __restrict__ B,
       const float* __restrict__ bias,
       float* __restrict__ C, __half* __restrict__ C16,
       int M, int N, int K, float scale)
{
    constexpr int TMv = WM * 64;
    constexpr int NT  = WM * 64;
    constexpr int STAGE = (TMv + TN) * ROWB;
    extern __shared__ char sm[];
    const uint32_t smem_u = smem_to_u32(sm);
    const int tid = threadIdx.x;
    const int lane = tid & 31, wid = tid >> 5;
    const int bm = blockIdx.y * TMv, bn = blockIdx.x * TN;
    const int wm = (wid >> 1) * 64, wn = (wid & 1) * 64;

    float acc[4][8][4];
#pragma unroll
    for (int i = 0; i < 4; i++)
#pragma unroll
        for (int j = 0; j < 8; j++)
#pragma unroll
            for (int k = 0; k < 4; k++) acc[i][j][k] = 0.0f;

    const int NC = K / KC1;

    auto load_chunk = [&](int c, int st) {
        const int k0 = c * KC1;
        const uint32_t sb = smem_u + st * STAGE;
#pragma unroll
        for (int u = tid; u < (TMv + TN) * 8; u += NT) {
            const int r = u >> 3, seg = u & 7;
            const __half* src = (r < TMv)
                ? A + (size_t)(bm + r) * K + k0 + seg * 8
                : B + (size_t)(bn + (r - TMv)) * K + k0 + seg * 8;
            cp16(sb + r * ROWB + seg * 16, src);
        }
    };

    load_chunk(0, 0); CP_COMMIT();
    load_chunk(1, 1); CP_COMMIT();

    const int mr = lane & 7, msel = lane >> 3;
    const int aro = ((msel & 1) << 3) + mr;
    const int aco = (msel >> 1) << 3;
    const int bro = ((msel >> 1) << 3) + mr;
    const int bco = (msel & 1) << 3;

    for (int c = 0; c < NC; c++) {
        CP_WAIT1();
        __syncthreads();
        const uint32_t base = smem_u + (c & 1) * STAGE;
#pragma unroll
        for (int ks = 0; ks < 4; ks++) {
            uint32_t ah[4][4], bh[8][2];
            const int colA = (ks * 16 + aco) * 2;
            const int colB = (ks * 16 + bco) * 2;
#pragma unroll
            for (int mi = 0; mi < 4; mi++)
                ldsm4(ah[mi], base + (wm + mi * 16 + aro) * ROWB + colA);
#pragma unroll
            for (int g = 0; g < 4; g++) {
                uint32_t t[4];
                ldsm4(t, base + (TMv + wn + g * 16 + bro) * ROWB + colB);
                bh[2*g][0] = t[0]; bh[2*g][1] = t[1];
                bh[2*g+1][0] = t[2]; bh[2*g+1][1] = t[3];
            }
#pragma unroll
            for (int mi = 0; mi < 4; mi++)
#pragma unroll
                for (int nb = 0; nb < 8; nb++)
                    mma_fp(acc[mi][nb], ah[mi], bh[nb]);
        }
        __syncthreads();
        if (c + 2 < NC) load_chunk(c + 2, c & 1);
        CP_COMMIT();
    }

    const int group = lane >> 2, tig = lane & 3;
#pragma unroll
    for (int mi = 0; mi < 4; mi++) {
        const int r_lo = bm + wm + mi * 16 + group;
#pragma unroll
        for (int nb = 0; nb < 8; nb++) {
            const int col = bn + wn + nb * 8 + tig * 2;
            float b0 = 0.0f, b1 = 0.0f;
            if (bias) { b0 = bias[col]; b1 = bias[col + 1]; }
            float v00 = (acc[mi][nb][0] + b0) * scale;
            float v01 = (acc[mi][nb][1] + b1) * scale;
            float v10 = (acc[mi][nb][2] + b0) * scale;
            float v11 = (acc[mi][nb][3] + b1) * scale;
            if (MODE == 0) {
                *reinterpret_cast<float2*>(&C[dst_of<0>(r_lo,     col, N)]) = make_float2(v00, v01);
                *reinterpret_cast<float2*>(&C[dst_of<0>(r_lo + 8, col, N)]) = make_float2(v10, v11);
            } else {
                *reinterpret_cast<__half2*>(&C16[dst_of<MODE>(r_lo,     col, N)]) = __floats2half2_rn(v00, v01);
                *reinterpret_cast<__half2*>(&C16[dst_of<MODE>(r_lo + 8, col, N)]) = __floats2half2_rn(v10, v11);
            }
        }
    }
}

// ---------------- prep / small kernels ----------------
__global__ void __launch_bounds__(256) transpose_split(const float* __restrict__ in,
                                                       bf16* __restrict__ oh, bf16* __restrict__ ol,
                                                       int R, int C)
{
    __shared__ float t[32][33];
    const int c0 = blockIdx.x * 32, r0 = blockIdx.y * 32;
    const int x = threadIdx.x & 31, y = threadIdx.x >> 5;
#pragma unroll
    for (int i = 0; i < 32; i += 8) t[y + i][x] = in[(size_t)(r0 + y + i) * C + c0 + x];
    __syncthreads();
#pragma unroll
    for (int i = 0; i < 32; i += 8) {
        float v = t[x][y + i];
        bf16 h = __float2bfloat16(v);
        bf16 l = __float2bfloat16(v - __bfloat162float(h));
        const size_t d = (size_t)(c0 + y + i) * R + r0 + x;
        oh[d] = h; ol[d] = l;
    }
}

__global__ void __launch_bounds__(256) transpose_half(const float* __restrict__ in,
                                                      __half* __restrict__ out, int R, int C)
{
    __shared__ float t[32][33];
    const int c0 = blockIdx.x * 32, r0 = blockIdx.y * 32;
    const int x = threadIdx.x & 31, y = threadIdx.x >> 5;
#pragma unroll
    for (int i = 0; i < 32; i += 8) t[y + i][x] = in[(size_t)(r0 + y + i) * C + c0 + x];
    __syncthreads();
#pragma unroll
    for (int i = 0; i < 32; i += 8)
        out[(size_t)(c0 + y + i) * R + r0 + x] = __float2half(t[x][y + i]);
}

__global__ void __launch_bounds__(256) split_f32(const float* __restrict__ in,
                                                 bf16* __restrict__ oh, bf16* __restrict__ ol, int n2)
{
    int i = (blockIdx.x * 256 + threadIdx.x) * 2;
    if (i < n2) {
        float2 v = *reinterpret_cast<const float2*>(&in[i]);
        uint32_t h, l;
        splitpack(v.x, v.y, h, l);
        *reinterpret_cast<uint32_t*>(&oh[i]) = h;
        *reinterpret_cast<uint32_t*>(&ol[i]) = l;
    }
}

__global__ void __launch_bounds__(256) cvt_half(const float* __restrict__ in,
                                                __half* __restrict__ out, int n2)
{
    int i = (blockIdx.x * 256 + threadIdx.x) * 2;
    if (i < n2) {
        float2 v = *reinterpret_cast<const float2*>(&in[i]);
        *reinterpret_cast<__half2*>(&out[i]) = __floats2half2_rn(v.x, v.y);
    }
}

__global__ void __launch_bounds__(256) softmax_h(const float* __restrict__ S,
                                                 __half* __restrict__ P16)
{
    __shared__ float row[MEMN];
    __shared__ float red[256];
    const size_t r = blockIdx.x;
    const float* p = S + r * MEMN;
    const int tid = threadIdx.x;
    float mx = -1e30f;
    for (int i = tid * 2; i < MEMN; i += 512) {
        float2 v = *reinterpret_cast<const float2*>(&p[i]);
        row[i] = v.x; row[i+1] = v.y;
        mx = fmaxf(mx, fmaxf(v.x, v.y));
    }
    red[tid] = mx; __syncthreads();
    for (int s = 128; s > 0; s >>= 1) { if (tid < s) red[tid] = fmaxf(red[tid], red[tid + s]); __syncthreads(); }
    mx = red[0]; __syncthreads();
    float sum = 0.0f;
    for (int i = tid; i < MEMN; i += 256) { float e = expf(row[i] - mx); row[i] = e; sum += e; }
    red[tid] = sum; __syncthreads();
    for (int s = 128; s > 0; s >>= 1) { if (tid < s) red[tid] += red[tid + s]; __syncthreads(); }
    const float inv = 512.0f / red[0];
    __syncthreads();
    for (int i = tid * 2; i < MEMN; i += 512)
        *reinterpret_cast<__half2*>(&P16[r * MEMN + i]) =
            __floats2half2_rn(row[i] * inv, row[i+1] * inv);
}

__global__ void __launch_bounds__(256) normalize_split(const float* __restrict__ X,
                                                       bf16* __restrict__ oh, bf16* __restrict__ ol)
{
    __shared__ float red[256];
    const int r = blockIdx.x, tid = threadIdx.x;
    const float* p = X + (size_t)r * KD_;
    float ss = 0.0f;
    for (int i = tid; i < KD_; i += 256) { float v = p[i]; ss += v * v; }
    red[tid] = ss; __syncthreads();
    for (int s = 128; s > 0; s >>= 1) { if (tid < s) red[tid] += red[tid + s]; __syncthreads(); }
    const float inv = 1.0f / fmaxf(sqrtf(red[0]), 1e-8f);
    for (int i = tid * 2; i < KD_; i += 512) {
        uint32_t h, l;
        splitpack(p[i] * inv, p[i+1] * inv, h, l);
        *reinterpret_cast<uint32_t*>(&oh[(size_t)r * KD_ + i]) = h;
        *reinterpret_cast<uint32_t*>(&ol[(size_t)r * KD_ + i]) = l;
    }
}

__global__ void __launch_bounds__(256) argmax_rows(const float* __restrict__ S,
                                                   int* __restrict__ idx)
{
    __shared__ float rv[256];
    __shared__ int   ri[256];
    const int r = blockIdx.x, tid = threadIdx.x;
    const float* p = S + (size_t)r * MEMN;
    float bv = -1e30f; int bi = 0;
    for (int i = tid; i < MEMN; i += 256) { float v = p[i]; if (v > bv) { bv = v; bi = i; } }
    rv[tid] = bv; ri[tid] = bi; __syncthreads();
    for (int s = 128; s > 0; s >>= 1) {
        if (tid < s) {
            if (rv[tid + s] > rv[tid] || (rv[tid + s] == rv[tid] && ri[tid + s] < ri[tid])) {
                rv[tid] = rv[tid + s]; ri[tid] = ri[tid + s];
            }
        }
        __syncthreads();
    }
    if (tid == 0) idx[r] = ri[0];
}

__global__ void __launch_bounds__(256) gather_split(const float* __restrict__ mv,
                                                    const int* __restrict__ idx,
                                                    bf16* __restrict__ oh, bf16* __restrict__ ol)
{
    const int t = blockIdx.x, tid = threadIdx.x;
    const int row = idx[t];
    const float* src = mv + (size_t)row * KD_;
    const int c = tid * 2;
    uint32_t h, l;
    splitpack(src[c], src[c + 1], h, l);
    *reinterpret_cast<uint32_t*>(&oh[(size_t)t * KD_ + c]) = h;
    *reinterpret_cast<uint32_t*>(&ol[(size_t)t * KD_ + c]) = l;
}

__global__ void __launch_bounds__(256) chain_update(
    const float* __restrict__ wk, const float* __restrict__ wv,
    const float* __restrict__ Wg, const float* __restrict__ Aw,
    const float* __restrict__ BV,
    const int*   __restrict__ idx,
    const float* __restrict__ mk, const float* __restrict__ mv,
    float* __restrict__ outK, float* __restrict__ outV)
{
    __shared__ float sK[KD_], sV[KD_];
    __shared__ int   list[BWN];
    __shared__ int   cnt;
    const int s = blockIdx.x, tid = threadIdx.x;
    if (tid == 0) cnt = 0;
    __syncthreads();
    for (int t = tid; t < BWN; t += 256)
        if (idx[t] == s) { int p = atomicAdd(&cnt, 1); list[p] = t; }
    __syncthreads();
    const int n = cnt;
    if (n == 0) return;
    if (tid == 0) {
        for (int i = 1; i < n; i++) {
            int v = list[i], j = i - 1;
            while (j >= 0 && list[j] > v) { list[j + 1] = list[j]; j--; }
            list[j + 1] = v;
        }
    }
    for (int i = tid; i < KD_; i += 256) {
        sK[i] = mk[(size_t)s * KD_ + i];
        sV[i] = mv[(size_t)s * KD_ + i];
    }
    __syncthreads();
    for (int e = 0; e < n; e++) {
        const int t = list[e];
        const int j0 = tid, j1 = tid + 256;
        float a0, a1;
        if (e == 0) {
            a0 = Aw[(size_t)t * KD_ + j0] + BV[(size_t)t * KD_ + j0];
            a1 = Aw[(size_t)t * KD_ + j1] + BV[(size_t)t * KD_ + j1];
        } else {
            a0 = Aw[(size_t)t * KD_ + j0];
            a1 = Aw[(size_t)t * KD_ + j1];
#pragma unroll 8
            for (int r = 0; r < KD_; r++) {
                const float v = sV[r];
                const float* wrow = Wg + (size_t)(KD_ + r) * KD_;
                a0 += v * wrow[j0];
                a1 += v * wrow[j1];
            }
        }
        const float g0 = 1.0f / (1.0f + expf(-a0));
        const float g1 = 1.0f / (1.0f + expf(-a1));
        __syncthreads();
        sK[j0] = g0 * wk[(size_t)t * KD_ + j0] + (1.0f - g0) * sK[j0];
        sK[j1] = g1 * wk[(size_t)t * KD_ + j1] + (1.0f - g1) * sK[j1];
        sV[j0] = g0 * wv[(size_t)t * KD_ + j0] + (1.0f - g0) * sV[j0];
        sV[j1] = g1 * wv[(size_t)t * KD_ + j1] + (1.0f - g1) * sV[j1];
        __syncthreads();
    }
    for (int i = tid; i < KD_; i += 256) {
        outK[(size_t)s * KD_ + i] = sK[i];
        outV[(size_t)s * KD_ + i] = sV[i];
    }
}

// ---------------- launcher ----------------
extern "C" void kernel_launch(void* const* d_in, const int* in_sizes, int n_in,
                              void* d_out, int out_size)
{
    const float* queries    = (const float*)d_in[0];
    const float* write_keys = (const float*)d_in[1];
    const float* write_vals = (const float*)d_in[2];
    const float* mem_keys   = (const float*)d_in[3];
    const float* mem_values = (const float*)d_in[4];
    const float* Wq         = (const float*)d_in[5];
    const float* bq         = (const float*)d_in[6];
    const float* Wvp        = (const float*)d_in[7];
    const float* bvp        = (const float*)d_in[8];
    const float* Wg         = (const float*)d_in[9];
    const float* bg         = (const float*)d_in[10];

    float* out_read = (float*)d_out;
    float* out_k    = out_read + (size_t)RB * KD_;
    float* out_v    = out_k    + (size_t)MEMN * KD_;

    void *pS, *pSIM, *pA, *pBV, *pIdx, *pQI16, *pQ16, *pP16, *pRV16, *pMK16, *pMVT16;
    void *pWqT16, *pWvpT16, *pKNh, *pKNl, *pMNh, *pMNl, *pWKh, *pWKl;
    void *pWgTh, *pWgTl, *pWgBh, *pWgBl, *pGVh, *pGVl;
    cudaGetSymbolAddress(&pS, g_S);         cudaGetSymbolAddress(&pSIM, g_SIM);
    cudaGetSymbolAddress(&pA, g_A);         cudaGetSymbolAddress(&pBV, g_BV);
    cudaGetSymbolAddress(&pIdx, g_idx);
    cudaGetSymbolAddress(&pQI16, g_QI16);   cudaGetSymbolAddress(&pQ16, g_Q16);
    cudaGetSymbolAddress(&pP16, g_P16);     cudaGetSymbolAddress(&pRV16, g_RV16);
    cudaGetSymbolAddress(&pMK16, g_MK16);   cudaGetSymbolAddress(&pMVT16, g_MVT16);
    cudaGetSymbolAddress(&pWqT16, g_WqT16); cudaGetSymbolAddress(&pWvpT16, g_WvpT16);
    cudaGetSymbolAddress(&pKNh, g_KNh);     cudaGetSymbolAddress(&pKNl, g_KNl);
    cudaGetSymbolAddress(&pMNh, g_MNh);     cudaGetSymbolAddress(&pMNl, g_MNl);
    cudaGetSymbolAddress(&pWKh, g_WKh);     cudaGetSymbolAddress(&pWKl, g_WKl);
    cudaGetSymbolAddress(&pWgTh, g_WgTh);   cudaGetSymbolAddress(&pWgTl, g_WgTl);
    cudaGetSymbolAddress(&pWgBh, g_WgBh);   cudaGetSymbolAddress(&pWgBl, g_WgBl);
    cudaGetSymbolAddress(&pGVh, g_GVh);     cudaGetSymbolAddress(&pGVl, g_GVl);

    constexpr int DYN1_256 = 2 * (256 + TN) * ROWB;
    constexpr int DYN1_128 = 2 * (128 + TN) * ROWB;
    cudaFuncSetAttribute(bgemm3,      cudaFuncAttributeMaxDynamicSharedMemorySize, DYN3);
    cudaFuncSetAttribute(hgemm1<0,4>, cudaFuncAttributeMaxDynamicSharedMemorySize, DYN1_256);
    cudaFuncSetAttribute(hgemm1<1,4>, cudaFuncAttributeMaxDynamicSharedMemorySize, DYN1_256);
    cudaFuncSetAttribute(hgemm1<2,4>, cudaFuncAttributeMaxDynamicSharedMemorySize, DYN1_256);
    cudaFuncSetAttribute(hgemm1<0,2>, cudaFuncAttributeMaxDynamicSharedMemorySize, DYN1_128);

    const float qscale = 0.044194173824159216f;  // 1/sqrt(512)/TEMP

    // ---- prep ----
    transpose_half<<<dim3((HH*KD_)/32, KD_/32), 256>>>(Wq, (__half*)pWqT16, KD_, HH*KD_);
    transpose_half<<<dim3(KD_/32, (HH*KD_)/32), 256>>>(Wvp, (__half*)pWvpT16, HH*KD_, KD_);
    transpose_half<<<dim3(KD_/32, MEMN/32),     256>>>(mem_values, (__half*)pMVT16, MEMN, KD_);
    transpose_split<<<dim3(KD_/32, KD_/32),     256>>>(Wg, (bf16*)pWgTh, (bf16*)pWgTl, KD_, KD_);
    transpose_split<<<dim3(KD_/32, KD_/32),     256>>>(Wg + (size_t)KD_ * KD_,
                                                       (bf16*)pWgBh, (bf16*)pWgBl, KD_, KD_);
    cvt_half<<<(MEMN*KD_/2 + 255)/256, 256>>>(mem_keys, (__half*)pMK16, MEMN*KD_);
    cvt_half<<<(RB*KD_/2 + 255)/256,   256>>>(queries,  (__half*)pQI16, RB*KD_);
    split_f32<<<(BWN*KD_/2 + 255)/256, 256>>>(write_keys, (bf16*)pWKh, (bf16*)pWKl, BWN*KD_);
    normalize_split<<<MEMN, 256>>>(mem_keys,   (bf16*)pMNh, (bf16*)pMNl);
    normalize_split<<<BWN,  256>>>(write_keys, (bf16*)pKNh, (bf16*)pKNl);

    // ---- write path ----
    bgemm3<<<dim3(MEMN/TN, BWN/TM3), 256, DYN3>>>(
        (bf16*)pKNh, (bf16*)pKNl, (bf16*)pMNh, (bf16*)pMNl,
        nullptr, (float*)pSIM, BWN, MEMN, KD_, 1.0f);
    argmax_rows<<<BWN, 256>>>((float*)pSIM, (int*)pIdx);
    gather_split<<<BWN, 256>>>(mem_values, (int*)pIdx, (bf16*)pGVh, (bf16*)pGVl);
    bgemm3<<<dim3(KD_/TN, BWN/TM3), 256, DYN3>>>(
        (bf16*)pGVh, (bf16*)pGVl, (bf16*)pWgBh, (bf16*)pWgBl,
        nullptr, (float*)pBV, BWN, KD_, KD_, 1.0f);
    bgemm3<<<dim3(KD_/TN, BWN/TM3), 256, DYN3>>>(
        (bf16*)pWKh, (bf16*)pWKl, (bf16*)pWgTh, (bf16*)pWgTl,
        bg, (float*)pA, BWN, KD_, KD_, 1.0f);
    cudaMemcpyAsync(out_k, mem_keys,   (size_t)MEMN * KD_ * sizeof(float), cudaMemcpyDeviceToDevice);
    cudaMemcpyAsync(out_v, mem_values, (size_t)MEMN * KD_ * sizeof(float), cudaMemcpyDeviceToDevice);
    chain_update<<<MEMN, 256>>>(write_keys, write_vals, Wg, (float*)pA, (float*)pBV,
                                (int*)pIdx, mem_keys, mem_values, out_k, out_v);

    // ---- read path ----
    hgemm1<1,4><<<dim3((HH*KD_)/TN, RB/256), 256, DYN1_256>>>(
        (__half*)pQI16, (__half*)pWqT16, bq, nullptr, (__half*)pQ16,
        RB, HH*KD_, KD_, qscale);
    hgemm1<0,4><<<dim3(MEMN/TN, RQ/256), 256, DYN1_256>>>(
        (__half*)pQ16, (__half*)pMK16, nullptr, (float*)pS, nullptr,
        RQ, MEMN, KD_, 1.0f);
    softmax_h<<<RQ, 256>>>((float*)pS, (__half*)pP16);
    hgemm1<2,4><<<dim3(KD_/TN, RQ/256), 256, DYN1_256>>>(
        (__half*)pP16, (__half*)pMVT16, nullptr, nullptr, (__half*)pRV16,
        RQ, KD_, MEMN, 1.0f / 512.0f);
    hgemm1<0,2><<<dim3(KD_/TN, RB/128), 128, DYN1_128>>>(
        (__half*)pRV16, (__half*)pWvpT16, bvp, out_read, nullptr,
        RB, KD_, HH*KD_, 1.0f);
}

// round 7
// speedup vs baseline: 5.7675x; 1.0782x over previous
#include <cuda_runtime.h>
#include <cuda_bf16.h>
#include <cuda_fp16.h>
#include <math.h>
#include <stdint.h>

#define BB   4
#define NN_  1024
#define KD_  512
#define HH   8
#define MEMN 4096
#define BWN  1024
#define RQ   (BB*HH*NN_)
#define RB   (BB*NN_)

typedef __nv_bfloat16 bf16;

// ---------------- scratch ----------------
__device__ float  g_S  [(size_t)RQ * MEMN];
__device__ float  g_A  [(size_t)BWN * KD_];          // wk@WgTop + bg
__device__ float  g_BV [(size_t)BWN * KD_];          // V0[idx]@WgBot
__device__ int    g_idx[BWN];
__device__ unsigned long long g_pk[BWN];             // packed (val,idx) argmax
__device__ __half g_QI16[(size_t)RB * KD_];
__device__ __half g_Q16[(size_t)RQ * KD_];
__device__ __half g_P16[(size_t)RQ * MEMN];
__device__ __half g_RV16[(size_t)RB * (HH*KD_)];
__device__ __half g_MK16[(size_t)MEMN * KD_];
__device__ __half g_MVT16[(size_t)KD_ * MEMN];
__device__ __half g_WqT16[(size_t)(HH*KD_) * KD_];
__device__ __half g_WvpT16[(size_t)KD_ * (HH*KD_)];
__device__ bf16 g_KNh[(size_t)BWN * KD_],  g_KNl[(size_t)BWN * KD_];
__device__ bf16 g_MNh[(size_t)MEMN * KD_], g_MNl[(size_t)MEMN * KD_];
__device__ bf16 g_WgTh[(size_t)KD_ * KD_], g_WgTl[(size_t)KD_ * KD_];
__device__ bf16 g_WgBh[(size_t)KD_ * KD_], g_WgBl[(size_t)KD_ * KD_];
__device__ bf16 g_GAh[(size_t)2*BWN * KD_], g_GAl[(size_t)2*BWN * KD_];  // [wk rows | V0[idx] rows]

// ---------------- helpers ----------------
__device__ __forceinline__ uint32_t smem_to_u32(const void* p) {
    uint32_t a;
    asm("{ .reg .u64 t; cvta.to.shared.u64 t, %1; cvt.u32.u64 %0, t; }" : "=r"(a) : "l"(p));
    return a;
}
__device__ __forceinline__ void ldsm4(uint32_t* r, uint32_t addr) {
    asm volatile("ldmatrix.sync.aligned.m8n8.x4.shared.b16 {%0,%1,%2,%3}, [%4];"
                 : "=r"(r[0]), "=r"(r[1]), "=r"(r[2]), "=r"(r[3]) : "r"(addr));
}
__device__ __forceinline__ void mma_bf(float* c, const uint32_t* a, const uint32_t* b) {
    asm volatile(
        "mma.sync.aligned.m16n8k16.row.col.f32.bf16.bf16.f32 "
        "{%0,%1,%2,%3}, {%4,%5,%6,%7}, {%8,%9}, {%0,%1,%2,%3};"
        : "+f"(c[0]), "+f"(c[1]), "+f"(c[2]), "+f"(c[3])
        : "r"(a[0]), "r"(a[1]), "r"(a[2]), "r"(a[3]), "r"(b[0]), "r"(b[1]));
}
__device__ __forceinline__ void mma_fp(float* c, const uint32_t* a, const uint32_t* b) {
    asm volatile(
        "mma.sync.aligned.m16n8k16.row.col.f32.f16.f16.f32 "
        "{%0,%1,%2,%3}, {%4,%5,%6,%7}, {%8,%9}, {%0,%1,%2,%3};"
        : "+f"(c[0]), "+f"(c[1]), "+f"(c[2]), "+f"(c[3])
        : "r"(a[0]), "r"(a[1]), "r"(a[2]), "r"(a[3]), "r"(b[0]), "r"(b[1]));
}
__device__ __forceinline__ void cp16(uint32_t dst, const void* src) {
    asm volatile("cp.async.cg.shared.global [%0], [%1], 16;" :: "r"(dst), "l"(src));
}
#define CP_COMMIT() asm volatile("cp.async.commit_group;" ::: "memory")
#define CP_WAIT1()  asm volatile("cp.async.wait_group 1;" ::: "memory")

__device__ __forceinline__ void splitpack(float x, float y, uint32_t& h, uint32_t& l) {
    bf16 hx = __float2bfloat16(x), hy = __float2bfloat16(y);
    float rx = x - __bfloat162float(hx), ry = y - __bfloat162float(hy);
    bf16 lx = __float2bfloat16(rx), ly = __float2bfloat16(ry);
    h = (uint32_t)__bfloat16_as_ushort(hx) | ((uint32_t)__bfloat16_as_ushort(hy) << 16);
    l = (uint32_t)__bfloat16_as_ushort(lx) | ((uint32_t)__bfloat16_as_ushort(ly) << 16);
}
__device__ __forceinline__ unsigned long long packmax(float v, int col) {
    uint32_t b = __float_as_uint(v);
    b = (b & 0x80000000u) ? ~b : (b | 0x80000000u);
    return ((unsigned long long)b << 32) | (unsigned long long)(0xFFFFFFFFu - (uint32_t)col);
}

#define TN 128
#define ROWB 144    // KC=32 bf16 hi|lo row
#define ROWB1 272   // KC=128 fp16 row

template<int MODE>
__device__ __forceinline__ size_t dst_of(int r, int c, int N) {
    if (MODE == 0) return (size_t)r * N + c;
    if (MODE == 1) {
        const int b_ = r >> 10, n_ = r & 1023, h_ = c >> 9, d_ = c & 511;
        return ((size_t)((b_ * 8 + h_) * 1024 + n_) << 9) + d_;
    }
    const int b_ = r >> 13, h_ = (r >> 10) & 7, n_ = r & 1023;
    return ((size_t)(b_ * 1024 + n_) << 12) + ((size_t)h_ << 9) + c;
}

// ================= 3-term split-bf16 GEMM, TM=256 (MODE 3: fused row-argmax) =================
#define TM3 256
#define KC3 32
#define STAGE3 ((TM3 + TN) * ROWB)
#define DYN3 (2 * STAGE3)

template<int MODE>
__global__ void __launch_bounds__(256, 1)
bgemm3(const bf16* __restrict__ Ah, const bf16* __restrict__ Al,
       const bf16* __restrict__ Bh, const bf16* __restrict__ Bl,
       const float* __restrict__ bias, float* __restrict__ C,
       unsigned long long* __restrict__ Packed,
       int M, int N, int K, float scale)
{
    extern __shared__ char sm[];
    const uint32_t smem_u = smem_to_u32(sm);
    const int tid = threadIdx.x;
    const int lane = tid & 31, wid = tid >> 5;
    const int bm = blockIdx.y * TM3, bn = blockIdx.x * TN;
    const int wm = (wid >> 1) * 64, wn = (wid & 1) * 64;

    float acc[4][8][4];
#pragma unroll
    for (int i = 0; i < 4; i++)
#pragma unroll
        for (int j = 0; j < 8; j++)
#pragma unroll
            for (int k = 0; k < 4; k++) acc[i][j][k] = 0.0f;

    const int NC = K / KC3;

    auto load_chunk = [&](int c, int st) {
        const int k0 = c * KC3;
        const uint32_t sb = smem_u + st * STAGE3;
#pragma unroll
        for (int u = 0; u < 3; u++) {
            const int unit = tid + u * 256;
            const int r = (unit & 511) >> 1, pl = unit & 1;
            const bf16* src;
            uint32_t dst;
            if (unit < 512) {
                src = (pl ? Al : Ah) + (size_t)(bm + r) * K + k0;
                dst = sb + r * ROWB + pl * 64;
            } else {
                src = (pl ? Bl : Bh) + (size_t)(bn + r) * K + k0;
                dst = sb + (TM3 + r) * ROWB + pl * 64;
            }
#pragma unroll
            for (int i = 0; i < 4; i++) cp16(dst + i * 16, src + i * 8);
        }
    };

    load_chunk(0, 0); CP_COMMIT();
    load_chunk(1, 1); CP_COMMIT();

    const int mr = lane & 7, msel = lane >> 3;
    const int aro = ((msel & 1) << 3) + mr;
    const int aco = (msel >> 1) << 3;
    const int bro = ((msel >> 1) << 3) + mr;
    const int bco = (msel & 1) << 3;

    for (int c = 0; c < NC; c++) {
        CP_WAIT1();
        __syncthreads();
        const uint32_t base = smem_u + (c & 1) * STAGE3;
#pragma unroll
        for (int ks = 0; ks < 2; ks++) {
            uint32_t ah[4][4], al[4][4], bh[8][2], bl[8][2];
            const int colA = (ks * 16 + aco) * 2;
            const int colB = (ks * 16 + bco) * 2;
#pragma unroll
            for (int mi = 0; mi < 4; mi++) {
                const uint32_t ad = base + (wm + mi * 16 + aro) * ROWB + colA;
                ldsm4(ah[mi], ad);
                ldsm4(al[mi], ad + 64);
            }
#pragma unroll
            for (int g = 0; g < 4; g++) {
                const uint32_t bd = base + (TM3 + wn + g * 16 + bro) * ROWB + colB;
                uint32_t t[4];
                ldsm4(t, bd);
                bh[2*g][0] = t[0]; bh[2*g][1] = t[1];
                bh[2*g+1][0] = t[2]; bh[2*g+1][1] = t[3];
                ldsm4(t, bd + 64);
                bl[2*g][0] = t[0]; bl[2*g][1] = t[1];
                bl[2*g+1][0] = t[2]; bl[2*g+1][1] = t[3];
            }
#pragma unroll
            for (int mi = 0; mi < 4; mi++)
#pragma unroll
                for (int nb = 0; nb < 8; nb++) {
                    mma_bf(acc[mi][nb], ah[mi], bh[nb]);
                    mma_bf(acc[mi][nb], ah[mi], bl[nb]);
                    mma_bf(acc[mi][nb], al[mi], bh[nb]);
                }
        }
        __syncthreads();
        if (c + 2 < NC) load_chunk(c + 2, c & 1);
        CP_COMMIT();
    }

    const int group = lane >> 2, tig = lane & 3;
    if (MODE == 3) {
        // fused per-row argmax: reduce within thread, then across the tig quad, then atomic
#pragma unroll
        for (int mi = 0; mi < 4; mi++) {
#pragma unroll
            for (int half = 0; half < 2; half++) {
                const int row = bm + wm + mi * 16 + group + half * 8;
                float bv = -1e30f; int bc = 0;
#pragma unroll
                for (int nb = 0; nb < 8; nb++) {
                    const int col = bn + wn + nb * 8 + tig * 2;
                    const float v0 = acc[mi][nb][half * 2 + 0];
                    const float v1 = acc[mi][nb][half * 2 + 1];
                    if (v0 > bv) { bv = v0; bc = col; }
                    if (v1 > bv) { bv = v1; bc = col + 1; }
                }
#pragma unroll
                for (int m = 1; m <= 2; m <<= 1) {
                    float ov = __shfl_xor_sync(0xffffffffu, bv, m);
                    int   oc = __shfl_xor_sync(0xffffffffu, bc, m);
                    if (ov > bv || (ov == bv && oc < bc)) { bv = ov; bc = oc; }
                }
                if (tig == 0) atomicMax(Packed + row, packmax(bv, bc));
            }
        }
    } else {
#pragma unroll
        for (int mi = 0; mi < 4; mi++) {
            const int r_lo = bm + wm + mi * 16 + group;
#pragma unroll
            for (int nb = 0; nb < 8; nb++) {
                const int col = bn + wn + nb * 8 + tig * 2;
                float b0 = 0.0f, b1 = 0.0f;
                if (bias) { b0 = bias[col]; b1 = bias[col + 1]; }
                *reinterpret_cast<float2*>(&C[(size_t)r_lo * N + col]) =
                    make_float2((acc[mi][nb][0] + b0) * scale, (acc[mi][nb][1] + b1) * scale);
                *reinterpret_cast<float2*>(&C[(size_t)(r_lo + 8) * N + col]) =
                    make_float2((acc[mi][nb][2] + b0) * scale, (acc[mi][nb][3] + b1) * scale);
            }
        }
    }
}

// ====== small-tile 3-term gate GEMM: M=2048 (rows<1024: WgT+bias->outA; else WgB->outBV) ======
#define TMS 64
#define TNS 64
#define STAGES ((TMS + TNS) * ROWB)     // 18432
#define DYNS (2 * STAGES)

__global__ void __launch_bounds__(128, 1)
bgemm3s(const bf16* __restrict__ Ah, const bf16* __restrict__ Al,
        const bf16* __restrict__ B1h, const bf16* __restrict__ B1l,
        const bf16* __restrict__ B2h, const bf16* __restrict__ B2l,
        const float* __restrict__ bias, float* __restrict__ outA, float* __restrict__ outBV)
{
    constexpr int K = KD_, N = KD_;
    extern __shared__ char sm[];
    const uint32_t smem_u = smem_to_u32(sm);
    const int tid = threadIdx.x;
    const int lane = tid & 31, wid = tid >> 5;
    const int bm = blockIdx.y * TMS, bn = blockIdx.x * TNS;
    const bool second = bm >= BWN;
    const bf16* Bh = second ? B2h : B1h;
    const bf16* Bl = second ? B2l : B1l;
    float* out = second ? outBV : outA;
    const int rowbase = second ? bm - BWN : bm;
    const int wm = (wid >> 1) * 32, wn = (wid & 1) * 32;

    float acc[2][4][4];
#pragma unroll
    for (int i = 0; i < 2; i++)
#pragma unroll
        for (int j = 0; j < 4; j++)
#pragma unroll
            for (int k = 0; k < 4; k++) acc[i][j][k] = 0.0f;

    const int NC = K / KC3;   // 16

    auto load_chunk = [&](int c, int st) {
        const int k0 = c * KC3;
        const uint32_t sb = smem_u + st * STAGES;
#pragma unroll
        for (int u = 0; u < 2; u++) {
            const int unit = tid + u * 128;
            const int r = (unit & 127) >> 1, pl = unit & 1;
            const bf16* src;
            uint32_t dst;
            if (unit < 128) {
                src = (pl ? Al : Ah) + (size_t)(bm + r) * K + k0;
                dst = sb + r * ROWB + pl * 64;
            } else {
                src = (pl ? Bl : Bh) + (size_t)(bn + r) * K + k0;
                dst = sb + (TMS + r) * ROWB + pl * 64;
            }
#pragma unroll
            for (int i = 0; i < 4; i++) cp16(dst + i * 16, src + i * 8);
        }
    };

    load_chunk(0, 0); CP_COMMIT();
    load_chunk(1, 1); CP_COMMIT();

    const int mr = lane & 7, msel = lane >> 3;
    const int aro = ((msel & 1) << 3) + mr;
    const int aco = (msel >> 1) << 3;
    const int bro = ((msel >> 1) << 3) + mr;
    const int bco = (msel & 1) << 3;

    for (int c = 0; c < NC; c++) {
        CP_WAIT1();
        __syncthreads();
        const uint32_t base = smem_u + (c & 1) * STAGES;
#pragma unroll
        for (int ks = 0; ks < 2; ks++) {
            uint32_t ah[2][4], al[2][4], bh[4][2], bl[4][2];
            const int colA = (ks * 16 + aco) * 2;
            const int colB = (ks * 16 + bco) * 2;
#pragma unroll
            for (int mi = 0; mi < 2; mi++) {
                const uint32_t ad = base + (wm + mi * 16 + aro) * ROWB + colA;
                ldsm4(ah[mi], ad);
                ldsm4(al[mi], ad + 64);
            }
#pragma unroll
            for (int g = 0; g < 2; g++) {
                const uint32_t bd = base + (TMS + wn + g * 16 + bro) * ROWB + colB;
                uint32_t t[4];
                ldsm4(t, bd);
                bh[2*g][0] = t[0]; bh[2*g][1] = t[1];
                bh[2*g+1][0] = t[2]; bh[2*g+1][1] = t[3];
                ldsm4(t, bd + 64);
                bl[2*g][0] = t[0]; bl[2*g][1] = t[1];
                bl[2*g+1][0] = t[2]; bl[2*g+1][1] = t[3];
            }
#pragma unroll
            for (int mi = 0; mi < 2; mi++)
#pragma unroll
                for (int nb = 0; nb < 4; nb++) {
                    mma_bf(acc[mi][nb], ah[mi], bh[nb]);
                    mma_bf(acc[mi][nb], ah[mi], bl[nb]);
                    mma_bf(acc[mi][nb], al[mi], bh[nb]);
                }
        }
        __syncthreads();
        if (c + 2 < NC) load_chunk(c + 2, c & 1);
        CP_COMMIT();
    }

    const int group = lane >> 2, tig = lane & 3;
#pragma unroll
    for (int mi = 0; mi < 2; mi++) {
        const int r_lo = rowbase + wm + mi * 16 + group;
#pragma unroll
        for (int nb = 0; nb < 4; nb++) {
            const int col = bn + wn + nb * 8 + tig * 2;
            float b0 = 0.0f, b1 = 0.0f;
            if (!second) { b0 = bias[col]; b1 = bias[col + 1]; }
            *reinterpret_cast<float2*>(&out[(size_t)r_lo * N + col]) =
                make_float2(acc[mi][nb][0] + b0, acc[mi][nb][1] + b1);
            *reinterpret_cast<float2*>(&out[(size_t)(r_lo + 8) * N + col]) =
                make_float2(acc[mi][nb][2] + b0, acc[mi][nb][3] + b1);
        }
    }
}

// ================= single-term fp16 GEMM (KC=128), TM = WM*64 =================
#define KC1 128

template<int MODE, int WM>
__global__ void __launch_bounds__(WM*64, 1)
hgemm1(const __half* __restrict__ A, const __half* __restrict__ B,
       const float* __restrict__ bias,
       float* __restrict__ C, __half* __restrict__ C16,
       int M, int N, int K, float scale)
{
    constexpr int TMv = WM * 64;
    constexpr int NT  = WM * 64;
    constexpr int STAGE = (TMv + TN) * ROWB1;
    extern __shared__ char sm[];
    const uint32_t smem_u = smem_to_u32(sm);
    const int tid = threadIdx.x;
    const int lane = tid & 31, wid = tid >> 5;
    const int bm = blockIdx.y * TMv, bn = blockIdx.x * TN;
    const int wm = (wid >> 1) * 64, wn = (wid & 1) * 64;

    float acc[4][8][4];
#pragma unroll
    for (int i = 0; i < 4; i++)
#pragma unroll
        for (int j = 0; j < 8; j++)
#pragma unroll
            for (int k = 0; k < 4; k++) acc[i][j][k] = 0.0f;

    const int NC = K / KC1;

    auto load_chunk = [&](int c, int st) {
        const int k0 = c * KC1;
        const uint32_t sb = smem_u + st * STAGE;
#pragma unroll
        for (int u = tid; u < (TMv + TN) * 16; u += NT) {
            const int r = u >> 4, seg = u & 15;
            const __half* src = (r < TMv)
                ? A + (size_t)(bm + r) * K + k0 + seg * 8
                : B + (size_t)(bn + (r - TMv)) * K + k0 + seg * 8;
            cp16(sb + r * ROWB1 + seg * 16, src);
        }
    };

    load_chunk(0, 0); CP_COMMIT();
    load_chunk(1, 1); CP_COMMIT();

    const int mr = lane & 7, msel = lane >> 3;
    const int aro = ((msel & 1) << 3) + mr;
    const int aco = (msel >> 1) << 3;
    const int bro = ((msel >> 1) << 3) + mr;
    const int bco = (msel & 1) << 3;

    for (int c = 0; c < NC; c++) {
        CP_WAIT1();
        __syncthreads();
        const uint32_t base = smem_u + (c & 1) * STAGE;
#pragma unroll
        for (int ks = 0; ks < 8; ks++) {
            uint32_t ah[4][4], bh[8][2];
            const int colA = (ks * 16 + aco) * 2;
            const int colB = (ks * 16 + bco) * 2;
#pragma unroll
            for (int mi = 0; mi < 4; mi++)
                ldsm4(ah[mi], base + (wm + mi * 16 + aro) * ROWB1 + colA);
#pragma unroll
            for (int g = 0; g < 4; g++) {
                uint32_t t[4];
                ldsm4(t, base + (TMv + wn + g * 16 + bro) * ROWB1 + colB);
                bh[2*g][0] = t[0]; bh[2*g][1] = t[1];
                bh[2*g+1][0] = t[2]; bh[2*g+1][1] = t[3];
            }
#pragma unroll
            for (int mi = 0; mi < 4; mi++)
#pragma unroll
                for (int nb = 0; nb < 8; nb++)
                    mma_fp(acc[mi][nb], ah[mi], bh[nb]);
        }
        __syncthreads();
        if (c + 2 < NC) load_chunk(c + 2, c & 1);
        CP_COMMIT();
    }

    const int group = lane >> 2, tig = lane & 3;
#pragma unroll
    for (int mi = 0; mi < 4; mi++) {
        const int r_lo = bm + wm + mi * 16 + group;
#pragma unroll
        for (int nb = 0; nb < 8; nb++) {
            const int col = bn + wn + nb * 8 + tig * 2;
            float b0 = 0.0f, b1 = 0.0f;
            if (bias) { b0 = bias[col]; b1 = bias[col + 1]; }
            float v00 = (acc[mi][nb][0] + b0) * scale;
            float v01 = (acc[mi][nb][1] + b1) * scale;
            float v10 = (acc[mi][nb][2] + b0) * scale;
            float v11 = (acc[mi][nb][3] + b1) * scale;
            if (MODE == 0) {
                *reinterpret_cast<float2*>(&C[dst_of<0>(r_lo,     col, N)]) = make_float2(v00, v01);
                *reinterpret_cast<float2*>(&C[dst_of<0>(r_lo + 8, col, N)]) = make_float2(v10, v11);
            } else {
                *reinterpret_cast<__half2*>(&C16[dst_of<MODE>(r_lo,     col, N)]) = __floats2half2_rn(v00, v01);
                *reinterpret_cast<__half2*>(&C16[dst_of<MODE>(r_lo + 8, col, N)]) = __floats2half2_rn(v10, v11);
            }
        }
    }
}

// ---------------- prep / small kernels ----------------
__global__ void __launch_bounds__(256) transpose_split(const float* __restrict__ in,
                                                       bf16* __restrict__ oh, bf16* __restrict__ ol,
                                                       int R, int C)
{
    __shared__ float t[32][33];
    const int c0 = blockIdx.x * 32, r0 = blockIdx.y * 32;
    const int x = threadIdx.x & 31, y = threadIdx.x >> 5;
#pragma unroll
    for (int i = 0; i < 32; i += 8) t[y + i][x] = in[(size_t)(r0 + y + i) * C + c0 + x];
    __syncthreads();
#pragma unroll
    for (int i = 0; i < 32; i += 8) {
        float v = t[x][y + i];
        bf16 h = __float2bfloat16(v);
        bf16 l = __float2bfloat16(v - __bfloat162float(h));
        const size_t d = (size_t)(c0 + y + i) * R + r0 + x;
        oh[d] = h; ol[d] = l;
    }
}

__global__ void __launch_bounds__(256) transpose_half(const float* __restrict__ in,
                                                      __half* __restrict__ out, int R, int C)
{
    __shared__ float t[32][33];
    const int c0 = blockIdx.x * 32, r0 = blockIdx.y * 32;
    const int x = threadIdx.x & 31, y = threadIdx.x >> 5;
#pragma unroll
    for (int i = 0; i < 32; i += 8) t[y + i][x] = in[(size_t)(r0 + y + i) * C + c0 + x];
    __syncthreads();
#pragma unroll
    for (int i = 0; i < 32; i += 8)
        out[(size_t)(c0 + y + i) * R + r0 + x] = __float2half(t[x][y + i]);
}

__global__ void __launch_bounds__(256) cvt_half(const float* __restrict__ in,
                                                __half* __restrict__ out, int n2)
{
    int i = (blockIdx.x * 256 + threadIdx.x) * 2;
    if (i < n2) {
        float2 v = *reinterpret_cast<const float2*>(&in[i]);
        *reinterpret_cast<__half2*>(&out[i]) = __floats2half2_rn(v.x, v.y);
    }
}

// mem_keys: one read -> normalized bf16 planes + raw fp16
__global__ void __launch_bounds__(256) mem_prep(const float* __restrict__ X,
                                                bf16* __restrict__ oh, bf16* __restrict__ ol,
                                                __half* __restrict__ o16)
{
    __shared__ float red[256];
    const int r = blockIdx.x, tid = threadIdx.x;
    const float* p = X + (size_t)r * KD_;
    float ss = 0.0f;
    for (int i = tid; i < KD_; i += 256) { float v = p[i]; ss += v * v; }
    red[tid] = ss; __syncthreads();
    for (int s = 128; s > 0; s >>= 1) { if (tid < s) red[tid] += red[tid + s]; __syncthreads(); }
    const float inv = 1.0f / fmaxf(sqrtf(red[0]), 1e-8f);
    const int i = tid * 2;
    float2 v = *reinterpret_cast<const float2*>(&p[i]);
    uint32_t h, l;
    splitpack(v.x * inv, v.y * inv, h, l);
    *reinterpret_cast<uint32_t*>(&oh[(size_t)r * KD_ + i]) = h;
    *reinterpret_cast<uint32_t*>(&ol[(size_t)r * KD_ + i]) = l;
    *reinterpret_cast<__half2*>(&o16[(size_t)r * KD_ + i]) = __floats2half2_rn(v.x, v.y);
}

// write_keys: one read -> normalized planes (for sim) + raw planes (gate GEMM top half)
__global__ void __launch_bounds__(256) wk_prep(const float* __restrict__ X,
                                               bf16* __restrict__ nh, bf16* __restrict__ nl,
                                               bf16* __restrict__ gh, bf16* __restrict__ gl)
{
    __shared__ float red[256];
    const int r = blockIdx.x, tid = threadIdx.x;
    const float* p = X + (size_t)r * KD_;
    float ss = 0.0f;
    for (int i = tid; i < KD_; i += 256) { float v = p[i]; ss += v * v; }
    red[tid] = ss; __syncthreads();
    for (int s = 128; s > 0; s >>= 1) { if (tid < s) red[tid] += red[tid + s]; __syncthreads(); }
    const float inv = 1.0f / fmaxf(sqrtf(red[0]), 1e-8f);
    const int i = tid * 2;
    float2 v = *reinterpret_cast<const float2*>(&p[i]);
    uint32_t h, l;
    splitpack(v.x * inv, v.y * inv, h, l);
    *reinterpret_cast<uint32_t*>(&nh[(size_t)r * KD_ + i]) = h;
    *reinterpret_cast<uint32_t*>(&nl[(size_t)r * KD_ + i]) = l;
    splitpack(v.x, v.y, h, l);
    *reinterpret_cast<uint32_t*>(&gh[(size_t)r * KD_ + i]) = h;
    *reinterpret_cast<uint32_t*>(&gl[(size_t)r * KD_ + i]) = l;
}

__global__ void __launch_bounds__(256) softmax_h(const float* __restrict__ S,
                                                 __half* __restrict__ P16)
{
    __shared__ float row[MEMN];
    __shared__ float red[256];
    const size_t r = blockIdx.x;
    const float* p = S + r * MEMN;
    const int tid = threadIdx.x;
    float mx = -1e30f;
    for (int i = tid * 2; i < MEMN; i += 512) {
        float2 v = *reinterpret_cast<const float2*>(&p[i]);
        row[i] = v.x; row[i+1] = v.y;
        mx = fmaxf(mx, fmaxf(v.x, v.y));
    }
    red[tid] = mx; __syncthreads();
    for (int s = 128; s > 0; s >>= 1) { if (tid < s) red[tid] = fmaxf(red[tid], red[tid + s]); __syncthreads(); }
    mx = red[0]; __syncthreads();
    float sum = 0.0f;
    for (int i = tid; i < MEMN; i += 256) { float e = expf(row[i] - mx); row[i] = e; sum += e; }
    red[tid] = sum; __syncthreads();
    for (int s = 128; s > 0; s >>= 1) { if (tid < s) red[tid] += red[tid + s]; __syncthreads(); }
    const float inv = 512.0f / red[0];
    __syncthreads();
    for (int i = tid * 2; i < MEMN; i += 512)
        *reinterpret_cast<__half2*>(&P16[r * MEMN + i]) =
            __floats2half2_rn(row[i] * inv, row[i+1] * inv);
}

// unpack argmax + gather V0[idx] into gate-GEMM bottom half
__global__ void __launch_bounds__(256) gather_unpack(const unsigned long long* __restrict__ pk,
                                                     const float* __restrict__ mv,
                                                     int* __restrict__ idx,
                                                     bf16* __restrict__ gh, bf16* __restrict__ gl)
{
    const int t = blockIdx.x, tid = threadIdx.x;
    const unsigned long long v = pk[t];
    const int col = (int)(0xFFFFFFFFu - (uint32_t)(v & 0xFFFFFFFFu));
    if (tid == 0) idx[t] = col;
    const float* src = mv + (size_t)col * KD_;
    const int i = tid * 2;
    uint32_t h, l;
    splitpack(src[i], src[i + 1], h, l);
    *reinterpret_cast<uint32_t*>(&gh[(size_t)(BWN + t) * KD_ + i]) = h;
    *reinterpret_cast<uint32_t*>(&gl[(size_t)(BWN + t) * KD_ + i]) = l;
}

__global__ void __launch_bounds__(256) chain_update(
    const float* __restrict__ wk, const float* __restrict__ wv,
    const float* __restrict__ Wg, const float* __restrict__ Aw,
    const float* __restrict__ BV,
    const int*   __restrict__ idx,
    const float* __restrict__ mk, const float* __restrict__ mv,
    float* __restrict__ outK, float* __restrict__ outV)
{
    __shared__ float sK[KD_], sV[KD_];
    __shared__ int   list[BWN];
    __shared__ int   cnt;
    const int s = blockIdx.x, tid = threadIdx.x;
    if (tid == 0) cnt = 0;
    __syncthreads();
    for (int t = tid; t < BWN; t += 256)
        if (idx[t] == s) { int p = atomicAdd(&cnt, 1); list[p] = t; }
    __syncthreads();
    const int n = cnt;
    if (n == 0) return;
    if (tid == 0) {
        for (int i = 1; i < n; i++) {
            int v = list[i], j = i - 1;
            while (j >= 0 && list[j] > v) { list[j + 1] = list[j]; j--; }
            list[j + 1] = v;
        }
    }
    for (int i = tid; i < KD_; i += 256) {
        sK[i] = mk[(size_t)s * KD_ + i];
        sV[i] = mv[(size_t)s * KD_ + i];
    }
    __syncthreads();
    for (int e = 0; e < n; e++) {
        const int t = list[e];
        const int j0 = tid, j1 = tid + 256;
        float a0, a1;
        if (e == 0) {
            a0 = Aw[(size_t)t * KD_ + j0] + BV[(size_t)t * KD_ + j0];
            a1 = Aw[(size_t)t * KD_ + j1] + BV[(size_t)t * KD_ + j1];
        } else {
            a0 = Aw[(size_t)t * KD_ + j0];
            a1 = Aw[(size_t)t * KD_ + j1];
#pragma unroll 8
            for (int r = 0; r < KD_; r++) {
                const float v = sV[r];
                const float* wrow = Wg + (size_t)(KD_ + r) * KD_;
                a0 += v * wrow[j0];
                a1 += v * wrow[j1];
            }
        }
        const float g0 = 1.0f / (1.0f + expf(-a0));
        const float g1 = 1.0f / (1.0f + expf(-a1));
        __syncthreads();
        sK[j0] = g0 * wk[(size_t)t * KD_ + j0] + (1.0f - g0) * sK[j0];
        sK[j1] = g1 * wk[(size_t)t * KD_ + j1] + (1.0f - g1) * sK[j1];
        sV[j0] = g0 * wv[(size_t)t * KD_ + j0] + (1.0f - g0) * sV[j0];
        sV[j1] = g1 * wv[(size_t)t * KD_ + j1] + (1.0f - g1) * sV[j1];
        __syncthreads();
    }
    for (int i = tid; i < KD_; i += 256) {
        outK[(size_t)s * KD_ + i] = sK[i];
        outV[(size_t)s * KD_ + i] = sV[i];
    }
}

// ---------------- launcher ----------------
extern "C" void kernel_launch(void* const* d_in, const int* in_sizes, int n_in,
                              void* d_out, int out_size)
{
    const float* queries    = (const float*)d_in[0];
    const float* write_keys = (const float*)d_in[1];
    const float* write_vals = (const float*)d_in[2];
    const float* mem_keys   = (const float*)d_in[3];
    const float* mem_values = (const float*)d_in[4];
    const float* Wq         = (const float*)d_in[5];
    const float* bq         = (const float*)d_in[6];
    const float* Wvp        = (const float*)d_in[7];
    const float* bvp        = (const float*)d_in[8];
    const float* Wg         = (const float*)d_in[9];
    const float* bg         = (const float*)d_in[10];

    float* out_read = (float*)d_out;
    float* out_k    = out_read + (size_t)RB * KD_;
    float* out_v    = out_k    + (size_t)MEMN * KD_;

    void *pS, *pA, *pBV, *pIdx, *pPk, *pQI16, *pQ16, *pP16, *pRV16, *pMK16, *pMVT16;
    void *pWqT16, *pWvpT16, *pKNh, *pKNl, *pMNh, *pMNl;
    void *pWgTh, *pWgTl, *pWgBh, *pWgBl, *pGAh, *pGAl;
    cudaGetSymbolAddress(&pS, g_S);
    cudaGetSymbolAddress(&pA, g_A);         cudaGetSymbolAddress(&pBV, g_BV);
    cudaGetSymbolAddress(&pIdx, g_idx);     cudaGetSymbolAddress(&pPk, g_pk);
    cudaGetSymbolAddress(&pQI16, g_QI16);   cudaGetSymbolAddress(&pQ16, g_Q16);
    cudaGetSymbolAddress(&pP16, g_P16);     cudaGetSymbolAddress(&pRV16, g_RV16);
    cudaGetSymbolAddress(&pMK16, g_MK16);   cudaGetSymbolAddress(&pMVT16, g_MVT16);
    cudaGetSymbolAddress(&pWqT16, g_WqT16); cudaGetSymbolAddress(&pWvpT16, g_WvpT16);
    cudaGetSymbolAddress(&pKNh, g_KNh);     cudaGetSymbolAddress(&pKNl, g_KNl);
    cudaGetSymbolAddress(&pMNh, g_MNh);     cudaGetSymbolAddress(&pMNl, g_MNl);
    cudaGetSymbolAddress(&pWgTh, g_WgTh);   cudaGetSymbolAddress(&pWgTl, g_WgTl);
    cudaGetSymbolAddress(&pWgBh, g_WgBh);   cudaGetSymbolAddress(&pWgBl, g_WgBl);
    cudaGetSymbolAddress(&pGAh, g_GAh);     cudaGetSymbolAddress(&pGAl, g_GAl);

    constexpr int DYN1_256 = 2 * (256 + TN) * ROWB1;   // 208896
    constexpr int DYN1_128 = 2 * (128 + TN) * ROWB1;   // 139264
    cudaFuncSetAttribute(bgemm3<3>,   cudaFuncAttributeMaxDynamicSharedMemorySize, DYN3);
    cudaFuncSetAttribute(bgemm3s,     cudaFuncAttributeMaxDynamicSharedMemorySize, DYNS);
    cudaFuncSetAttribute(hgemm1<0,4>, cudaFuncAttributeMaxDynamicSharedMemorySize, DYN1_256);
    cudaFuncSetAttribute(hgemm1<1,4>, cudaFuncAttributeMaxDynamicSharedMemorySize, DYN1_256);
    cudaFuncSetAttribute(hgemm1<2,4>, cudaFuncAttributeMaxDynamicSharedMemorySize, DYN1_256);
    cudaFuncSetAttribute(hgemm1<0,2>, cudaFuncAttributeMaxDynamicSharedMemorySize, DYN1_128);

    const float qscale = 0.044194173824159216f;  // 1/sqrt(512)/TEMP

    // ---- prep ----
    cudaMemsetAsync(pPk, 0, BWN * sizeof(unsigned long long));
    transpose_half<<<dim3((HH*KD_)/32, KD_/32), 256>>>(Wq, (__half*)pWqT16, KD_, HH*KD_);
    transpose_half<<<dim3(KD_/32, (HH*KD_)/32), 256>>>(Wvp, (__half*)pWvpT16, HH*KD_, KD_);
    transpose_half<<<dim3(KD_/32, MEMN/32),     256>>>(mem_values, (__half*)pMVT16, MEMN, KD_);
    transpose_split<<<dim3(KD_/32, KD_/32),     256>>>(Wg, (bf16*)pWgTh, (bf16*)pWgTl, KD_, KD_);
    transpose_split<<<dim3(KD_/32, KD_/32),     256>>>(Wg + (size_t)KD_ * KD_,
                                                       (bf16*)pWgBh, (bf16*)pWgBl, KD_, KD_);
    mem_prep<<<MEMN, 256>>>(mem_keys, (bf16*)pMNh, (bf16*)pMNl, (__half*)pMK16);
    wk_prep<<<BWN, 256>>>(write_keys, (bf16*)pKNh, (bf16*)pKNl, (bf16*)pGAh, (bf16*)pGAl);
    cvt_half<<<(RB*KD_/2 + 255)/256, 256>>>(queries, (__half*)pQI16, RB*KD_);

    // ---- write path ----
    bgemm3<3><<<dim3(MEMN/TN, BWN/TM3), 256, DYN3>>>(
        (bf16*)pKNh, (bf16*)pKNl, (bf16*)pMNh, (bf16*)pMNl,
        nullptr, nullptr, (unsigned long long*)pPk, BWN, MEMN, KD_, 1.0f);
    gather_unpack<<<BWN, 256>>>((unsigned long long*)pPk, mem_values, (int*)pIdx,
                                (bf16*)pGAh, (bf16*)pGAl);
    bgemm3s<<<dim3(KD_/TNS, (2*BWN)/TMS), 128, DYNS>>>(
        (bf16*)pGAh, (bf16*)pGAl,
        (bf16*)pWgTh, (bf16*)pWgTl, (bf16*)pWgBh, (bf16*)pWgBl,
        bg, (float*)pA, (float*)pBV);
    cudaMemcpyAsync(out_k, mem_keys,   (size_t)MEMN * KD_ * sizeof(float), cudaMemcpyDeviceToDevice);
    cudaMemcpyAsync(out_v, mem_values, (size_t)MEMN * KD_ * sizeof(float), cudaMemcpyDeviceToDevice);
    chain_update<<<MEMN, 256>>>(write_keys, write_vals, Wg, (float*)pA, (float*)pBV,
                                (int*)pIdx, mem_keys, mem_values, out_k, out_v);

    // ---- read path ----
    hgemm1<1,4><<<dim3((HH*KD_)/TN, RB/256), 256, DYN1_256>>>(
        (__half*)pQI16, (__half*)pWqT16, bq, nullptr, (__half*)pQ16,
        RB, HH*KD_, KD_, qscale);
    hgemm1<0,4><<<dim3(MEMN/TN, RQ/256), 256, DYN1_256>>>(
        (__half*)pQ16, (__half*)pMK16, nullptr, (float*)pS, nullptr,
        RQ, MEMN, KD_, 1.0f);
    softmax_h<<<RQ, 256>>>((float*)pS, (__half*)pP16);
    hgemm1<2,4><<<dim3(KD_/TN, RQ/256), 256, DYN1_256>>>(
        (__half*)pP16, (__half*)pMVT16, nullptr, nullptr, (__half*)pRV16,
        RQ, KD_, MEMN, 1.0f / 512.0f);
    hgemm1<0,2><<<dim3(KD_/TN, RB/128), 128, DYN1_128>>>(
        (__half*)pRV16, (__half*)pWvpT16, bvp, out_read, nullptr,
        RB, KD_, HH*KD_, 1.0f);
}

// round 8
// speedup vs baseline: 5.9683x; 1.0348x over previous
#include <cuda_runtime.h>
#include <cuda_bf16.h>
#include <cuda_fp16.h>
#include <math.h>
#include <stdint.h>

#define BB   4
#define NN_  1024
#define KD_  512
#define HH   8
#define MEMN 4096
#define BWN  1024
#define RQ   (BB*HH*NN_)
#define RB   (BB*NN_)

typedef __nv_bfloat16 bf16;

// ---------------- scratch ----------------
__device__ __half g_S16[(size_t)RQ * MEMN];          // scores fp16 (256 MB)
__device__ float  g_A  [(size_t)BWN * KD_];          // wk@WgTop + bg
__device__ float  g_BV [(size_t)BWN * KD_];          // V0[idx]@WgBot
__device__ int    g_idx[BWN];
__device__ unsigned long long g_pk[BWN];             // packed (val,idx) argmax
__device__ __half g_QI16[(size_t)RB * KD_];
__device__ __half g_Q16[(size_t)RQ * KD_];
__device__ __half g_P16[(size_t)RQ * MEMN];
__device__ __half g_RV16[(size_t)RB * (HH*KD_)];
__device__ __half g_MK16[(size_t)MEMN * KD_];
__device__ __half g_MVT16[(size_t)KD_ * MEMN];
__device__ __half g_WqT16[(size_t)(HH*KD_) * KD_];
__device__ __half g_WvpT16[(size_t)KD_ * (HH*KD_)];
__device__ bf16 g_KNh[(size_t)BWN * KD_],  g_KNl[(size_t)BWN * KD_];
__device__ bf16 g_MNh[(size_t)MEMN * KD_], g_MNl[(size_t)MEMN * KD_];
__device__ bf16 g_WgTh[(size_t)KD_ * KD_], g_WgTl[(size_t)KD_ * KD_];
__device__ bf16 g_WgBh[(size_t)KD_ * KD_], g_WgBl[(size_t)KD_ * KD_];
__device__ bf16 g_WB16[(size_t)KD_ * KD_];            // WgBot row-major bf16 (chain matvec)
__device__ bf16 g_GAh[(size_t)2*BWN * KD_], g_GAl[(size_t)2*BWN * KD_];  // [wk rows | V0[idx] rows]

// ---------------- helpers ----------------
__device__ __forceinline__ uint32_t smem_to_u32(const void* p) {
    uint32_t a;
    asm("{ .reg .u64 t; cvta.to.shared.u64 t, %1; cvt.u32.u64 %0, t; }" : "=r"(a) : "l"(p));
    return a;
}
__device__ __forceinline__ void ldsm4(uint32_t* r, uint32_t addr) {
    asm volatile("ldmatrix.sync.aligned.m8n8.x4.shared.b16 {%0,%1,%2,%3}, [%4];"
                 : "=r"(r[0]), "=r"(r[1]), "=r"(r[2]), "=r"(r[3]) : "r"(addr));
}
__device__ __forceinline__ void mma_bf(float* c, const uint32_t* a, const uint32_t* b) {
    asm volatile(
        "mma.sync.aligned.m16n8k16.row.col.f32.bf16.bf16.f32 "
        "{%0,%1,%2,%3}, {%4,%5,%6,%7}, {%8,%9}, {%0,%1,%2,%3};"
        : "+f"(c[0]), "+f"(c[1]), "+f"(c[2]), "+f"(c[3])
        : "r"(a[0]), "r"(a[1]), "r"(a[2]), "r"(a[3]), "r"(b[0]), "r"(b[1]));
}
__device__ __forceinline__ void mma_fp(float* c, const uint32_t* a, const uint32_t* b) {
    asm volatile(
        "mma.sync.aligned.m16n8k16.row.col.f32.f16.f16.f32 "
        "{%0,%1,%2,%3}, {%4,%5,%6,%7}, {%8,%9}, {%0,%1,%2,%3};"
        : "+f"(c[0]), "+f"(c[1]), "+f"(c[2]), "+f"(c[3])
        : "r"(a[0]), "r"(a[1]), "r"(a[2]), "r"(a[3]), "r"(b[0]), "r"(b[1]));
}
__device__ __forceinline__ void cp16(uint32_t dst, const void* src) {
    asm volatile("cp.async.cg.shared.global [%0], [%1], 16;" :: "r"(dst), "l"(src));
}
#define CP_COMMIT() asm volatile("cp.async.commit_group;" ::: "memory")
#define CP_WAIT1()  asm volatile("cp.async.wait_group 1;" ::: "memory")

__device__ __forceinline__ void splitpack(float x, float y, uint32_t& h, uint32_t& l) {
    bf16 hx = __float2bfloat16(x), hy = __float2bfloat16(y);
    float rx = x - __bfloat162float(hx), ry = y - __bfloat162float(hy);
    bf16 lx = __float2bfloat16(rx), ly = __float2bfloat16(ry);
    h = (uint32_t)__bfloat16_as_ushort(hx) | ((uint32_t)__bfloat16_as_ushort(hy) << 16);
    l = (uint32_t)__bfloat16_as_ushort(lx) | ((uint32_t)__bfloat16_as_ushort(ly) << 16);
}
__device__ __forceinline__ unsigned long long packmax(float v, int col) {
    uint32_t b = __float_as_uint(v);
    b = (b & 0x80000000u) ? ~b : (b | 0x80000000u);
    return ((unsigned long long)b << 32) | (unsigned long long)(0xFFFFFFFFu - (uint32_t)col);
}
__device__ __forceinline__ float2 bf2_to_f2(uint32_t u) {
    float2 r;
    r.x = __uint_as_float(u << 16);
    r.y = __uint_as_float(u & 0xFFFF0000u);
    return r;
}

#define TN 128
#define ROWB 144    // KC=32 bf16 hi|lo row
#define ROWB1 272   // KC=128 fp16 row

template<int MODE>
__device__ __forceinline__ size_t dst_of(int r, int c, int N) {
    if (MODE == 0 || MODE == 4) return (size_t)r * N + c;
    if (MODE == 1) {
        const int b_ = r >> 10, n_ = r & 1023, h_ = c >> 9, d_ = c & 511;
        return ((size_t)((b_ * 8 + h_) * 1024 + n_) << 9) + d_;
    }
    const int b_ = r >> 13, h_ = (r >> 10) & 7, n_ = r & 1023;
    return ((size_t)(b_ * 1024 + n_) << 12) + ((size_t)h_ << 9) + c;
}

// ================= 3-term split-bf16 GEMM, TM=256 (MODE 3: fused row-argmax) =================
#define TM3 256
#define KC3 32
#define STAGE3 ((TM3 + TN) * ROWB)
#define DYN3 (2 * STAGE3)

template<int MODE>
__global__ void __launch_bounds__(256, 1)
bgemm3(const bf16* __restrict__ Ah, const bf16* __restrict__ Al,
       const bf16* __restrict__ Bh, const bf16* __restrict__ Bl,
       const float* __restrict__ bias, float* __restrict__ C,
       unsigned long long* __restrict__ Packed,
       int M, int N, int K, float scale)
{
    extern __shared__ char sm[];
    const uint32_t smem_u = smem_to_u32(sm);
    const int tid = threadIdx.x;
    const int lane = tid & 31, wid = tid >> 5;
    const int bm = blockIdx.y * TM3, bn = blockIdx.x * TN;
    const int wm = (wid >> 1) * 64, wn = (wid & 1) * 64;

    float acc[4][8][4];
#pragma unroll
    for (int i = 0; i < 4; i++)
#pragma unroll
        for (int j = 0; j < 8; j++)
#pragma unroll
            for (int k = 0; k < 4; k++) acc[i][j][k] = 0.0f;

    const int NC = K / KC3;

    auto load_chunk = [&](int c, int st) {
        const int k0 = c * KC3;
        const uint32_t sb = smem_u + st * STAGE3;
#pragma unroll
        for (int u = 0; u < 3; u++) {
            const int unit = tid + u * 256;
            const int r = (unit & 511) >> 1, pl = unit & 1;
            const bf16* src;
            uint32_t dst;
            if (unit < 512) {
                src = (pl ? Al : Ah) + (size_t)(bm + r) * K + k0;
                dst = sb + r * ROWB + pl * 64;
            } else {
                src = (pl ? Bl : Bh) + (size_t)(bn + r) * K + k0;
                dst = sb + (TM3 + r) * ROWB + pl * 64;
            }
#pragma unroll
            for (int i = 0; i < 4; i++) cp16(dst + i * 16, src + i * 8);
        }
    };

    load_chunk(0, 0); CP_COMMIT();
    load_chunk(1, 1); CP_COMMIT();

    const int mr = lane & 7, msel = lane >> 3;
    const int aro = ((msel & 1) << 3) + mr;
    const int aco = (msel >> 1) << 3;
    const int bro = ((msel >> 1) << 3) + mr;
    const int bco = (msel & 1) << 3;

    for (int c = 0; c < NC; c++) {
        CP_WAIT1();
        __syncthreads();
        const uint32_t base = smem_u + (c & 1) * STAGE3;
#pragma unroll
        for (int ks = 0; ks < 2; ks++) {
            uint32_t ah[4][4], al[4][4], bh[8][2], bl[8][2];
            const int colA = (ks * 16 + aco) * 2;
            const int colB = (ks * 16 + bco) * 2;
#pragma unroll
            for (int mi = 0; mi < 4; mi++) {
                const uint32_t ad = base + (wm + mi * 16 + aro) * ROWB + colA;
                ldsm4(ah[mi], ad);
                ldsm4(al[mi], ad + 64);
            }
#pragma unroll
            for (int g = 0; g < 4; g++) {
                const uint32_t bd = base + (TM3 + wn + g * 16 + bro) * ROWB + colB;
                uint32_t t[4];
                ldsm4(t, bd);
                bh[2*g][0] = t[0]; bh[2*g][1] = t[1];
                bh[2*g+1][0] = t[2]; bh[2*g+1][1] = t[3];
                ldsm4(t, bd + 64);
                bl[2*g][0] = t[0]; bl[2*g][1] = t[1];
                bl[2*g+1][0] = t[2]; bl[2*g+1][1] = t[3];
            }
#pragma unroll
            for (int mi = 0; mi < 4; mi++)
#pragma unroll
                for (int nb = 0; nb < 8; nb++) {
                    mma_bf(acc[mi][nb], ah[mi], bh[nb]);
                    mma_bf(acc[mi][nb], ah[mi], bl[nb]);
                    mma_bf(acc[mi][nb], al[mi], bh[nb]);
                }
        }
        __syncthreads();
        if (c + 2 < NC) load_chunk(c + 2, c & 1);
        CP_COMMIT();
    }

    const int group = lane >> 2, tig = lane & 3;
    if (MODE == 3) {
#pragma unroll
        for (int mi = 0; mi < 4; mi++) {
#pragma unroll
            for (int half = 0; half < 2; half++) {
                const int row = bm + wm + mi * 16 + group + half * 8;
                float bv = -1e30f; int bc = 0;
#pragma unroll
                for (int nb = 0; nb < 8; nb++) {
                    const int col = bn + wn + nb * 8 + tig * 2;
                    const float v0 = acc[mi][nb][half * 2 + 0];
                    const float v1 = acc[mi][nb][half * 2 + 1];
                    if (v0 > bv) { bv = v0; bc = col; }
                    if (v1 > bv) { bv = v1; bc = col + 1; }
                }
#pragma unroll
                for (int m = 1; m <= 2; m <<= 1) {
                    float ov = __shfl_xor_sync(0xffffffffu, bv, m);
                    int   oc = __shfl_xor_sync(0xffffffffu, bc, m);
                    if (ov > bv || (ov == bv && oc < bc)) { bv = ov; bc = oc; }
                }
                if (tig == 0) atomicMax(Packed + row, packmax(bv, bc));
            }
        }
    } else {
#pragma unroll
        for (int mi = 0; mi < 4; mi++) {
            const int r_lo = bm + wm + mi * 16 + group;
#pragma unroll
            for (int nb = 0; nb < 8; nb++) {
                const int col = bn + wn + nb * 8 + tig * 2;
                float b0 = 0.0f, b1 = 0.0f;
                if (bias) { b0 = bias[col]; b1 = bias[col + 1]; }
                *reinterpret_cast<float2*>(&C[(size_t)r_lo * N + col]) =
                    make_float2((acc[mi][nb][0] + b0) * scale, (acc[mi][nb][1] + b1) * scale);
                *reinterpret_cast<float2*>(&C[(size_t)(r_lo + 8) * N + col]) =
                    make_float2((acc[mi][nb][2] + b0) * scale, (acc[mi][nb][3] + b1) * scale);
            }
        }
    }
}

// ====== small-tile 3-term gate GEMM: M=2048 (rows<1024: WgT+bias->outA; else WgB->outBV) ======
#define TMS 64
#define TNS 64
#define STAGES ((TMS + TNS) * ROWB)
#define DYNS (2 * STAGES)

__global__ void __launch_bounds__(128, 1)
bgemm3s(const bf16* __restrict__ Ah, const bf16* __restrict__ Al,
        const bf16* __restrict__ B1h, const bf16* __restrict__ B1l,
        const bf16* __restrict__ B2h, const bf16* __restrict__ B2l,
        const float* __restrict__ bias, float* __restrict__ outA, float* __restrict__ outBV)
{
    constexpr int K = KD_, N = KD_;
    extern __shared__ char sm[];
    const uint32_t smem_u = smem_to_u32(sm);
    const int tid = threadIdx.x;
    const int lane = tid & 31, wid = tid >> 5;
    const int bm = blockIdx.y * TMS, bn = blockIdx.x * TNS;
    const bool second = bm >= BWN;
    const bf16* Bh = second ? B2h : B1h;
    const bf16* Bl = second ? B2l : B1l;
    float* out = second ? outBV : outA;
    const int rowbase = second ? bm - BWN : bm;
    const int wm = (wid >> 1) * 32, wn = (wid & 1) * 32;

    float acc[2][4][4];
#pragma unroll
    for (int i = 0; i < 2; i++)
#pragma unroll
        for (int j = 0; j < 4; j++)
#pragma unroll
            for (int k = 0; k < 4; k++) acc[i][j][k] = 0.0f;

    const int NC = K / KC3;

    auto load_chunk = [&](int c, int st) {
        const int k0 = c * KC3;
        const uint32_t sb = smem_u + st * STAGES;
#pragma unroll
        for (int u = 0; u < 2; u++) {
            const int unit = tid + u * 128;
            const int r = (unit & 127) >> 1, pl = unit & 1;
            const bf16* src;
            uint32_t dst;
            if (unit < 128) {
                src = (pl ? Al : Ah) + (size_t)(bm + r) * K + k0;
                dst = sb + r * ROWB + pl * 64;
            } else {
                src = (pl ? Bl : Bh) + (size_t)(bn + r) * K + k0;
                dst = sb + (TMS + r) * ROWB + pl * 64;
            }
#pragma unroll
            for (int i = 0; i < 4; i++) cp16(dst + i * 16, src + i * 8);
        }
    };

    load_chunk(0, 0); CP_COMMIT();
    load_chunk(1, 1); CP_COMMIT();

    const int mr = lane & 7, msel = lane >> 3;
    const int aro = ((msel & 1) << 3) + mr;
    const int aco = (msel >> 1) << 3;
    const int bro = ((msel >> 1) << 3) + mr;
    const int bco = (msel & 1) << 3;

    for (int c = 0; c < NC; c++) {
        CP_WAIT1();
        __syncthreads();
        const uint32_t base = smem_u + (c & 1) * STAGES;
#pragma unroll
        for (int ks = 0; ks < 2; ks++) {
            uint32_t ah[2][4], al[2][4], bh[4][2], bl[4][2];
            const int colA = (ks * 16 + aco) * 2;
            const int colB = (ks * 16 + bco) * 2;
#pragma unroll
            for (int mi = 0; mi < 2; mi++) {
                const uint32_t ad = base + (wm + mi * 16 + aro) * ROWB + colA;
                ldsm4(ah[mi], ad);
                ldsm4(al[mi], ad + 64);
            }
#pragma unroll
            for (int g = 0; g < 2; g++) {
                const uint32_t bd = base + (TMS + wn + g * 16 + bro) * ROWB + colB;
                uint32_t t[4];
                ldsm4(t, bd);
                bh[2*g][0] = t[0]; bh[2*g][1] = t[1];
                bh[2*g+1][0] = t[2]; bh[2*g+1][1] = t[3];
                ldsm4(t, bd + 64);
                bl[2*g][0] = t[0]; bl[2*g][1] = t[1];
                bl[2*g+1][0] = t[2]; bl[2*g+1][1] = t[3];
            }
#pragma unroll
            for (int mi = 0; mi < 2; mi++)
#pragma unroll
                for (int nb = 0; nb < 4; nb++) {
                    mma_bf(acc[mi][nb], ah[mi], bh[nb]);
                    mma_bf(acc[mi][nb], ah[mi], bl[nb]);
                    mma_bf(acc[mi][nb], al[mi], bh[nb]);
                }
        }
        __syncthreads();
        if (c + 2 < NC) load_chunk(c + 2, c & 1);
        CP_COMMIT();
    }

    const int group = lane >> 2, tig = lane & 3;
#pragma unroll
    for (int mi = 0; mi < 2; mi++) {
        const int r_lo = rowbase + wm + mi * 16 + group;
#pragma unroll
        for (int nb = 0; nb < 4; nb++) {
            const int col = bn + wn + nb * 8 + tig * 2;
            float b0 = 0.0f, b1 = 0.0f;
            if (!second) { b0 = bias[col]; b1 = bias[col + 1]; }
            *reinterpret_cast<float2*>(&out[(size_t)r_lo * N + col]) =
                make_float2(acc[mi][nb][0] + b0, acc[mi][nb][1] + b1);
            *reinterpret_cast<float2*>(&out[(size_t)(r_lo + 8) * N + col]) =
                make_float2(acc[mi][nb][2] + b0, acc[mi][nb][3] + b1);
        }
    }
}

// ================= single-term fp16 GEMM (KC=128), TM = WM*64 =================
#define KC1 128

template<int MODE, int WM>
__global__ void __launch_bounds__(WM*64, 1)
hgemm1(const __half* __restrict__ A, const __half* __restrict__ B,
       const float* __restrict__ bias,
       float* __restrict__ C, __half* __restrict__ C16,
       int M, int N, int K, float scale)
{
    constexpr int TMv = WM * 64;
    constexpr int NT  = WM * 64;
    constexpr int STAGE = (TMv + TN) * ROWB1;
    extern __shared__ char sm[];
    const uint32_t smem_u = smem_to_u32(sm);
    const int tid = threadIdx.x;
    const int lane = tid & 31, wid = tid >> 5;
    const int bm = blockIdx.y * TMv, bn = blockIdx.x * TN;
    const int wm = (wid >> 1) * 64, wn = (wid & 1) * 64;

    float acc[4][8][4];
#pragma unroll
    for (int i = 0; i < 4; i++)
#pragma unroll
        for (int j = 0; j < 8; j++)
#pragma unroll
            for (int k = 0; k < 4; k++) acc[i][j][k] = 0.0f;

    const int NC = K / KC1;

    auto load_chunk = [&](int c, int st) {
        const int k0 = c * KC1;
        const uint32_t sb = smem_u + st * STAGE;
#pragma unroll
        for (int u = tid; u < (TMv + TN) * 16; u += NT) {
            const int r = u >> 4, seg = u & 15;
            const __half* src = (r < TMv)
                ? A + (size_t)(bm + r) * K + k0 + seg * 8
                : B + (size_t)(bn + (r - TMv)) * K + k0 + seg * 8;
            cp16(sb + r * ROWB1 + seg * 16, src);
        }
    };

    load_chunk(0, 0); CP_COMMIT();
    load_chunk(1, 1); CP_COMMIT();

    const int mr = lane & 7, msel = lane >> 3;
    const int aro = ((msel & 1) << 3) + mr;
    const int aco = (msel >> 1) << 3;
    const int bro = ((msel >> 1) << 3) + mr;
    const int bco = (msel & 1) << 3;

    for (int c = 0; c < NC; c++) {
        CP_WAIT1();
        __syncthreads();
        const uint32_t base = smem_u + (c & 1) * STAGE;
#pragma unroll
        for (int ks = 0; ks < 8; ks++) {
            uint32_t ah[4][4], bh[8][2];
            const int colA = (ks * 16 + aco) * 2;
            const int colB = (ks * 16 + bco) * 2;
#pragma unroll
            for (int mi = 0; mi < 4; mi++)
                ldsm4(ah[mi], base + (wm + mi * 16 + aro) * ROWB1 + colA);
#pragma unroll
            for (int g = 0; g < 4; g++) {
                uint32_t t[4];
                ldsm4(t, base + (TMv + wn + g * 16 + bro) * ROWB1 + colB);
                bh[2*g][0] = t[0]; bh[2*g][1] = t[1];
                bh[2*g+1][0] = t[2]; bh[2*g+1][1] = t[3];
            }
#pragma unroll
            for (int mi = 0; mi < 4; mi++)
#pragma unroll
                for (int nb = 0; nb < 8; nb++)
                    mma_fp(acc[mi][nb], ah[mi], bh[nb]);
        }
        __syncthreads();
        if (c + 2 < NC) load_chunk(c + 2, c & 1);
        CP_COMMIT();
    }

    const int group = lane >> 2, tig = lane & 3;
#pragma unroll
    for (int mi = 0; mi < 4; mi++) {
        const int r_lo = bm + wm + mi * 16 + group;
#pragma unroll
        for (int nb = 0; nb < 8; nb++) {
            const int col = bn + wn + nb * 8 + tig * 2;
            float b0 = 0.0f, b1 = 0.0f;
            if (bias) { b0 = bias[col]; b1 = bias[col + 1]; }
            float v00 = (acc[mi][nb][0] + b0) * scale;
            float v01 = (acc[mi][nb][1] + b1) * scale;
            float v10 = (acc[mi][nb][2] + b0) * scale;
            float v11 = (acc[mi][nb][3] + b1) * scale;
            if (MODE == 0) {
                *reinterpret_cast<float2*>(&C[dst_of<0>(r_lo,     col, N)]) = make_float2(v00, v01);
                *reinterpret_cast<float2*>(&C[dst_of<0>(r_lo + 8, col, N)]) = make_float2(v10, v11);
            } else {
                *reinterpret_cast<__half2*>(&C16[dst_of<MODE>(r_lo,     col, N)]) = __floats2half2_rn(v00, v01);
                *reinterpret_cast<__half2*>(&C16[dst_of<MODE>(r_lo + 8, col, N)]) = __floats2half2_rn(v10, v11);
            }
        }
    }
}

// ---------------- prep / small kernels ----------------
__global__ void __launch_bounds__(256) transpose_split(const float* __restrict__ in,
                                                       bf16* __restrict__ oh, bf16* __restrict__ ol,
                                                       int R, int C)
{
    __shared__ float t[32][33];
    const int c0 = blockIdx.x * 32, r0 = blockIdx.y * 32;
    const int x = threadIdx.x & 31, y = threadIdx.x >> 5;
#pragma unroll
    for (int i = 0; i < 32; i += 8) t[y + i][x] = in[(size_t)(r0 + y + i) * C + c0 + x];
    __syncthreads();
#pragma unroll
    for (int i = 0; i < 32; i += 8) {
        float v = t[x][y + i];
        bf16 h = __float2bfloat16(v);
        bf16 l = __float2bfloat16(v - __bfloat162float(h));
        const size_t d = (size_t)(c0 + y + i) * R + r0 + x;
        oh[d] = h; ol[d] = l;
    }
}

__global__ void __launch_bounds__(256) transpose_half(const float* __restrict__ in,
                                                      __half* __restrict__ out, int R, int C)
{
    __shared__ float t[32][33];
    const int c0 = blockIdx.x * 32, r0 = blockIdx.y * 32;
    const int x = threadIdx.x & 31, y = threadIdx.x >> 5;
#pragma unroll
    for (int i = 0; i < 32; i += 8) t[y + i][x] = in[(size_t)(r0 + y + i) * C + c0 + x];
    __syncthreads();
#pragma unroll
    for (int i = 0; i < 32; i += 8)
        out[(size_t)(c0 + y + i) * R + r0 + x] = __float2half(t[x][y + i]);
}

__global__ void __launch_bounds__(256) cvt_half(const float* __restrict__ in,
                                                __half* __restrict__ out, int n2)
{
    int i = (blockIdx.x * 256 + threadIdx.x) * 2;
    if (i < n2) {
        float2 v = *reinterpret_cast<const float2*>(&in[i]);
        *reinterpret_cast<__half2*>(&out[i]) = __floats2half2_rn(v.x, v.y);
    }
}

__global__ void __launch_bounds__(256) cvt_bf16(const float* __restrict__ in,
                                                bf16* __restrict__ out, int n2)
{
    int i = (blockIdx.x * 256 + threadIdx.x) * 2;
    if (i < n2) {
        float2 v = *reinterpret_cast<const float2*>(&in[i]);
        uint32_t h = (uint32_t)__bfloat16_as_ushort(__float2bfloat16(v.x)) |
                     ((uint32_t)__bfloat16_as_ushort(__float2bfloat16(v.y)) << 16);
        *reinterpret_cast<uint32_t*>(&out[i]) = h;
    }
}

// mem_keys: one read -> normalized bf16 planes + raw fp16
__global__ void __launch_bounds__(256) mem_prep(const float* __restrict__ X,
                                                bf16* __restrict__ oh, bf16* __restrict__ ol,
                                                __half* __restrict__ o16)
{
    __shared__ float red[256];
    const int r = blockIdx.x, tid = threadIdx.x;
    const float* p = X + (size_t)r * KD_;
    float ss = 0.0f;
    for (int i = tid; i < KD_; i += 256) { float v = p[i]; ss += v * v; }
    red[tid] = ss; __syncthreads();
    for (int s = 128; s > 0; s >>= 1) { if (tid < s) red[tid] += red[tid + s]; __syncthreads(); }
    const float inv = 1.0f / fmaxf(sqrtf(red[0]), 1e-8f);
    const int i = tid * 2;
    float2 v = *reinterpret_cast<const float2*>(&p[i]);
    uint32_t h, l;
    splitpack(v.x * inv, v.y * inv, h, l);
    *reinterpret_cast<uint32_t*>(&oh[(size_t)r * KD_ + i]) = h;
    *reinterpret_cast<uint32_t*>(&ol[(size_t)r * KD_ + i]) = l;
    *reinterpret_cast<__half2*>(&o16[(size_t)r * KD_ + i]) = __floats2half2_rn(v.x, v.y);
}

// write_keys: one read -> normalized planes (for sim) + raw planes (gate GEMM top half)
__global__ void __launch_bounds__(256) wk_prep(const float* __restrict__ X,
                                               bf16* __restrict__ nh, bf16* __restrict__ nl,
                                               bf16* __restrict__ gh, bf16* __restrict__ gl)
{
    __shared__ float red[256];
    const int r = blockIdx.x, tid = threadIdx.x;
    const float* p = X + (size_t)r * KD_;
    float ss = 0.0f;
    for (int i = tid; i < KD_; i += 256) { float v = p[i]; ss += v * v; }
    red[tid] = ss; __syncthreads();
    for (int s = 128; s > 0; s >>= 1) { if (tid < s) red[tid] += red[tid + s]; __syncthreads(); }
    const float inv = 1.0f / fmaxf(sqrtf(red[0]), 1e-8f);
    const int i = tid * 2;
    float2 v = *reinterpret_cast<const float2*>(&p[i]);
    uint32_t h, l;
    splitpack(v.x * inv, v.y * inv, h, l);
    *reinterpret_cast<uint32_t*>(&nh[(size_t)r * KD_ + i]) = h;
    *reinterpret_cast<uint32_t*>(&nl[(size_t)r * KD_ + i]) = l;
    splitpack(v.x, v.y, h, l);
    *reinterpret_cast<uint32_t*>(&gh[(size_t)r * KD_ + i]) = h;
    *reinterpret_cast<uint32_t*>(&gl[(size_t)r * KD_ + i]) = l;
}

// softmax: fp16 scores -> fp16 attn*512
__global__ void __launch_bounds__(256) softmax_h(const __half* __restrict__ S,
                                                 __half* __restrict__ P16)
{
    __shared__ float row[MEMN];
    __shared__ float red[256];
    const size_t r = blockIdx.x;
    const __half* p = S + r * MEMN;
    const int tid = threadIdx.x;
    float mx = -1e30f;
    for (int i = tid * 2; i < MEMN; i += 512) {
        float2 v = __half22float2(*reinterpret_cast<const __half2*>(&p[i]));
        row[i] = v.x; row[i+1] = v.y;
        mx = fmaxf(mx, fmaxf(v.x, v.y));
    }
    red[tid] = mx; __syncthreads();
    for (int s = 128; s > 0; s >>= 1) { if (tid < s) red[tid] = fmaxf(red[tid], red[tid + s]); __syncthreads(); }
    mx = red[0]; __syncthreads();
    float sum = 0.0f;
    for (int i = tid; i < MEMN; i += 256) { float e = expf(row[i] - mx); row[i] = e; sum += e; }
    red[tid] = sum; __syncthreads();
    for (int s = 128; s > 0; s >>= 1) { if (tid < s) red[tid] += red[tid + s]; __syncthreads(); }
    const float inv = 512.0f / red[0];
    __syncthreads();
    for (int i = tid * 2; i < MEMN; i += 512)
        *reinterpret_cast<__half2*>(&P16[r * MEMN + i]) =
            __floats2half2_rn(row[i] * inv, row[i+1] * inv);
}

// unpack argmax + gather V0[idx] into gate-GEMM bottom half
__global__ void __launch_bounds__(256) gather_unpack(const unsigned long long* __restrict__ pk,
                                                     const float* __restrict__ mv,
                                                     int* __restrict__ idx,
                                                     bf16* __restrict__ gh, bf16* __restrict__ gl)
{
    const int t = blockIdx.x, tid = threadIdx.x;
    const unsigned long long v = pk[t];
    const int col = (int)(0xFFFFFFFFu - (uint32_t)(v & 0xFFFFFFFFu));
    if (tid == 0) idx[t] = col;
    const float* src = mv + (size_t)col * KD_;
    const int i = tid * 2;
    uint32_t h, l;
    splitpack(src[i], src[i + 1], h, l);
    *reinterpret_cast<uint32_t*>(&gh[(size_t)(BWN + t) * KD_ + i]) = h;
    *reinterpret_cast<uint32_t*>(&gl[(size_t)(BWN + t) * KD_ + i]) = l;
}

// per-slot chains; first event uses precomputed gate; deeper events: bf16x2 matvec
__global__ void __launch_bounds__(256) chain_update(
    const float* __restrict__ wk, const float* __restrict__ wv,
    const uint32_t* __restrict__ WB,        // WgBot bf16x2 packed [r][256]
    const float* __restrict__ Aw,
    const float* __restrict__ BV,
    const int*   __restrict__ idx,
    const float* __restrict__ mk, const float* __restrict__ mv,
    float* __restrict__ outK, float* __restrict__ outV)
{
    __shared__ float sK[KD_], sV[KD_];
    __shared__ int   list[BWN];
    __shared__ int   cnt;
    const int s = blockIdx.x, tid = threadIdx.x;
    if (tid == 0) cnt = 0;
    __syncthreads();
    for (int t = tid; t < BWN; t += 256)
        if (idx[t] == s) { int p = atomicAdd(&cnt, 1); list[p] = t; }
    __syncthreads();
    const int n = cnt;
    if (n == 0) return;
    if (tid == 0) {
        for (int i = 1; i < n; i++) {
            int v = list[i], j = i - 1;
            while (j >= 0 && list[j] > v) { list[j + 1] = list[j]; j--; }
            list[j + 1] = v;
        }
    }
    for (int i = tid; i < KD_; i += 256) {
        sK[i] = mk[(size_t)s * KD_ + i];
        sV[i] = mv[(size_t)s * KD_ + i];
    }
    __syncthreads();
    const int j0 = tid * 2;
    for (int e = 0; e < n; e++) {
        const int t = list[e];
        float a0, a1;
        {
            float2 aw = *reinterpret_cast<const float2*>(&Aw[(size_t)t * KD_ + j0]);
            a0 = aw.x; a1 = aw.y;
        }
        if (e == 0) {
            float2 bv = *reinterpret_cast<const float2*>(&BV[(size_t)t * KD_ + j0]);
            a0 += bv.x; a1 += bv.y;
        } else {
#pragma unroll 8
            for (int r = 0; r < KD_; r++) {
                const float v = sV[r];
                float2 w = bf2_to_f2(WB[r * 256 + tid]);
                a0 += v * w.x;
                a1 += v * w.y;
            }
        }
        const float g0 = 1.0f / (1.0f + expf(-a0));
        const float g1 = 1.0f / (1.0f + expf(-a1));
        __syncthreads();
        float2 k2 = *reinterpret_cast<const float2*>(&wk[(size_t)t * KD_ + j0]);
        float2 v2 = *reinterpret_cast<const float2*>(&wv[(size_t)t * KD_ + j0]);
        sK[j0]     = g0 * k2.x + (1.0f - g0) * sK[j0];
        sK[j0 + 1] = g1 * k2.y + (1.0f - g1) * sK[j0 + 1];
        sV[j0]     = g0 * v2.x + (1.0f - g0) * sV[j0];
        sV[j0 + 1] = g1 * v2.y + (1.0f - g1) * sV[j0 + 1];
        __syncthreads();
    }
    for (int i = tid; i < KD_; i += 256) {
        outK[(size_t)s * KD_ + i] = sK[i];
        outV[(size_t)s * KD_ + i] = sV[i];
    }
}

// ---------------- launcher ----------------
extern "C" void kernel_launch(void* const* d_in, const int* in_sizes, int n_in,
                              void* d_out, int out_size)
{
    const float* queries    = (const float*)d_in[0];
    const float* write_keys = (const float*)d_in[1];
    const float* write_vals = (const float*)d_in[2];
    const float* mem_keys   = (const float*)d_in[3];
    const float* mem_values = (const float*)d_in[4];
    const float* Wq         = (const float*)d_in[5];
    const float* bq         = (const float*)d_in[6];
    const float* Wvp        = (const float*)d_in[7];
    const float* bvp        = (const float*)d_in[8];
    const float* Wg         = (const float*)d_in[9];
    const float* bg         = (const float*)d_in[10];

    float* out_read = (float*)d_out;
    float* out_k    = out_read + (size_t)RB * KD_;
    float* out_v    = out_k    + (size_t)MEMN * KD_;

    void *pS16, *pA, *pBV, *pIdx, *pPk, *pQI16, *pQ16, *pP16, *pRV16, *pMK16, *pMVT16;
    void *pWqT16, *pWvpT16, *pKNh, *pKNl, *pMNh, *pMNl;
    void *pWgTh, *pWgTl, *pWgBh, *pWgBl, *pWB16, *pGAh, *pGAl;
    cudaGetSymbolAddress(&pS16, g_S16);
    cudaGetSymbolAddress(&pA, g_A);         cudaGetSymbolAddress(&pBV, g_BV);
    cudaGetSymbolAddress(&pIdx, g_idx);     cudaGetSymbolAddress(&pPk, g_pk);
    cudaGetSymbolAddress(&pQI16, g_QI16);   cudaGetSymbolAddress(&pQ16, g_Q16);
    cudaGetSymbolAddress(&pP16, g_P16);     cudaGetSymbolAddress(&pRV16, g_RV16);
    cudaGetSymbolAddress(&pMK16, g_MK16);   cudaGetSymbolAddress(&pMVT16, g_MVT16);
    cudaGetSymbolAddress(&pWqT16, g_WqT16); cudaGetSymbolAddress(&pWvpT16, g_WvpT16);
    cudaGetSymbolAddress(&pKNh, g_KNh);     cudaGetSymbolAddress(&pKNl, g_KNl);
    cudaGetSymbolAddress(&pMNh, g_MNh);     cudaGetSymbolAddress(&pMNl, g_MNl);
    cudaGetSymbolAddress(&pWgTh, g_WgTh);   cudaGetSymbolAddress(&pWgTl, g_WgTl);
    cudaGetSymbolAddress(&pWgBh, g_WgBh);   cudaGetSymbolAddress(&pWgBl, g_WgBl);
    cudaGetSymbolAddress(&pWB16, g_WB16);
    cudaGetSymbolAddress(&pGAh, g_GAh);     cudaGetSymbolAddress(&pGAl, g_GAl);

    constexpr int DYN1_256 = 2 * (256 + TN) * ROWB1;
    constexpr int DYN1_128 = 2 * (128 + TN) * ROWB1;
    cudaFuncSetAttribute(bgemm3<3>,   cudaFuncAttributeMaxDynamicSharedMemorySize, DYN3);
    cudaFuncSetAttribute(bgemm3s,     cudaFuncAttributeMaxDynamicSharedMemorySize, DYNS);
    cudaFuncSetAttribute(hgemm1<4,4>, cudaFuncAttributeMaxDynamicSharedMemorySize, DYN1_256);
    cudaFuncSetAttribute(hgemm1<1,4>, cudaFuncAttributeMaxDynamicSharedMemorySize, DYN1_256);
    cudaFuncSetAttribute(hgemm1<2,4>, cudaFuncAttributeMaxDynamicSharedMemorySize, DYN1_256);
    cudaFuncSetAttribute(hgemm1<0,2>, cudaFuncAttributeMaxDynamicSharedMemorySize, DYN1_128);

    const float qscale = 0.044194173824159216f;  // 1/sqrt(512)/TEMP

    // ---- prep ----
    cudaMemsetAsync(pPk, 0, BWN * sizeof(unsigned long long));
    transpose_half<<<dim3((HH*KD_)/32, KD_/32), 256>>>(Wq, (__half*)pWqT16, KD_, HH*KD_);
    transpose_half<<<dim3(KD_/32, (HH*KD_)/32), 256>>>(Wvp, (__half*)pWvpT16, HH*KD_, KD_);
    transpose_half<<<dim3(KD_/32, MEMN/32),     256>>>(mem_values, (__half*)pMVT16, MEMN, KD_);
    transpose_split<<<dim3(KD_/32, KD_/32),     256>>>(Wg, (bf16*)pWgTh, (bf16*)pWgTl, KD_, KD_);
    transpose_split<<<dim3(KD_/32, KD_/32),     256>>>(Wg + (size_t)KD_ * KD_,
                                                       (bf16*)pWgBh, (bf16*)pWgBl, KD_, KD_);
    cvt_bf16<<<(KD_*KD_/2 + 255)/256, 256>>>(Wg + (size_t)KD_ * KD_, (bf16*)pWB16, KD_*KD_);
    mem_prep<<<MEMN, 256>>>(mem_keys, (bf16*)pMNh, (bf16*)pMNl, (__half*)pMK16);
    wk_prep<<<BWN, 256>>>(write_keys, (bf16*)pKNh, (bf16*)pKNl, (bf16*)pGAh, (bf16*)pGAl);
    cvt_half<<<(RB*KD_/2 + 255)/256, 256>>>(queries, (__half*)pQI16, RB*KD_);

    // ---- write path ----
    bgemm3<3><<<dim3(MEMN/TN, BWN/TM3), 256, DYN3>>>(
        (bf16*)pKNh, (bf16*)pKNl, (bf16*)pMNh, (bf16*)pMNl,
        nullptr, nullptr, (unsigned long long*)pPk, BWN, MEMN, KD_, 1.0f);
    gather_unpack<<<BWN, 256>>>((unsigned long long*)pPk, mem_values, (int*)pIdx,
                                (bf16*)pGAh, (bf16*)pGAl);
    bgemm3s<<<dim3(KD_/TNS, (2*BWN)/TMS), 128, DYNS>>>(
        (bf16*)pGAh, (bf16*)pGAl,
        (bf16*)pWgTh, (bf16*)pWgTl, (bf16*)pWgBh, (bf16*)pWgBl,
        bg, (float*)pA, (float*)pBV);
    cudaMemcpyAsync(out_k, mem_keys,   (size_t)MEMN * KD_ * sizeof(float), cudaMemcpyDeviceToDevice);
    cudaMemcpyAsync(out_v, mem_values, (size_t)MEMN * KD_ * sizeof(float), cudaMemcpyDeviceToDevice);
    chain_update<<<MEMN, 256>>>(write_keys, write_vals, (const uint32_t*)pWB16,
                                (float*)pA, (float*)pBV,
                                (int*)pIdx, mem_keys, mem_values, out_k, out_v);

    // ---- read path ----
    hgemm1<1,4><<<dim3((HH*KD_)/TN, RB/256), 256, DYN1_256>>>(
        (__half*)pQI16, (__half*)pWqT16, bq, nullptr, (__half*)pQ16,
        RB, HH*KD_, KD_, qscale);
    hgemm1<4,4><<<dim3(MEMN/TN, RQ/256), 256, DYN1_256>>>(
        (__half*)pQ16, (__half*)pMK16, nullptr, nullptr, (__half*)pS16,
        RQ, MEMN, KD_, 1.0f);
    softmax_h<<<RQ, 256>>>((__half*)pS16, (__half*)pP16);
    hgemm1<2,4><<<dim3(KD_/TN, RQ/256), 256, DYN1_256>>>(
        (__half*)pP16, (__half*)pMVT16, nullptr, nullptr, (__half*)pRV16,
        RQ, KD_, MEMN, 1.0f / 512.0f);
    hgemm1<0,2><<<dim3(KD_/TN, RB/128), 128, DYN1_128>>>(
        (__half*)pRV16, (__half*)pWvpT16, bvp, out_read, nullptr,
        RB, KD_, HH*KD_, 1.0f);
}

// round 9
// speedup vs baseline: 6.9401x; 1.1628x over previous
#include <cuda_runtime.h>
#include <cuda_bf16.h>
#include <cuda_fp16.h>
#include <math.h>
#include <stdint.h>

#define BB   4
#define NN_  1024
#define KD_  512
#define HH   8
#define MEMN 4096
#define BWN  1024
#define RQ   (BB*HH*NN_)
#define RB   (BB*NN_)

typedef __nv_bfloat16 bf16;

// ---------------- scratch ----------------
__device__ float  g_A  [(size_t)BWN * KD_];          // wk@WgTop + bg
__device__ float  g_BV [(size_t)BWN * KD_];          // V0[idx]@WgBot
__device__ float  g_rsum[RQ];                        // softmax row sums
__device__ int    g_idx[BWN];
__device__ unsigned long long g_pk[BWN];             // packed (val,idx) argmax
__device__ __half g_QI16[(size_t)RB * KD_];
__device__ __half g_Q16[(size_t)RQ * KD_];
__device__ __half g_P16[(size_t)RQ * MEMN];          // exp(scores) fp16
__device__ __half g_RV16[(size_t)RB * (HH*KD_)];
__device__ __half g_MK16[(size_t)MEMN * KD_];
__device__ __half g_MVT16[(size_t)KD_ * MEMN];
__device__ __half g_WqT16[(size_t)(HH*KD_) * KD_];
__device__ __half g_WvpT16[(size_t)KD_ * (HH*KD_)];
__device__ bf16 g_KNh[(size_t)BWN * KD_],  g_KNl[(size_t)BWN * KD_];
__device__ bf16 g_MNh[(size_t)MEMN * KD_], g_MNl[(size_t)MEMN * KD_];
__device__ bf16 g_WgTh[(size_t)KD_ * KD_], g_WgTl[(size_t)KD_ * KD_];
__device__ bf16 g_WgBh[(size_t)KD_ * KD_], g_WgBl[(size_t)KD_ * KD_];
__device__ bf16 g_WB16[(size_t)KD_ * KD_];            // WgBot row-major bf16 (chain matvec)
__device__ bf16 g_GAh[(size_t)2*BWN * KD_], g_GAl[(size_t)2*BWN * KD_];  // [wk rows | V0[idx] rows]

// ---------------- helpers ----------------
__device__ __forceinline__ uint32_t smem_to_u32(const void* p) {
    uint32_t a;
    asm("{ .reg .u64 t; cvta.to.shared.u64 t, %1; cvt.u32.u64 %0, t; }" : "=r"(a) : "l"(p));
    return a;
}
__device__ __forceinline__ void ldsm4(uint32_t* r, uint32_t addr) {
    asm volatile("ldmatrix.sync.aligned.m8n8.x4.shared.b16 {%0,%1,%2,%3}, [%4];"
                 : "=r"(r[0]), "=r"(r[1]), "=r"(r[2]), "=r"(r[3]) : "r"(addr));
}
__device__ __forceinline__ void mma_bf(float* c, const uint32_t* a, const uint32_t* b) {
    asm volatile(
        "mma.sync.aligned.m16n8k16.row.col.f32.bf16.bf16.f32 "
        "{%0,%1,%2,%3}, {%4,%5,%6,%7}, {%8,%9}, {%0,%1,%2,%3};"
        : "+f"(c[0]), "+f"(c[1]), "+f"(c[2]), "+f"(c[3])
        : "r"(a[0]), "r"(a[1]), "r"(a[2]), "r"(a[3]), "r"(b[0]), "r"(b[1]));
}
__device__ __forceinline__ void mma_fp(float* c, const uint32_t* a, const uint32_t* b) {
    asm volatile(
        "mma.sync.aligned.m16n8k16.row.col.f32.f16.f16.f32 "
        "{%0,%1,%2,%3}, {%4,%5,%6,%7}, {%8,%9}, {%0,%1,%2,%3};"
        : "+f"(c[0]), "+f"(c[1]), "+f"(c[2]), "+f"(c[3])
        : "r"(a[0]), "r"(a[1]), "r"(a[2]), "r"(a[3]), "r"(b[0]), "r"(b[1]));
}
__device__ __forceinline__ void cp16(uint32_t dst, const void* src) {
    asm volatile("cp.async.cg.shared.global [%0], [%1], 16;" :: "r"(dst), "l"(src));
}
#define CP_COMMIT() asm volatile("cp.async.commit_group;" ::: "memory")
#define CP_WAIT1()  asm volatile("cp.async.wait_group 1;" ::: "memory")

__device__ __forceinline__ void splitpack(float x, float y, uint32_t& h, uint32_t& l) {
    bf16 hx = __float2bfloat16(x), hy = __float2bfloat16(y);
    float rx = x - __bfloat162float(hx), ry = y - __bfloat162float(hy);
    bf16 lx = __float2bfloat16(rx), ly = __float2bfloat16(ry);
    h = (uint32_t)__bfloat16_as_ushort(hx) | ((uint32_t)__bfloat16_as_ushort(hy) << 16);
    l = (uint32_t)__bfloat16_as_ushort(lx) | ((uint32_t)__bfloat16_as_ushort(ly) << 16);
}
__device__ __forceinline__ unsigned long long packmax(float v, int col) {
    uint32_t b = __float_as_uint(v);
    b = (b & 0x80000000u) ? ~b : (b | 0x80000000u);
    return ((unsigned long long)b << 32) | (unsigned long long)(0xFFFFFFFFu - (uint32_t)col);
}
__device__ __forceinline__ float2 bf2_to_f2(uint32_t u) {
    float2 r;
    r.x = __uint_as_float(u << 16);
    r.y = __uint_as_float(u & 0xFFFF0000u);
    return r;
}

#define TN 128
#define ROWB 144    // KC=32 bf16 hi|lo row
#define ROWB1 272   // KC=128 fp16 row

template<int MODE>
__device__ __forceinline__ size_t dst_of(int r, int c, int N) {
    if (MODE == 0 || MODE == 5) return (size_t)r * N + c;
    if (MODE == 1) {
        const int b_ = r >> 10, n_ = r & 1023, h_ = c >> 9, d_ = c & 511;
        return ((size_t)((b_ * 8 + h_) * 1024 + n_) << 9) + d_;
    }
    const int b_ = r >> 13, h_ = (r >> 10) & 7, n_ = r & 1023;
    return ((size_t)(b_ * 1024 + n_) << 12) + ((size_t)h_ << 9) + c;
}

// ================= 3-term split-bf16 GEMM, TM=256 (MODE 3: fused row-argmax) =================
#define TM3 256
#define KC3 32
#define STAGE3 ((TM3 + TN) * ROWB)
#define DYN3 (2 * STAGE3)

template<int MODE>
__global__ void __launch_bounds__(256, 1)
bgemm3(const bf16* __restrict__ Ah, const bf16* __restrict__ Al,
       const bf16* __restrict__ Bh, const bf16* __restrict__ Bl,
       const float* __restrict__ bias, float* __restrict__ C,
       unsigned long long* __restrict__ Packed,
       int M, int N, int K, float scale)
{
    extern __shared__ char sm[];
    const uint32_t smem_u = smem_to_u32(sm);
    const int tid = threadIdx.x;
    const int lane = tid & 31, wid = tid >> 5;
    const int bm = blockIdx.y * TM3, bn = blockIdx.x * TN;
    const int wm = (wid >> 1) * 64, wn = (wid & 1) * 64;

    float acc[4][8][4];
#pragma unroll
    for (int i = 0; i < 4; i++)
#pragma unroll
        for (int j = 0; j < 8; j++)
#pragma unroll
            for (int k = 0; k < 4; k++) acc[i][j][k] = 0.0f;

    const int NC = K / KC3;

    auto load_chunk = [&](int c, int st) {
        const int k0 = c * KC3;
        const uint32_t sb = smem_u + st * STAGE3;
#pragma unroll
        for (int u = 0; u < 3; u++) {
            const int unit = tid + u * 256;
            const int r = (unit & 511) >> 1, pl = unit & 1;
            const bf16* src;
            uint32_t dst;
            if (unit < 512) {
                src = (pl ? Al : Ah) + (size_t)(bm + r) * K + k0;
                dst = sb + r * ROWB + pl * 64;
            } else {
                src = (pl ? Bl : Bh) + (size_t)(bn + r) * K + k0;
                dst = sb + (TM3 + r) * ROWB + pl * 64;
            }
#pragma unroll
            for (int i = 0; i < 4; i++) cp16(dst + i * 16, src + i * 8);
        }
    };

    load_chunk(0, 0); CP_COMMIT();
    load_chunk(1, 1); CP_COMMIT();

    const int mr = lane & 7, msel = lane >> 3;
    const int aro = ((msel & 1) << 3) + mr;
    const int aco = (msel >> 1) << 3;
    const int bro = ((msel >> 1) << 3) + mr;
    const int bco = (msel & 1) << 3;

    for (int c = 0; c < NC; c++) {
        CP_WAIT1();
        __syncthreads();
        const uint32_t base = smem_u + (c & 1) * STAGE3;
#pragma unroll
        for (int ks = 0; ks < 2; ks++) {
            uint32_t ah[4][4], al[4][4], bh[8][2], bl[8][2];
            const int colA = (ks * 16 + aco) * 2;
            const int colB = (ks * 16 + bco) * 2;
#pragma unroll
            for (int mi = 0; mi < 4; mi++) {
                const uint32_t ad = base + (wm + mi * 16 + aro) * ROWB + colA;
                ldsm4(ah[mi], ad);
                ldsm4(al[mi], ad + 64);
            }
#pragma unroll
            for (int g = 0; g < 4; g++) {
                const uint32_t bd = base + (TM3 + wn + g * 16 + bro) * ROWB + colB;
                uint32_t t[4];
                ldsm4(t, bd);
                bh[2*g][0] = t[0]; bh[2*g][1] = t[1];
                bh[2*g+1][0] = t[2]; bh[2*g+1][1] = t[3];
                ldsm4(t, bd + 64);
                bl[2*g][0] = t[0]; bl[2*g][1] = t[1];
                bl[2*g+1][0] = t[2]; bl[2*g+1][1] = t[3];
            }
#pragma unroll
            for (int mi = 0; mi < 4; mi++)
#pragma unroll
                for (int nb = 0; nb < 8; nb++) {
                    mma_bf(acc[mi][nb], ah[mi], bh[nb]);
                    mma_bf(acc[mi][nb], ah[mi], bl[nb]);
                    mma_bf(acc[mi][nb], al[mi], bh[nb]);
                }
        }
        __syncthreads();
        if (c + 2 < NC) load_chunk(c + 2, c & 1);
        CP_COMMIT();
    }

    const int group = lane >> 2, tig = lane & 3;
    if (MODE == 3) {
#pragma unroll
        for (int mi = 0; mi < 4; mi++) {
#pragma unroll
            for (int half = 0; half < 2; half++) {
                const int row = bm + wm + mi * 16 + group + half * 8;
                float bv = -1e30f; int bc = 0;
#pragma unroll
                for (int nb = 0; nb < 8; nb++) {
                    const int col = bn + wn + nb * 8 + tig * 2;
                    const float v0 = acc[mi][nb][half * 2 + 0];
                    const float v1 = acc[mi][nb][half * 2 + 1];
                    if (v0 > bv) { bv = v0; bc = col; }
                    if (v1 > bv) { bv = v1; bc = col + 1; }
                }
#pragma unroll
                for (int m = 1; m <= 2; m <<= 1) {
                    float ov = __shfl_xor_sync(0xffffffffu, bv, m);
                    int   oc = __shfl_xor_sync(0xffffffffu, bc, m);
                    if (ov > bv || (ov == bv && oc < bc)) { bv = ov; bc = oc; }
                }
                if (tig == 0) atomicMax(Packed + row, packmax(bv, bc));
            }
        }
    } else {
#pragma unroll
        for (int mi = 0; mi < 4; mi++) {
            const int r_lo = bm + wm + mi * 16 + group;
#pragma unroll
            for (int nb = 0; nb < 8; nb++) {
                const int col = bn + wn + nb * 8 + tig * 2;
                float b0 = 0.0f, b1 = 0.0f;
                if (bias) { b0 = bias[col]; b1 = bias[col + 1]; }
                *reinterpret_cast<float2*>(&C[(size_t)r_lo * N + col]) =
                    make_float2((acc[mi][nb][0] + b0) * scale, (acc[mi][nb][1] + b1) * scale);
                *reinterpret_cast<float2*>(&C[(size_t)(r_lo + 8) * N + col]) =
                    make_float2((acc[mi][nb][2] + b0) * scale, (acc[mi][nb][3] + b1) * scale);
            }
        }
    }
}

// ====== small-tile 3-term gate GEMM: M=2048 (rows<1024: WgT+bias->outA; else WgB->outBV) ======
#define TMS 64
#define TNS 64
#define STAGES ((TMS + TNS) * ROWB)
#define DYNS (2 * STAGES)

__global__ void __launch_bounds__(128, 1)
bgemm3s(const bf16* __restrict__ Ah, const bf16* __restrict__ Al,
        const bf16* __restrict__ B1h, const bf16* __restrict__ B1l,
        const bf16* __restrict__ B2h, const bf16* __restrict__ B2l,
        const float* __restrict__ bias, float* __restrict__ outA, float* __restrict__ outBV)
{
    constexpr int K = KD_, N = KD_;
    extern __shared__ char sm[];
    const uint32_t smem_u = smem_to_u32(sm);
    const int tid = threadIdx.x;
    const int lane = tid & 31, wid = tid >> 5;
    const int bm = blockIdx.y * TMS, bn = blockIdx.x * TNS;
    const bool second = bm >= BWN;
    const bf16* Bh = second ? B2h : B1h;
    const bf16* Bl = second ? B2l : B1l;
    float* out = second ? outBV : outA;
    const int rowbase = second ? bm - BWN : bm;
    const int wm = (wid >> 1) * 32, wn = (wid & 1) * 32;

    float acc[2][4][4];
#pragma unroll
    for (int i = 0; i < 2; i++)
#pragma unroll
        for (int j = 0; j < 4; j++)
#pragma unroll
            for (int k = 0; k < 4; k++) acc[i][j][k] = 0.0f;

    const int NC = K / KC3;

    auto load_chunk = [&](int c, int st) {
        const int k0 = c * KC3;
        const uint32_t sb = smem_u + st * STAGES;
#pragma unroll
        for (int u = 0; u < 2; u++) {
            const int unit = tid + u * 128;
            const int r = (unit & 127) >> 1, pl = unit & 1;
            const bf16* src;
            uint32_t dst;
            if (unit < 128) {
                src = (pl ? Al : Ah) + (size_t)(bm + r) * K + k0;
                dst = sb + r * ROWB + pl * 64;
            } else {
                src = (pl ? Bl : Bh) + (size_t)(bn + r) * K + k0;
                dst = sb + (TMS + r) * ROWB + pl * 64;
            }
#pragma unroll
            for (int i = 0; i < 4; i++) cp16(dst + i * 16, src + i * 8);
        }
    };

    load_chunk(0, 0); CP_COMMIT();
    load_chunk(1, 1); CP_COMMIT();

    const int mr = lane & 7, msel = lane >> 3;
    const int aro = ((msel & 1) << 3) + mr;
    const int aco = (msel >> 1) << 3;
    const int bro = ((msel >> 1) << 3) + mr;
    const int bco = (msel & 1) << 3;

    for (int c = 0; c < NC; c++) {
        CP_WAIT1();
        __syncthreads();
        const uint32_t base = smem_u + (c & 1) * STAGES;
#pragma unroll
        for (int ks = 0; ks < 2; ks++) {
            uint32_t ah[2][4], al[2][4], bh[4][2], bl[4][2];
            const int colA = (ks * 16 + aco) * 2;
            const int colB = (ks * 16 + bco) * 2;
#pragma unroll
            for (int mi = 0; mi < 2; mi++) {
                const uint32_t ad = base + (wm + mi * 16 + aro) * ROWB + colA;
                ldsm4(ah[mi], ad);
                ldsm4(al[mi], ad + 64);
            }
#pragma unroll
            for (int g = 0; g < 2; g++) {
                const uint32_t bd = base + (TMS + wn + g * 16 + bro) * ROWB + colB;
                uint32_t t[4];
                ldsm4(t, bd);
                bh[2*g][0] = t[0]; bh[2*g][1] = t[1];
                bh[2*g+1][0] = t[2]; bh[2*g+1][1] = t[3];
                ldsm4(t, bd + 64);
                bl[2*g][0] = t[0]; bl[2*g][1] = t[1];
                bl[2*g+1][0] = t[2]; bl[2*g+1][1] = t[3];
            }
#pragma unroll
            for (int mi = 0; mi < 2; mi++)
#pragma unroll
                for (int nb = 0; nb < 4; nb++) {
                    mma_bf(acc[mi][nb], ah[mi], bh[nb]);
                    mma_bf(acc[mi][nb], ah[mi], bl[nb]);
                    mma_bf(acc[mi][nb], al[mi], bh[nb]);
                }
        }
        __syncthreads();
        if (c + 2 < NC) load_chunk(c + 2, c & 1);
        CP_COMMIT();
    }

    const int group = lane >> 2, tig = lane & 3;
#pragma unroll
    for (int mi = 0; mi < 2; mi++) {
        const int r_lo = rowbase + wm + mi * 16 + group;
#pragma unroll
        for (int nb = 0; nb < 4; nb++) {
            const int col = bn + wn + nb * 8 + tig * 2;
            float b0 = 0.0f, b1 = 0.0f;
            if (!second) { b0 = bias[col]; b1 = bias[col + 1]; }
            *reinterpret_cast<float2*>(&out[(size_t)r_lo * N + col]) =
                make_float2(acc[mi][nb][0] + b0, acc[mi][nb][1] + b1);
            *reinterpret_cast<float2*>(&out[(size_t)(r_lo + 8) * N + col]) =
                make_float2(acc[mi][nb][2] + b0, acc[mi][nb][3] + b1);
        }
    }
}

// ================= single-term fp16 GEMM (KC=128), TM = WM*64 =================
// MODE 0: fp32 out; MODE 1: qproj remap fp16; MODE 2: AV remap fp16 scaled by 1/rsum[row];
// MODE 5: scores -> exp() fp16 + per-row sum atomics
#define KC1 128

template<int MODE, int WM>
__global__ void __launch_bounds__(WM*64, 1)
hgemm1(const __half* __restrict__ A, const __half* __restrict__ B,
       const float* __restrict__ bias,
       float* __restrict__ C, __half* __restrict__ C16,
       const float* __restrict__ rsum, float* __restrict__ rsumo,
       int M, int N, int K, float scale)
{
    constexpr int TMv = WM * 64;
    constexpr int NT  = WM * 64;
    constexpr int STAGE = (TMv + TN) * ROWB1;
    extern __shared__ char sm[];
    const uint32_t smem_u = smem_to_u32(sm);
    const int tid = threadIdx.x;
    const int lane = tid & 31, wid = tid >> 5;
    const int bm = blockIdx.y * TMv, bn = blockIdx.x * TN;
    const int wm = (wid >> 1) * 64, wn = (wid & 1) * 64;

    float acc[4][8][4];
#pragma unroll
    for (int i = 0; i < 4; i++)
#pragma unroll
        for (int j = 0; j < 8; j++)
#pragma unroll
            for (int k = 0; k < 4; k++) acc[i][j][k] = 0.0f;

    const int NC = K / KC1;

    auto load_chunk = [&](int c, int st) {
        const int k0 = c * KC1;
        const uint32_t sb = smem_u + st * STAGE;
#pragma unroll
        for (int u = tid; u < (TMv + TN) * 16; u += NT) {
            const int r = u >> 4, seg = u & 15;
            const __half* src = (r < TMv)
                ? A + (size_t)(bm + r) * K + k0 + seg * 8
                : B + (size_t)(bn + (r - TMv)) * K + k0 + seg * 8;
            cp16(sb + r * ROWB1 + seg * 16, src);
        }
    };

    load_chunk(0, 0); CP_COMMIT();
    load_chunk(1, 1); CP_COMMIT();

    const int mr = lane & 7, msel = lane >> 3;
    const int aro = ((msel & 1) << 3) + mr;
    const int aco = (msel >> 1) << 3;
    const int bro = ((msel >> 1) << 3) + mr;
    const int bco = (msel & 1) << 3;

    for (int c = 0; c < NC; c++) {
        CP_WAIT1();
        __syncthreads();
        const uint32_t base = smem_u + (c & 1) * STAGE;
#pragma unroll
        for (int ks = 0; ks < 8; ks++) {
            uint32_t ah[4][4], bh[8][2];
            const int colA = (ks * 16 + aco) * 2;
            const int colB = (ks * 16 + bco) * 2;
#pragma unroll
            for (int mi = 0; mi < 4; mi++)
                ldsm4(ah[mi], base + (wm + mi * 16 + aro) * ROWB1 + colA);
#pragma unroll
            for (int g = 0; g < 4; g++) {
                uint32_t t[4];
                ldsm4(t, base + (TMv + wn + g * 16 + bro) * ROWB1 + colB);
                bh[2*g][0] = t[0]; bh[2*g][1] = t[1];
                bh[2*g+1][0] = t[2]; bh[2*g+1][1] = t[3];
            }
#pragma unroll
            for (int mi = 0; mi < 4; mi++)
#pragma unroll
                for (int nb = 0; nb < 8; nb++)
                    mma_fp(acc[mi][nb], ah[mi], bh[nb]);
        }
        __syncthreads();
        if (c + 2 < NC) load_chunk(c + 2, c & 1);
        CP_COMMIT();
    }

    const int group = lane >> 2, tig = lane & 3;
    if (MODE == 5) {
        // exp + fp16 store + per-row sum atomics
#pragma unroll
        for (int mi = 0; mi < 4; mi++) {
            const int r_lo = bm + wm + mi * 16 + group;
            float rs0 = 0.0f, rs1 = 0.0f;
#pragma unroll
            for (int nb = 0; nb < 8; nb++) {
                const int col = bn + wn + nb * 8 + tig * 2;
                float e00 = __expf(acc[mi][nb][0]);
                float e01 = __expf(acc[mi][nb][1]);
                float e10 = __expf(acc[mi][nb][2]);
                float e11 = __expf(acc[mi][nb][3]);
                rs0 += e00 + e01;
                rs1 += e10 + e11;
                *reinterpret_cast<__half2*>(&C16[(size_t)r_lo * N + col]) = __floats2half2_rn(e00, e01);
                *reinterpret_cast<__half2*>(&C16[(size_t)(r_lo + 8) * N + col]) = __floats2half2_rn(e10, e11);
            }
            rs0 += __shfl_xor_sync(0xffffffffu, rs0, 1);
            rs0 += __shfl_xor_sync(0xffffffffu, rs0, 2);
            rs1 += __shfl_xor_sync(0xffffffffu, rs1, 1);
            rs1 += __shfl_xor_sync(0xffffffffu, rs1, 2);
            if (tig == 0) {
                atomicAdd(rsumo + r_lo, rs0);
                atomicAdd(rsumo + r_lo + 8, rs1);
            }
        }
    } else {
#pragma unroll
        for (int mi = 0; mi < 4; mi++) {
            const int r_lo = bm + wm + mi * 16 + group;
            float s0 = scale, s1 = scale;
            if (MODE == 2) {
                s0 = scale / rsum[r_lo];
                s1 = scale / rsum[r_lo + 8];
            }
#pragma unroll
            for (int nb = 0; nb < 8; nb++) {
                const int col = bn + wn + nb * 8 + tig * 2;
                float b0 = 0.0f, b1 = 0.0f;
                if (bias) { b0 = bias[col]; b1 = bias[col + 1]; }
                float v00 = (acc[mi][nb][0] + b0) * s0;
                float v01 = (acc[mi][nb][1] + b1) * s0;
                float v10 = (acc[mi][nb][2] + b0) * s1;
                float v11 = (acc[mi][nb][3] + b1) * s1;
                if (MODE == 0) {
                    *reinterpret_cast<float2*>(&C[dst_of<0>(r_lo,     col, N)]) = make_float2(v00, v01);
                    *reinterpret_cast<float2*>(&C[dst_of<0>(r_lo + 8, col, N)]) = make_float2(v10, v11);
                } else {
                    *reinterpret_cast<__half2*>(&C16[dst_of<MODE>(r_lo,     col, N)]) = __floats2half2_rn(v00, v01);
                    *reinterpret_cast<__half2*>(&C16[dst_of<MODE>(r_lo + 8, col, N)]) = __floats2half2_rn(v10, v11);
                }
            }
        }
    }
}

// ---------------- prep / small kernels ----------------
// transpose + split; optional extra raw (non-transposed) bf16 output
__global__ void __launch_bounds__(256) transpose_split(const float* __restrict__ in,
                                                       bf16* __restrict__ oh, bf16* __restrict__ ol,
                                                       bf16* __restrict__ raw16,
                                                       int R, int C)
{
    __shared__ float t[32][33];
    const int c0 = blockIdx.x * 32, r0 = blockIdx.y * 32;
    const int x = threadIdx.x & 31, y = threadIdx.x >> 5;
#pragma unroll
    for (int i = 0; i < 32; i += 8) {
        float v = in[(size_t)(r0 + y + i) * C + c0 + x];
        t[y + i][x] = v;
        if (raw16) raw16[(size_t)(r0 + y + i) * C + c0 + x] = __float2bfloat16(v);
    }
    __syncthreads();
#pragma unroll
    for (int i = 0; i < 32; i += 8) {
        float v = t[x][y + i];
        bf16 h = __float2bfloat16(v);
        bf16 l = __float2bfloat16(v - __bfloat162float(h));
        const size_t d = (size_t)(c0 + y + i) * R + r0 + x;
        oh[d] = h; ol[d] = l;
    }
}

__global__ void __launch_bounds__(256) transpose_half(const float* __restrict__ in,
                                                      __half* __restrict__ out, int R, int C)
{
    __shared__ float t[32][33];
    const int c0 = blockIdx.x * 32, r0 = blockIdx.y * 32;
    const int x = threadIdx.x & 31, y = threadIdx.x >> 5;
#pragma unroll
    for (int i = 0; i < 32; i += 8) t[y + i][x] = in[(size_t)(r0 + y + i) * C + c0 + x];
    __syncthreads();
#pragma unroll
    for (int i = 0; i < 32; i += 8)
        out[(size_t)(c0 + y + i) * R + r0 + x] = __float2half(t[x][y + i]);
}

__global__ void __launch_bounds__(256) cvt_half(const float* __restrict__ in,
                                                __half* __restrict__ out, int n2)
{
    int i = (blockIdx.x * 256 + threadIdx.x) * 2;
    if (i < n2) {
        float2 v = *reinterpret_cast<const float2*>(&in[i]);
        *reinterpret_cast<__half2*>(&out[i]) = __floats2half2_rn(v.x, v.y);
    }
}

// mem_keys: one read -> normalized bf16 planes + raw fp16
__global__ void __launch_bounds__(256) mem_prep(const float* __restrict__ X,
                                                bf16* __restrict__ oh, bf16* __restrict__ ol,
                                                __half* __restrict__ o16)
{
    __shared__ float red[256];
    const int r = blockIdx.x, tid = threadIdx.x;
    const float* p = X + (size_t)r * KD_;
    float ss = 0.0f;
    for (int i = tid; i < KD_; i += 256) { float v = p[i]; ss += v * v; }
    red[tid] = ss; __syncthreads();
    for (int s = 128; s > 0; s >>= 1) { if (tid < s) red[tid] += red[tid + s]; __syncthreads(); }
    const float inv = 1.0f / fmaxf(sqrtf(red[0]), 1e-8f);
    const int i = tid * 2;
    float2 v = *reinterpret_cast<const float2*>(&p[i]);
    uint32_t h, l;
    splitpack(v.x * inv, v.y * inv, h, l);
    *reinterpret_cast<uint32_t*>(&oh[(size_t)r * KD_ + i]) = h;
    *reinterpret_cast<uint32_t*>(&ol[(size_t)r * KD_ + i]) = l;
    *reinterpret_cast<__half2*>(&o16[(size_t)r * KD_ + i]) = __floats2half2_rn(v.x, v.y);
}

// write_keys: one read -> normalized planes (for sim) + raw planes (gate GEMM top half)
__global__ void __launch_bounds__(256) wk_prep(const float* __restrict__ X,
                                               bf16* __restrict__ nh, bf16* __restrict__ nl,
                                               bf16* __restrict__ gh, bf16* __restrict__ gl)
{
    __shared__ float red[256];
    const int r = blockIdx.x, tid = threadIdx.x;
    const float* p = X + (size_t)r * KD_;
    float ss = 0.0f;
    for (int i = tid; i < KD_; i += 256) { float v = p[i]; ss += v * v; }
    red[tid] = ss; __syncthreads();
    for (int s = 128; s > 0; s >>= 1) { if (tid < s) red[tid] += red[tid + s]; __syncthreads(); }
    const float inv = 1.0f / fmaxf(sqrtf(red[0]), 1e-8f);
    const int i = tid * 2;
    float2 v = *reinterpret_cast<const float2*>(&p[i]);
    uint32_t h, l;
    splitpack(v.x * inv, v.y * inv, h, l);
    *reinterpret_cast<uint32_t*>(&nh[(size_t)r * KD_ + i]) = h;
    *reinterpret_cast<uint32_t*>(&nl[(size_t)r * KD_ + i]) = l;
    splitpack(v.x, v.y, h, l);
    *reinterpret_cast<uint32_t*>(&gh[(size_t)r * KD_ + i]) = h;
    *reinterpret_cast<uint32_t*>(&gl[(size_t)r * KD_ + i]) = l;
}

// unpack argmax + gather V0[idx] into gate-GEMM bottom half
__global__ void __launch_bounds__(256) gather_unpack(const unsigned long long* __restrict__ pk,
                                                     const float* __restrict__ mv,
                                                     int* __restrict__ idx,
                                                     bf16* __restrict__ gh, bf16* __restrict__ gl)
{
    const int t = blockIdx.x, tid = threadIdx.x;
    const unsigned long long v = pk[t];
    const int col = (int)(0xFFFFFFFFu - (uint32_t)(v & 0xFFFFFFFFu));
    if (tid == 0) idx[t] = col;
    const float* src = mv + (size_t)col * KD_;
    const int i = tid * 2;
    uint32_t h, l;
    splitpack(src[i], src[i + 1], h, l);
    *reinterpret_cast<uint32_t*>(&gh[(size_t)(BWN + t) * KD_ + i]) = h;
    *reinterpret_cast<uint32_t*>(&gl[(size_t)(BWN + t) * KD_ + i]) = l;
}

// per-slot chains; first event uses precomputed gate; deeper events: bf16x2 matvec
__global__ void __launch_bounds__(256) chain_update(
    const float* __restrict__ wk, const float* __restrict__ wv,
    const uint32_t* __restrict__ WB,        // WgBot bf16x2 packed [r][256]
    const float* __restrict__ Aw,
    const float* __restrict__ BV,
    const int*   __restrict__ idx,
    const float* __restrict__ mk, const float* __restrict__ mv,
    float* __restrict__ outK, float* __restrict__ outV)
{
    __shared__ float sK[KD_], sV[KD_];
    __shared__ int   list[BWN];
    __shared__ int   cnt;
    const int s = blockIdx.x, tid = threadIdx.x;
    if (tid == 0) cnt = 0;
    __syncthreads();
    for (int t = tid; t < BWN; t += 256)
        if (idx[t] == s) { int p = atomicAdd(&cnt, 1); list[p] = t; }
    __syncthreads();
    const int n = cnt;
    if (n == 0) return;
    if (tid == 0) {
        for (int i = 1; i < n; i++) {
            int v = list[i], j = i - 1;
            while (j >= 0 && list[j] > v) { list[j + 1] = list[j]; j--; }
            list[j + 1] = v;
        }
    }
    for (int i = tid; i < KD_; i += 256) {
        sK[i] = mk[(size_t)s * KD_ + i];
        sV[i] = mv[(size_t)s * KD_ + i];
    }
    __syncthreads();
    const int j0 = tid * 2;
    for (int e = 0; e < n; e++) {
        const int t = list[e];
        float a0, a1;
        {
            float2 aw = *reinterpret_cast<const float2*>(&Aw[(size_t)t * KD_ + j0]);
            a0 = aw.x; a1 = aw.y;
        }
        if (e == 0) {
            float2 bv = *reinterpret_cast<const float2*>(&BV[(size_t)t * KD_ + j0]);
            a0 += bv.x; a1 += bv.y;
        } else {
#pragma unroll 8
            for (int r = 0; r < KD_; r++) {
                const float v = sV[r];
                float2 w = bf2_to_f2(WB[r * 256 + tid]);
                a0 += v * w.x;
                a1 += v * w.y;
            }
        }
        const float g0 = 1.0f / (1.0f + expf(-a0));
        const float g1 = 1.0f / (1.0f + expf(-a1));
        __syncthreads();
        float2 k2 = *reinterpret_cast<const float2*>(&wk[(size_t)t * KD_ + j0]);
        float2 v2 = *reinterpret_cast<const float2*>(&wv[(size_t)t * KD_ + j0]);
        sK[j0]     = g0 * k2.x + (1.0f - g0) * sK[j0];
        sK[j0 + 1] = g1 * k2.y + (1.0f - g1) * sK[j0 + 1];
        sV[j0]     = g0 * v2.x + (1.0f - g0) * sV[j0];
        sV[j0 + 1] = g1 * v2.y + (1.0f - g1) * sV[j0 + 1];
        __syncthreads();
    }
    for (int i = tid; i < KD_; i += 256) {
        outK[(size_t)s * KD_ + i] = sK[i];
        outV[(size_t)s * KD_ + i] = sV[i];
    }
}

// ---------------- launcher ----------------
extern "C" void kernel_launch(void* const* d_in, const int* in_sizes, int n_in,
                              void* d_out, int out_size)
{
    const float* queries    = (const float*)d_in[0];
    const float* write_keys = (const float*)d_in[1];
    const float* write_vals = (const float*)d_in[2];
    const float* mem_keys   = (const float*)d_in[3];
    const float* mem_values = (const float*)d_in[4];
    const float* Wq         = (const float*)d_in[5];
    const float* bq         = (const float*)d_in[6];
    const float* Wvp        = (const float*)d_in[7];
    const float* bvp        = (const float*)d_in[8];
    const float* Wg         = (const float*)d_in[9];
    const float* bg         = (const float*)d_in[10];

    float* out_read = (float*)d_out;
    float* out_k    = out_read + (size_t)RB * KD_;
    float* out_v    = out_k    + (size_t)MEMN * KD_;

    void *pA, *pBV, *pRsum, *pIdx, *pPk, *pQI16, *pQ16, *pP16, *pRV16, *pMK16, *pMVT16;
    void *pWqT16, *pWvpT16, *pKNh, *pKNl, *pMNh, *pMNl;
    void *pWgTh, *pWgTl, *pWgBh, *pWgBl, *pWB16, *pGAh, *pGAl;
    cudaGetSymbolAddress(&pA, g_A);         cudaGetSymbolAddress(&pBV, g_BV);
    cudaGetSymbolAddress(&pRsum, g_rsum);
    cudaGetSymbolAddress(&pIdx, g_idx);     cudaGetSymbolAddress(&pPk, g_pk);
    cudaGetSymbolAddress(&pQI16, g_QI16);   cudaGetSymbolAddress(&pQ16, g_Q16);
    cudaGetSymbolAddress(&pP16, g_P16);     cudaGetSymbolAddress(&pRV16, g_RV16);
    cudaGetSymbolAddress(&pMK16, g_MK16);   cudaGetSymbolAddress(&pMVT16, g_MVT16);
    cudaGetSymbolAddress(&pWqT16, g_WqT16); cudaGetSymbolAddress(&pWvpT16, g_WvpT16);
    cudaGetSymbolAddress(&pKNh, g_KNh);     cudaGetSymbolAddress(&pKNl, g_KNl);
    cudaGetSymbolAddress(&pMNh, g_MNh);     cudaGetSymbolAddress(&pMNl, g_MNl);
    cudaGetSymbolAddress(&pWgTh, g_WgTh);   cudaGetSymbolAddress(&pWgTl, g_WgTl);
    cudaGetSymbolAddress(&pWgBh, g_WgBh);   cudaGetSymbolAddress(&pWgBl, g_WgBl);
    cudaGetSymbolAddress(&pWB16, g_WB16);
    cudaGetSymbolAddress(&pGAh, g_GAh);     cudaGetSymbolAddress(&pGAl, g_GAl);

    constexpr int DYN1_256 = 2 * (256 + TN) * ROWB1;
    constexpr int DYN1_128 = 2 * (128 + TN) * ROWB1;
    cudaFuncSetAttribute(bgemm3<3>,   cudaFuncAttributeMaxDynamicSharedMemorySize, DYN3);
    cudaFuncSetAttribute(bgemm3s,     cudaFuncAttributeMaxDynamicSharedMemorySize, DYNS);
    cudaFuncSetAttribute(hgemm1<5,4>, cudaFuncAttributeMaxDynamicSharedMemorySize, DYN1_256);
    cudaFuncSetAttribute(hgemm1<1,4>, cudaFuncAttributeMaxDynamicSharedMemorySize, DYN1_256);
    cudaFuncSetAttribute(hgemm1<2,4>, cudaFuncAttributeMaxDynamicSharedMemorySize, DYN1_256);
    cudaFuncSetAttribute(hgemm1<0,2>, cudaFuncAttributeMaxDynamicSharedMemorySize, DYN1_128);

    const float qscale = 0.044194173824159216f;  // 1/sqrt(512)/TEMP

    // ---- prep ----
    cudaMemsetAsync(pPk, 0, BWN * sizeof(unsigned long long));
    cudaMemsetAsync(pRsum, 0, RQ * sizeof(float));
    transpose_half<<<dim3((HH*KD_)/32, KD_/32), 256>>>(Wq, (__half*)pWqT16, KD_, HH*KD_);
    transpose_half<<<dim3(KD_/32, (HH*KD_)/32), 256>>>(Wvp, (__half*)pWvpT16, HH*KD_, KD_);
    transpose_half<<<dim3(KD_/32, MEMN/32),     256>>>(mem_values, (__half*)pMVT16, MEMN, KD_);
    transpose_split<<<dim3(KD_/32, KD_/32),     256>>>(Wg, (bf16*)pWgTh, (bf16*)pWgTl,
                                                       nullptr, KD_, KD_);
    transpose_split<<<dim3(KD_/32, KD_/32),     256>>>(Wg + (size_t)KD_ * KD_,
                                                       (bf16*)pWgBh, (bf16*)pWgBl,
                                                       (bf16*)pWB16, KD_, KD_);
    mem_prep<<<MEMN, 256>>>(mem_keys, (bf16*)pMNh, (bf16*)pMNl, (__half*)pMK16);
    wk_prep<<<BWN, 256>>>(write_keys, (bf16*)pKNh, (bf16*)pKNl, (bf16*)pGAh, (bf16*)pGAl);
    cvt_half<<<(RB*KD_/2 + 255)/256, 256>>>(queries, (__half*)pQI16, RB*KD_);

    // ---- write path ----
    bgemm3<3><<<dim3(MEMN/TN, BWN/TM3), 256, DYN3>>>(
        (bf16*)pKNh, (bf16*)pKNl, (bf16*)pMNh, (bf16*)pMNl,
        nullptr, nullptr, (unsigned long long*)pPk, BWN, MEMN, KD_, 1.0f);
    gather_unpack<<<BWN, 256>>>((unsigned long long*)pPk, mem_values, (int*)pIdx,
                                (bf16*)pGAh, (bf16*)pGAl);
    bgemm3s<<<dim3(KD_/TNS, (2*BWN)/TMS), 128, DYNS>>>(
        (bf16*)pGAh, (bf16*)pGAl,
        (bf16*)pWgTh, (bf16*)pWgTl, (bf16*)pWgBh, (bf16*)pWgBl,
        bg, (float*)pA, (float*)pBV);
    cudaMemcpyAsync(out_k, mem_keys,   (size_t)MEMN * KD_ * sizeof(float), cudaMemcpyDeviceToDevice);
    cudaMemcpyAsync(out_v, mem_values, (size_t)MEMN * KD_ * sizeof(float), cudaMemcpyDeviceToDevice);
    chain_update<<<MEMN, 256>>>(write_keys, write_vals, (const uint32_t*)pWB16,
                                (float*)pA, (float*)pBV,
                                (int*)pIdx, mem_keys, mem_values, out_k, out_v);

    // ---- read path ----
    hgemm1<1,4><<<dim3((HH*KD_)/TN, RB/256), 256, DYN1_256>>>(
        (__half*)pQI16, (__half*)pWqT16, bq, nullptr, (__half*)pQ16,
        nullptr, nullptr, RB, HH*KD_, KD_, qscale);
    // scores -> exp(fp16) + row sums (softmax fused; no separate kernel)
    hgemm1<5,4><<<dim3(MEMN/TN, RQ/256), 256, DYN1_256>>>(
        (__half*)pQ16, (__half*)pMK16, nullptr, nullptr, (__half*)pP16,
        nullptr, (float*)pRsum, RQ, MEMN, KD_, 1.0f);
    // AV with per-row 1/rsum scaling
    hgemm1<2,4><<<dim3(KD_/TN, RQ/256), 256, DYN1_256>>>(
        (__half*)pP16, (__half*)pMVT16, nullptr, nullptr, (__half*)pRV16,
        (float*)pRsum, nullptr, RQ, KD_, MEMN, 1.0f);
    hgemm1<0,2><<<dim3(KD_/TN, RB/128), 128, DYN1_128>>>(
        (__half*)pRV16, (__half*)pWvpT16, bvp, out_read, nullptr,
        nullptr, nullptr, RB, KD_, HH*KD_, 1.0f);
}

// round 10
// speedup vs baseline: 7.4759x; 1.0772x over previous
#include <cuda_runtime.h>
#include <cuda_bf16.h>
#include <cuda_fp16.h>
#include <math.h>
#include <stdint.h>

#define BB   4
#define NN_  1024
#define KD_  512
#define HH   8
#define MEMN 4096
#define BWN  1024
#define RQ   (BB*HH*NN_)
#define RB   (BB*NN_)

typedef __nv_bfloat16 bf16;

// ---------------- scratch ----------------
__device__ float  g_A  [(size_t)BWN * KD_];          // wk@WgTop + bg
__device__ float  g_BV [(size_t)BWN * KD_];          // V0[idx]@WgBot
__device__ float  g_rsum[RQ];                        // softmax row sums
__device__ int    g_idx[BWN];
__device__ unsigned long long g_pk[BWN];             // packed (val,idx) argmax
__device__ __half g_QI16[(size_t)RB * KD_];
__device__ __half g_Q16[(size_t)RQ * KD_];
__device__ __half g_P16[(size_t)RQ * MEMN];          // exp(scores) fp16
__device__ __half g_RV16[(size_t)RB * (HH*KD_)];
__device__ __half g_MK16[(size_t)MEMN * KD_];
__device__ __half g_MVT16[(size_t)KD_ * MEMN];
__device__ __half g_WqT16[(size_t)(HH*KD_) * KD_];
__device__ __half g_WvpT16[(size_t)KD_ * (HH*KD_)];
__device__ bf16 g_KNh[(size_t)BWN * KD_],  g_KNl[(size_t)BWN * KD_];
__device__ bf16 g_MNh[(size_t)MEMN * KD_], g_MNl[(size_t)MEMN * KD_];
__device__ bf16 g_WgTh[(size_t)KD_ * KD_], g_WgTl[(size_t)KD_ * KD_];
__device__ bf16 g_WgBh[(size_t)KD_ * KD_], g_WgBl[(size_t)KD_ * KD_];
__device__ bf16 g_WB16[(size_t)KD_ * KD_];            // WgBot row-major bf16 (chain matvec)
__device__ bf16 g_GAh[(size_t)2*BWN * KD_], g_GAl[(size_t)2*BWN * KD_];  // [wk rows | V0[idx] rows]

// ---------------- helpers ----------------
__device__ __forceinline__ uint32_t smem_to_u32(const void* p) {
    uint32_t a;
    asm("{ .reg .u64 t; cvta.to.shared.u64 t, %1; cvt.u32.u64 %0, t; }" : "=r"(a) : "l"(p));
    return a;
}
__device__ __forceinline__ void ldsm4(uint32_t* r, uint32_t addr) {
    asm volatile("ldmatrix.sync.aligned.m8n8.x4.shared.b16 {%0,%1,%2,%3}, [%4];"
                 : "=r"(r[0]), "=r"(r[1]), "=r"(r[2]), "=r"(r[3]) : "r"(addr));
}
__device__ __forceinline__ void mma_bf(float* c, const uint32_t* a, const uint32_t* b) {
    asm volatile(
        "mma.sync.aligned.m16n8k16.row.col.f32.bf16.bf16.f32 "
        "{%0,%1,%2,%3}, {%4,%5,%6,%7}, {%8,%9}, {%0,%1,%2,%3};"
        : "+f"(c[0]), "+f"(c[1]), "+f"(c[2]), "+f"(c[3])
        : "r"(a[0]), "r"(a[1]), "r"(a[2]), "r"(a[3]), "r"(b[0]), "r"(b[1]));
}
__device__ __forceinline__ void mma_fp(float* c, const uint32_t* a, const uint32_t* b) {
    asm volatile(
        "mma.sync.aligned.m16n8k16.row.col.f32.f16.f16.f32 "
        "{%0,%1,%2,%3}, {%4,%5,%6,%7}, {%8,%9}, {%0,%1,%2,%3};"
        : "+f"(c[0]), "+f"(c[1]), "+f"(c[2]), "+f"(c[3])
        : "r"(a[0]), "r"(a[1]), "r"(a[2]), "r"(a[3]), "r"(b[0]), "r"(b[1]));
}
__device__ __forceinline__ void cp16(uint32_t dst, const void* src) {
    asm volatile("cp.async.cg.shared.global [%0], [%1], 16;" :: "r"(dst), "l"(src));
}
#define CP_COMMIT() asm volatile("cp.async.commit_group;" ::: "memory")
#define CP_WAIT1()  asm volatile("cp.async.wait_group 1;" ::: "memory")

__device__ __forceinline__ void splitpack(float x, float y, uint32_t& h, uint32_t& l) {
    bf16 hx = __float2bfloat16(x), hy = __float2bfloat16(y);
    float rx = x - __bfloat162float(hx), ry = y - __bfloat162float(hy);
    bf16 lx = __float2bfloat16(rx), ly = __float2bfloat16(ry);
    h = (uint32_t)__bfloat16_as_ushort(hx) | ((uint32_t)__bfloat16_as_ushort(hy) << 16);
    l = (uint32_t)__bfloat16_as_ushort(lx) | ((uint32_t)__bfloat16_as_ushort(ly) << 16);
}
__device__ __forceinline__ unsigned long long packmax(float v, int col) {
    uint32_t b = __float_as_uint(v);
    b = (b & 0x80000000u) ? ~b : (b | 0x80000000u);
    return ((unsigned long long)b << 32) | (unsigned long long)(0xFFFFFFFFu - (uint32_t)col);
}
__device__ __forceinline__ float2 bf2_to_f2(uint32_t u) {
    float2 r;
    r.x = __uint_as_float(u << 16);
    r.y = __uint_as_float(u & 0xFFFF0000u);
    return r;
}

#define TN 128
#define ROWB 144    // KC=32 bf16 hi|lo row
#define ROWB1 272   // KC=128 fp16 row

template<int MODE>
__device__ __forceinline__ size_t dst_of(int r, int c, int N) {
    if (MODE == 0 || MODE == 5) return (size_t)r * N + c;
    if (MODE == 1) {
        const int b_ = r >> 10, n_ = r & 1023, h_ = c >> 9, d_ = c & 511;
        return ((size_t)((b_ * 8 + h_) * 1024 + n_) << 9) + d_;
    }
    const int b_ = r >> 13, h_ = (r >> 10) & 7, n_ = r & 1023;
    return ((size_t)(b_ * 1024 + n_) << 12) + ((size_t)h_ << 9) + c;
}

// ================= 3-term split-bf16 GEMM, TM=256 (MODE 3: fused row-argmax) =================
#define TM3 256
#define KC3 32
#define STAGE3 ((TM3 + TN) * ROWB)
#define DYN3 (2 * STAGE3)

template<int MODE>
__global__ void __launch_bounds__(256, 1)
bgemm3(const bf16* __restrict__ Ah, const bf16* __restrict__ Al,
       const bf16* __restrict__ Bh, const bf16* __restrict__ Bl,
       const float* __restrict__ bias, float* __restrict__ C,
       unsigned long long* __restrict__ Packed,
       int M, int N, int K, float scale)
{
    extern __shared__ char sm[];
    const uint32_t smem_u = smem_to_u32(sm);
    const int tid = threadIdx.x;
    const int lane = tid & 31, wid = tid >> 5;
    const int bm = blockIdx.y * TM3, bn = blockIdx.x * TN;
    const int wm = (wid >> 1) * 64, wn = (wid & 1) * 64;

    float acc[4][8][4];
#pragma unroll
    for (int i = 0; i < 4; i++)
#pragma unroll
        for (int j = 0; j < 8; j++)
#pragma unroll
            for (int k = 0; k < 4; k++) acc[i][j][k] = 0.0f;

    const int NC = K / KC3;

    auto load_chunk = [&](int c, int st) {
        const int k0 = c * KC3;
        const uint32_t sb = smem_u + st * STAGE3;
#pragma unroll
        for (int u = 0; u < 3; u++) {
            const int unit = tid + u * 256;
            const int r = (unit & 511) >> 1, pl = unit & 1;
            const bf16* src;
            uint32_t dst;
            if (unit < 512) {
                src = (pl ? Al : Ah) + (size_t)(bm + r) * K + k0;
                dst = sb + r * ROWB + pl * 64;
            } else {
                src = (pl ? Bl : Bh) + (size_t)(bn + r) * K + k0;
                dst = sb + (TM3 + r) * ROWB + pl * 64;
            }
#pragma unroll
            for (int i = 0; i < 4; i++) cp16(dst + i * 16, src + i * 8);
        }
    };

    load_chunk(0, 0); CP_COMMIT();
    load_chunk(1, 1); CP_COMMIT();

    const int mr = lane & 7, msel = lane >> 3;
    const int aro = ((msel & 1) << 3) + mr;
    const int aco = (msel >> 1) << 3;
    const int bro = ((msel >> 1) << 3) + mr;
    const int bco = (msel & 1) << 3;

    for (int c = 0; c < NC; c++) {
        CP_WAIT1();
        __syncthreads();
        const uint32_t base = smem_u + (c & 1) * STAGE3;
#pragma unroll
        for (int ks = 0; ks < 2; ks++) {
            uint32_t ah[4][4], al[4][4], bh[8][2], bl[8][2];
            const int colA = (ks * 16 + aco) * 2;
            const int colB = (ks * 16 + bco) * 2;
#pragma unroll
            for (int mi = 0; mi < 4; mi++) {
                const uint32_t ad = base + (wm + mi * 16 + aro) * ROWB + colA;
                ldsm4(ah[mi], ad);
                ldsm4(al[mi], ad + 64);
            }
#pragma unroll
            for (int g = 0; g < 4; g++) {
                const uint32_t bd = base + (TM3 + wn + g * 16 + bro) * ROWB + colB;
                uint32_t t[4];
                ldsm4(t, bd);
                bh[2*g][0] = t[0]; bh[2*g][1] = t[1];
                bh[2*g+1][0] = t[2]; bh[2*g+1][1] = t[3];
                ldsm4(t, bd + 64);
                bl[2*g][0] = t[0]; bl[2*g][1] = t[1];
                bl[2*g+1][0] = t[2]; bl[2*g+1][1] = t[3];
            }
#pragma unroll
            for (int mi = 0; mi < 4; mi++)
#pragma unroll
                for (int nb = 0; nb < 8; nb++) {
                    mma_bf(acc[mi][nb], ah[mi], bh[nb]);
                    mma_bf(acc[mi][nb], ah[mi], bl[nb]);
                    mma_bf(acc[mi][nb], al[mi], bh[nb]);
                }
        }
        __syncthreads();
        if (c + 2 < NC) load_chunk(c + 2, c & 1);
        CP_COMMIT();
    }

    const int group = lane >> 2, tig = lane & 3;
    if (MODE == 3) {
#pragma unroll
        for (int mi = 0; mi < 4; mi++) {
#pragma unroll
            for (int half = 0; half < 2; half++) {
                const int row = bm + wm + mi * 16 + group + half * 8;
                float bv = -1e30f; int bc = 0;
#pragma unroll
                for (int nb = 0; nb < 8; nb++) {
                    const int col = bn + wn + nb * 8 + tig * 2;
                    const float v0 = acc[mi][nb][half * 2 + 0];
                    const float v1 = acc[mi][nb][half * 2 + 1];
                    if (v0 > bv) { bv = v0; bc = col; }
                    if (v1 > bv) { bv = v1; bc = col + 1; }
                }
#pragma unroll
                for (int m = 1; m <= 2; m <<= 1) {
                    float ov = __shfl_xor_sync(0xffffffffu, bv, m);
                    int   oc = __shfl_xor_sync(0xffffffffu, bc, m);
                    if (ov > bv || (ov == bv && oc < bc)) { bv = ov; bc = oc; }
                }
                if (tig == 0) atomicMax(Packed + row, packmax(bv, bc));
            }
        }
    } else {
#pragma unroll
        for (int mi = 0; mi < 4; mi++) {
            const int r_lo = bm + wm + mi * 16 + group;
#pragma unroll
            for (int nb = 0; nb < 8; nb++) {
                const int col = bn + wn + nb * 8 + tig * 2;
                float b0 = 0.0f, b1 = 0.0f;
                if (bias) { b0 = bias[col]; b1 = bias[col + 1]; }
                *reinterpret_cast<float2*>(&C[(size_t)r_lo * N + col]) =
                    make_float2((acc[mi][nb][0] + b0) * scale, (acc[mi][nb][1] + b1) * scale);
                *reinterpret_cast<float2*>(&C[(size_t)(r_lo + 8) * N + col]) =
                    make_float2((acc[mi][nb][2] + b0) * scale, (acc[mi][nb][3] + b1) * scale);
            }
        }
    }
}

// ====== small-tile 3-term gate GEMM: M=2048 (rows<1024: WgT+bias->outA; else WgB->outBV) ======
#define TMS 64
#define TNS 64
#define STAGES ((TMS + TNS) * ROWB)
#define DYNS (2 * STAGES)

__global__ void __launch_bounds__(128, 1)
bgemm3s(const bf16* __restrict__ Ah, const bf16* __restrict__ Al,
        const bf16* __restrict__ B1h, const bf16* __restrict__ B1l,
        const bf16* __restrict__ B2h, const bf16* __restrict__ B2l,
        const float* __restrict__ bias, float* __restrict__ outA, float* __restrict__ outBV)
{
    constexpr int K = KD_, N = KD_;
    extern __shared__ char sm[];
    const uint32_t smem_u = smem_to_u32(sm);
    const int tid = threadIdx.x;
    const int lane = tid & 31, wid = tid >> 5;
    const int bm = blockIdx.y * TMS, bn = blockIdx.x * TNS;
    const bool second = bm >= BWN;
    const bf16* Bh = second ? B2h : B1h;
    const bf16* Bl = second ? B2l : B1l;
    float* out = second ? outBV : outA;
    const int rowbase = second ? bm - BWN : bm;
    const int wm = (wid >> 1) * 32, wn = (wid & 1) * 32;

    float acc[2][4][4];
#pragma unroll
    for (int i = 0; i < 2; i++)
#pragma unroll
        for (int j = 0; j < 4; j++)
#pragma unroll
            for (int k = 0; k < 4; k++) acc[i][j][k] = 0.0f;

    const int NC = K / KC3;

    auto load_chunk = [&](int c, int st) {
        const int k0 = c * KC3;
        const uint32_t sb = smem_u + st * STAGES;
#pragma unroll
        for (int u = 0; u < 2; u++) {
            const int unit = tid + u * 128;
            const int r = (unit & 127) >> 1, pl = unit & 1;
            const bf16* src;
            uint32_t dst;
            if (unit < 128) {
                src = (pl ? Al : Ah) + (size_t)(bm + r) * K + k0;
                dst = sb + r * ROWB + pl * 64;
            } else {
                src = (pl ? Bl : Bh) + (size_t)(bn + r) * K + k0;
                dst = sb + (TMS + r) * ROWB + pl * 64;
            }
#pragma unroll
            for (int i = 0; i < 4; i++) cp16(dst + i * 16, src + i * 8);
        }
    };

    load_chunk(0, 0); CP_COMMIT();
    load_chunk(1, 1); CP_COMMIT();

    const int mr = lane & 7, msel = lane >> 3;
    const int aro = ((msel & 1) << 3) + mr;
    const int aco = (msel >> 1) << 3;
    const int bro = ((msel >> 1) << 3) + mr;
    const int bco = (msel & 1) << 3;

    for (int c = 0; c < NC; c++) {
        CP_WAIT1();
        __syncthreads();
        const uint32_t base = smem_u + (c & 1) * STAGES;
#pragma unroll
        for (int ks = 0; ks < 2; ks++) {
            uint32_t ah[2][4], al[2][4], bh[4][2], bl[4][2];
            const int colA = (ks * 16 + aco) * 2;
            const int colB = (ks * 16 + bco) * 2;
#pragma unroll
            for (int mi = 0; mi < 2; mi++) {
                const uint32_t ad = base + (wm + mi * 16 + aro) * ROWB + colA;
                ldsm4(ah[mi], ad);
                ldsm4(al[mi], ad + 64);
            }
#pragma unroll
            for (int g = 0; g < 2; g++) {
                const uint32_t bd = base + (TMS + wn + g * 16 + bro) * ROWB + colB;
                uint32_t t[4];
                ldsm4(t, bd);
                bh[2*g][0] = t[0]; bh[2*g][1] = t[1];
                bh[2*g+1][0] = t[2]; bh[2*g+1][1] = t[3];
                ldsm4(t, bd + 64);
                bl[2*g][0] = t[0]; bl[2*g][1] = t[1];
                bl[2*g+1][0] = t[2]; bl[2*g+1][1] = t[3];
            }
#pragma unroll
            for (int mi = 0; mi < 2; mi++)
#pragma unroll
                for (int nb = 0; nb < 4; nb++) {
                    mma_bf(acc[mi][nb], ah[mi], bh[nb]);
                    mma_bf(acc[mi][nb], ah[mi], bl[nb]);
                    mma_bf(acc[mi][nb], al[mi], bh[nb]);
                }
        }
        __syncthreads();
        if (c + 2 < NC) load_chunk(c + 2, c & 1);
        CP_COMMIT();
    }

    const int group = lane >> 2, tig = lane & 3;
#pragma unroll
    for (int mi = 0; mi < 2; mi++) {
        const int r_lo = rowbase + wm + mi * 16 + group;
#pragma unroll
        for (int nb = 0; nb < 4; nb++) {
            const int col = bn + wn + nb * 8 + tig * 2;
            float b0 = 0.0f, b1 = 0.0f;
            if (!second) { b0 = bias[col]; b1 = bias[col + 1]; }
            *reinterpret_cast<float2*>(&out[(size_t)r_lo * N + col]) =
                make_float2(acc[mi][nb][0] + b0, acc[mi][nb][1] + b1);
            *reinterpret_cast<float2*>(&out[(size_t)(r_lo + 8) * N + col]) =
                make_float2(acc[mi][nb][2] + b0, acc[mi][nb][3] + b1);
        }
    }
}

// ================= single-term fp16 GEMM (KC=128), TM = WM*64 =================
// MODE 0: fp32 out; MODE 1: qproj remap fp16; MODE 2: AV remap fp16 scaled by 1/rsum[row];
// MODE 5: scores -> exp() fp16 + per-row sum atomics
#define KC1 128

template<int MODE, int WM>
__global__ void __launch_bounds__(WM*64, 1)
hgemm1(const __half* __restrict__ A, const __half* __restrict__ B,
       const float* __restrict__ bias,
       float* __restrict__ C, __half* __restrict__ C16,
       const float* __restrict__ rsum, float* __restrict__ rsumo,
       int M, int N, int K, float scale)
{
    constexpr int TMv = WM * 64;
    constexpr int NT  = WM * 64;
    constexpr int STAGE = (TMv + TN) * ROWB1;
    extern __shared__ char sm[];
    const uint32_t smem_u = smem_to_u32(sm);
    const int tid = threadIdx.x;
    const int lane = tid & 31, wid = tid >> 5;
    const int bm = blockIdx.y * TMv, bn = blockIdx.x * TN;
    const int wm = (wid >> 1) * 64, wn = (wid & 1) * 64;

    float acc[4][8][4];
#pragma unroll
    for (int i = 0; i < 4; i++)
#pragma unroll
        for (int j = 0; j < 8; j++)
#pragma unroll
            for (int k = 0; k < 4; k++) acc[i][j][k] = 0.0f;

    const int NC = K / KC1;

    auto load_chunk = [&](int c, int st) {
        const int k0 = c * KC1;
        const uint32_t sb = smem_u + st * STAGE;
#pragma unroll
        for (int u = tid; u < (TMv + TN) * 16; u += NT) {
            const int r = u >> 4, seg = u & 15;
            const __half* src = (r < TMv)
                ? A + (size_t)(bm + r) * K + k0 + seg * 8
                : B + (size_t)(bn + (r - TMv)) * K + k0 + seg * 8;
            cp16(sb + r * ROWB1 + seg * 16, src);
        }
    };

    load_chunk(0, 0); CP_COMMIT();
    load_chunk(1, 1); CP_COMMIT();

    const int mr = lane & 7, msel = lane >> 3;
    const int aro = ((msel & 1) << 3) + mr;
    const int aco = (msel >> 1) << 3;
    const int bro = ((msel >> 1) << 3) + mr;
    const int bco = (msel & 1) << 3;

    for (int c = 0; c < NC; c++) {
        CP_WAIT1();
        __syncthreads();
        const uint32_t base = smem_u + (c & 1) * STAGE;
#pragma unroll
        for (int ks = 0; ks < 8; ks++) {
            uint32_t ah[4][4], bh[8][2];
            const int colA = (ks * 16 + aco) * 2;
            const int colB = (ks * 16 + bco) * 2;
#pragma unroll
            for (int mi = 0; mi < 4; mi++)
                ldsm4(ah[mi], base + (wm + mi * 16 + aro) * ROWB1 + colA);
#pragma unroll
            for (int g = 0; g < 4; g++) {
                uint32_t t[4];
                ldsm4(t, base + (TMv + wn + g * 16 + bro) * ROWB1 + colB);
                bh[2*g][0] = t[0]; bh[2*g][1] = t[1];
                bh[2*g+1][0] = t[2]; bh[2*g+1][1] = t[3];
            }
#pragma unroll
            for (int mi = 0; mi < 4; mi++)
#pragma unroll
                for (int nb = 0; nb < 8; nb++)
                    mma_fp(acc[mi][nb], ah[mi], bh[nb]);
        }
        __syncthreads();
        if (c + 2 < NC) load_chunk(c + 2, c & 1);
        CP_COMMIT();
    }

    const int group = lane >> 2, tig = lane & 3;
    if (MODE == 5) {
#pragma unroll
        for (int mi = 0; mi < 4; mi++) {
            const int r_lo = bm + wm + mi * 16 + group;
            float rs0 = 0.0f, rs1 = 0.0f;
#pragma unroll
            for (int nb = 0; nb < 8; nb++) {
                const int col = bn + wn + nb * 8 + tig * 2;
                float e00 = __expf(acc[mi][nb][0]);
                float e01 = __expf(acc[mi][nb][1]);
                float e10 = __expf(acc[mi][nb][2]);
                float e11 = __expf(acc[mi][nb][3]);
                rs0 += e00 + e01;
                rs1 += e10 + e11;
                *reinterpret_cast<__half2*>(&C16[(size_t)r_lo * N + col]) = __floats2half2_rn(e00, e01);
                *reinterpret_cast<__half2*>(&C16[(size_t)(r_lo + 8) * N + col]) = __floats2half2_rn(e10, e11);
            }
            rs0 += __shfl_xor_sync(0xffffffffu, rs0, 1);
            rs0 += __shfl_xor_sync(0xffffffffu, rs0, 2);
            rs1 += __shfl_xor_sync(0xffffffffu, rs1, 1);
            rs1 += __shfl_xor_sync(0xffffffffu, rs1, 2);
            if (tig == 0) {
                atomicAdd(rsumo + r_lo, rs0);
                atomicAdd(rsumo + r_lo + 8, rs1);
            }
        }
    } else {
#pragma unroll
        for (int mi = 0; mi < 4; mi++) {
            const int r_lo = bm + wm + mi * 16 + group;
            float s0 = scale, s1 = scale;
            if (MODE == 2) {
                s0 = scale / rsum[r_lo];
                s1 = scale / rsum[r_lo + 8];
            }
#pragma unroll
            for (int nb = 0; nb < 8; nb++) {
                const int col = bn + wn + nb * 8 + tig * 2;
                float b0 = 0.0f, b1 = 0.0f;
                if (bias) { b0 = bias[col]; b1 = bias[col + 1]; }
                float v00 = (acc[mi][nb][0] + b0) * s0;
                float v01 = (acc[mi][nb][1] + b1) * s0;
                float v10 = (acc[mi][nb][2] + b0) * s1;
                float v11 = (acc[mi][nb][3] + b1) * s1;
                if (MODE == 0) {
                    *reinterpret_cast<float2*>(&C[dst_of<0>(r_lo,     col, N)]) = make_float2(v00, v01);
                    *reinterpret_cast<float2*>(&C[dst_of<0>(r_lo + 8, col, N)]) = make_float2(v10, v11);
                } else {
                    *reinterpret_cast<__half2*>(&C16[dst_of<MODE>(r_lo,     col, N)]) = __floats2half2_rn(v00, v01);
                    *reinterpret_cast<__half2*>(&C16[dst_of<MODE>(r_lo + 8, col, N)]) = __floats2half2_rn(v10, v11);
                }
            }
        }
    }
}

// ---------------- prep / small kernels ----------------
__global__ void __launch_bounds__(256) transpose_split(const float* __restrict__ in,
                                                       bf16* __restrict__ oh, bf16* __restrict__ ol,
                                                       bf16* __restrict__ raw16,
                                                       int R, int C)
{
    __shared__ float t[32][33];
    const int c0 = blockIdx.x * 32, r0 = blockIdx.y * 32;
    const int x = threadIdx.x & 31, y = threadIdx.x >> 5;
#pragma unroll
    for (int i = 0; i < 32; i += 8) {
        float v = in[(size_t)(r0 + y + i) * C + c0 + x];
        t[y + i][x] = v;
        if (raw16) raw16[(size_t)(r0 + y + i) * C + c0 + x] = __float2bfloat16(v);
    }
    __syncthreads();
#pragma unroll
    for (int i = 0; i < 32; i += 8) {
        float v = t[x][y + i];
        bf16 h = __float2bfloat16(v);
        bf16 l = __float2bfloat16(v - __bfloat162float(h));
        const size_t d = (size_t)(c0 + y + i) * R + r0 + x;
        oh[d] = h; ol[d] = l;
    }
}

__global__ void __launch_bounds__(256) transpose_half(const float* __restrict__ in,
                                                      __half* __restrict__ out, int R, int C)
{
    __shared__ float t[32][33];
    const int c0 = blockIdx.x * 32, r0 = blockIdx.y * 32;
    const int x = threadIdx.x & 31, y = threadIdx.x >> 5;
#pragma unroll
    for (int i = 0; i < 32; i += 8) t[y + i][x] = in[(size_t)(r0 + y + i) * C + c0 + x];
    __syncthreads();
#pragma unroll
    for (int i = 0; i < 32; i += 8)
        out[(size_t)(c0 + y + i) * R + r0 + x] = __float2half(t[x][y + i]);
}

__global__ void __launch_bounds__(256) cvt_half(const float* __restrict__ in,
                                                __half* __restrict__ out, int n2)
{
    int i = (blockIdx.x * 256 + threadIdx.x) * 2;
    if (i < n2) {
        float2 v = *reinterpret_cast<const float2*>(&in[i]);
        *reinterpret_cast<__half2*>(&out[i]) = __floats2half2_rn(v.x, v.y);
    }
}

__global__ void __launch_bounds__(256) mem_prep(const float* __restrict__ X,
                                                bf16* __restrict__ oh, bf16* __restrict__ ol,
                                                __half* __restrict__ o16)
{
    __shared__ float red[256];
    const int r = blockIdx.x, tid = threadIdx.x;
    const float* p = X + (size_t)r * KD_;
    float ss = 0.0f;
    for (int i = tid; i < KD_; i += 256) { float v = p[i]; ss += v * v; }
    red[tid] = ss; __syncthreads();
    for (int s = 128; s > 0; s >>= 1) { if (tid < s) red[tid] += red[tid + s]; __syncthreads(); }
    const float inv = 1.0f / fmaxf(sqrtf(red[0]), 1e-8f);
    const int i = tid * 2;
    float2 v = *reinterpret_cast<const float2*>(&p[i]);
    uint32_t h, l;
    splitpack(v.x * inv, v.y * inv, h, l);
    *reinterpret_cast<uint32_t*>(&oh[(size_t)r * KD_ + i]) = h;
    *reinterpret_cast<uint32_t*>(&ol[(size_t)r * KD_ + i]) = l;
    *reinterpret_cast<__half2*>(&o16[(size_t)r * KD_ + i]) = __floats2half2_rn(v.x, v.y);
}

__global__ void __launch_bounds__(256) wk_prep(const float* __restrict__ X,
                                               bf16* __restrict__ nh, bf16* __restrict__ nl,
                                               bf16* __restrict__ gh, bf16* __restrict__ gl)
{
    __shared__ float red[256];
    const int r = blockIdx.x, tid = threadIdx.x;
    const float* p = X + (size_t)r * KD_;
    float ss = 0.0f;
    for (int i = tid; i < KD_; i += 256) { float v = p[i]; ss += v * v; }
    red[tid] = ss; __syncthreads();
    for (int s = 128; s > 0; s >>= 1) { if (tid < s) red[tid] += red[tid + s]; __syncthreads(); }
    const float inv = 1.0f / fmaxf(sqrtf(red[0]), 1e-8f);
    const int i = tid * 2;
    float2 v = *reinterpret_cast<const float2*>(&p[i]);
    uint32_t h, l;
    splitpack(v.x * inv, v.y * inv, h, l);
    *reinterpret_cast<uint32_t*>(&nh[(size_t)r * KD_ + i]) = h;
    *reinterpret_cast<uint32_t*>(&nl[(size_t)r * KD_ + i]) = l;
    splitpack(v.x, v.y, h, l);
    *reinterpret_cast<uint32_t*>(&gh[(size_t)r * KD_ + i]) = h;
    *reinterpret_cast<uint32_t*>(&gl[(size_t)r * KD_ + i]) = l;
}

__global__ void __launch_bounds__(256) gather_unpack(const unsigned long long* __restrict__ pk,
                                                     const float* __restrict__ mv,
                                                     int* __restrict__ idx,
                                                     bf16* __restrict__ gh, bf16* __restrict__ gl)
{
    const int t = blockIdx.x, tid = threadIdx.x;
    const unsigned long long v = pk[t];
    const int col = (int)(0xFFFFFFFFu - (uint32_t)(v & 0xFFFFFFFFu));
    if (tid == 0) idx[t] = col;
    const float* src = mv + (size_t)col * KD_;
    const int i = tid * 2;
    uint32_t h, l;
    splitpack(src[i], src[i + 1], h, l);
    *reinterpret_cast<uint32_t*>(&gh[(size_t)(BWN + t) * KD_ + i]) = h;
    *reinterpret_cast<uint32_t*>(&gl[(size_t)(BWN + t) * KD_ + i]) = l;
}

__global__ void __launch_bounds__(256) chain_update(
    const float* __restrict__ wk, const float* __restrict__ wv,
    const uint32_t* __restrict__ WB,
    const float* __restrict__ Aw,
    const float* __restrict__ BV,
    const int*   __restrict__ idx,
    const float* __restrict__ mk, const float* __restrict__ mv,
    float* __restrict__ outK, float* __restrict__ outV)
{
    __shared__ float sK[KD_], sV[KD_];
    __shared__ int   list[BWN];
    __shared__ int   cnt;
    const int s = blockIdx.x, tid = threadIdx.x;
    if (tid == 0) cnt = 0;
    __syncthreads();
    for (int t = tid; t < BWN; t += 256)
        if (idx[t] == s) { int p = atomicAdd(&cnt, 1); list[p] = t; }
    __syncthreads();
    const int n = cnt;
    if (n == 0) return;
    if (tid == 0) {
        for (int i = 1; i < n; i++) {
            int v = list[i], j = i - 1;
            while (j >= 0 && list[j] > v) { list[j + 1] = list[j]; j--; }
            list[j + 1] = v;
        }
    }
    for (int i = tid; i < KD_; i += 256) {
        sK[i] = mk[(size_t)s * KD_ + i];
        sV[i] = mv[(size_t)s * KD_ + i];
    }
    __syncthreads();
    const int j0 = tid * 2;
    for (int e = 0; e < n; e++) {
        const int t = list[e];
        float a0, a1;
        {
            float2 aw = *reinterpret_cast<const float2*>(&Aw[(size_t)t * KD_ + j0]);
            a0 = aw.x; a1 = aw.y;
        }
        if (e == 0) {
            float2 bv = *reinterpret_cast<const float2*>(&BV[(size_t)t * KD_ + j0]);
            a0 += bv.x; a1 += bv.y;
        } else {
#pragma unroll 8
            for (int r = 0; r < KD_; r++) {
                const float v = sV[r];
                float2 w = bf2_to_f2(WB[r * 256 + tid]);
                a0 += v * w.x;
                a1 += v * w.y;
            }
        }
        const float g0 = 1.0f / (1.0f + expf(-a0));
        const float g1 = 1.0f / (1.0f + expf(-a1));
        __syncthreads();
        float2 k2 = *reinterpret_cast<const float2*>(&wk[(size_t)t * KD_ + j0]);
        float2 v2 = *reinterpret_cast<const float2*>(&wv[(size_t)t * KD_ + j0]);
        sK[j0]     = g0 * k2.x + (1.0f - g0) * sK[j0];
        sK[j0 + 1] = g1 * k2.y + (1.0f - g1) * sK[j0 + 1];
        sV[j0]     = g0 * v2.x + (1.0f - g0) * sV[j0];
        sV[j0 + 1] = g1 * v2.y + (1.0f - g1) * sV[j0 + 1];
        __syncthreads();
    }
    for (int i = tid; i < KD_; i += 256) {
        outK[(size_t)s * KD_ + i] = sK[i];
        outV[(size_t)s * KD_ + i] = sV[i];
    }
}

// ---------------- launcher ----------------
extern "C" void kernel_launch(void* const* d_in, const int* in_sizes, int n_in,
                              void* d_out, int out_size)
{
    const float* queries    = (const float*)d_in[0];
    const float* write_keys = (const float*)d_in[1];
    const float* write_vals = (const float*)d_in[2];
    const float* mem_keys   = (const float*)d_in[3];
    const float* mem_values = (const float*)d_in[4];
    const float* Wq         = (const float*)d_in[5];
    const float* bq         = (const float*)d_in[6];
    const float* Wvp        = (const float*)d_in[7];
    const float* bvp        = (const float*)d_in[8];
    const float* Wg         = (const float*)d_in[9];
    const float* bg         = (const float*)d_in[10];

    float* out_read = (float*)d_out;
    float* out_k    = out_read + (size_t)RB * KD_;
    float* out_v    = out_k    + (size_t)MEMN * KD_;

    void *pA, *pBV, *pRsum, *pIdx, *pPk, *pQI16, *pQ16, *pP16, *pRV16, *pMK16, *pMVT16;
    void *pWqT16, *pWvpT16, *pKNh, *pKNl, *pMNh, *pMNl;
    void *pWgTh, *pWgTl, *pWgBh, *pWgBl, *pWB16, *pGAh, *pGAl;
    cudaGetSymbolAddress(&pA, g_A);         cudaGetSymbolAddress(&pBV, g_BV);
    cudaGetSymbolAddress(&pRsum, g_rsum);
    cudaGetSymbolAddress(&pIdx, g_idx);     cudaGetSymbolAddress(&pPk, g_pk);
    cudaGetSymbolAddress(&pQI16, g_QI16);   cudaGetSymbolAddress(&pQ16, g_Q16);
    cudaGetSymbolAddress(&pP16, g_P16);     cudaGetSymbolAddress(&pRV16, g_RV16);
    cudaGetSymbolAddress(&pMK16, g_MK16);   cudaGetSymbolAddress(&pMVT16, g_MVT16);
    cudaGetSymbolAddress(&pWqT16, g_WqT16); cudaGetSymbolAddress(&pWvpT16, g_WvpT16);
    cudaGetSymbolAddress(&pKNh, g_KNh);     cudaGetSymbolAddress(&pKNl, g_KNl);
    cudaGetSymbolAddress(&pMNh, g_MNh);     cudaGetSymbolAddress(&pMNl, g_MNl);
    cudaGetSymbolAddress(&pWgTh, g_WgTh);   cudaGetSymbolAddress(&pWgTl, g_WgTl);
    cudaGetSymbolAddress(&pWgBh, g_WgBh);   cudaGetSymbolAddress(&pWgBl, g_WgBl);
    cudaGetSymbolAddress(&pWB16, g_WB16);
    cudaGetSymbolAddress(&pGAh, g_GAh);     cudaGetSymbolAddress(&pGAl, g_GAl);

    constexpr int DYN1_256 = 2 * (256 + TN) * ROWB1;
    constexpr int DYN1_128 = 2 * (128 + TN) * ROWB1;
    cudaFuncSetAttribute(bgemm3<3>,   cudaFuncAttributeMaxDynamicSharedMemorySize, DYN3);
    cudaFuncSetAttribute(bgemm3s,     cudaFuncAttributeMaxDynamicSharedMemorySize, DYNS);
    cudaFuncSetAttribute(hgemm1<5,4>, cudaFuncAttributeMaxDynamicSharedMemorySize, DYN1_256);
    cudaFuncSetAttribute(hgemm1<1,4>, cudaFuncAttributeMaxDynamicSharedMemorySize, DYN1_256);
    cudaFuncSetAttribute(hgemm1<2,4>, cudaFuncAttributeMaxDynamicSharedMemorySize, DYN1_256);
    cudaFuncSetAttribute(hgemm1<0,2>, cudaFuncAttributeMaxDynamicSharedMemorySize, DYN1_128);

    // side stream + fork/join events (created once on the uncaptured correctness
    // call; reused by the capture call — work issued is identical every call)
    static cudaStream_t s2 = nullptr;
    static cudaEvent_t eF0 = nullptr, eF1 = nullptr, eJ = nullptr;
    if (s2 == nullptr) {
        cudaStreamCreateWithFlags(&s2, cudaStreamNonBlocking);
        cudaEventCreateWithFlags(&eF0, cudaEventDisableTiming);
        cudaEventCreateWithFlags(&eF1, cudaEventDisableTiming);
        cudaEventCreateWithFlags(&eJ,  cudaEventDisableTiming);
    }

    const float qscale = 0.044194173824159216f;  // 1/sqrt(512)/TEMP

    // ---- fork 0: write-path-only prep on s2 ----
    cudaEventRecord(eF0, 0);
    cudaStreamWaitEvent(s2, eF0, 0);
    cudaMemsetAsync(pPk, 0, BWN * sizeof(unsigned long long), s2);
    transpose_split<<<dim3(KD_/32, KD_/32), 256, 0, s2>>>(Wg, (bf16*)pWgTh, (bf16*)pWgTl,
                                                          nullptr, KD_, KD_);
    transpose_split<<<dim3(KD_/32, KD_/32), 256, 0, s2>>>(Wg + (size_t)KD_ * KD_,
                                                          (bf16*)pWgBh, (bf16*)pWgBl,
                                                          (bf16*)pWB16, KD_, KD_);
    cudaMemcpyAsync(out_k, mem_keys,   (size_t)MEMN * KD_ * sizeof(float),
                    cudaMemcpyDeviceToDevice, s2);
    cudaMemcpyAsync(out_v, mem_values, (size_t)MEMN * KD_ * sizeof(float),
                    cudaMemcpyDeviceToDevice, s2);

    // ---- main stream: shared + read-path prep ----
    cudaMemsetAsync(pRsum, 0, RQ * sizeof(float));
    mem_prep<<<MEMN, 256>>>(mem_keys, (bf16*)pMNh, (bf16*)pMNl, (__half*)pMK16);
    wk_prep<<<BWN, 256>>>(write_keys, (bf16*)pKNh, (bf16*)pKNl, (bf16*)pGAh, (bf16*)pGAl);
    cudaEventRecord(eF1, 0);                 // sim inputs ready
    transpose_half<<<dim3((HH*KD_)/32, KD_/32), 256>>>(Wq, (__half*)pWqT16, KD_, HH*KD_);
    transpose_half<<<dim3(KD_/32, (HH*KD_)/32), 256>>>(Wvp, (__half*)pWvpT16, HH*KD_, KD_);
    transpose_half<<<dim3(KD_/32, MEMN/32),     256>>>(mem_values, (__half*)pMVT16, MEMN, KD_);
    cvt_half<<<(RB*KD_/2 + 255)/256, 256>>>(queries, (__half*)pQI16, RB*KD_);

    // ---- write path on s2 (overlaps read-path GEMMs) ----
    cudaStreamWaitEvent(s2, eF1, 0);
    bgemm3<3><<<dim3(MEMN/TN, BWN/TM3), 256, DYN3, s2>>>(
        (bf16*)pKNh, (bf16*)pKNl, (bf16*)pMNh, (bf16*)pMNl,
        nullptr, nullptr, (unsigned long long*)pPk, BWN, MEMN, KD_, 1.0f);
    gather_unpack<<<BWN, 256, 0, s2>>>((unsigned long long*)pPk, mem_values, (int*)pIdx,
                                       (bf16*)pGAh, (bf16*)pGAl);
    bgemm3s<<<dim3(KD_/TNS, (2*BWN)/TMS), 128, DYNS, s2>>>(
        (bf16*)pGAh, (bf16*)pGAl,
        (bf16*)pWgTh, (bf16*)pWgTl, (bf16*)pWgBh, (bf16*)pWgBl,
        bg, (float*)pA, (float*)pBV);
    chain_update<<<MEMN, 256, 0, s2>>>(write_keys, write_vals, (const uint32_t*)pWB16,
                                       (float*)pA, (float*)pBV,
                                       (int*)pIdx, mem_keys, mem_values, out_k, out_v);
    cudaEventRecord(eJ, s2);

    // ---- read path on main stream ----
    hgemm1<1,4><<<dim3((HH*KD_)/TN, RB/256), 256, DYN1_256>>>(
        (__half*)pQI16, (__half*)pWqT16, bq, nullptr, (__half*)pQ16,
        nullptr, nullptr, RB, HH*KD_, KD_, qscale);
    hgemm1<5,4><<<dim3(MEMN/TN, RQ/256), 256, DYN1_256>>>(
        (__half*)pQ16, (__half*)pMK16, nullptr, nullptr, (__half*)pP16,
        nullptr, (float*)pRsum, RQ, MEMN, KD_, 1.0f);
    hgemm1<2,4><<<dim3(KD_/TN, RQ/256), 256, DYN1_256>>>(
        (__half*)pP16, (__half*)pMVT16, nullptr, nullptr, (__half*)pRV16,
        (float*)pRsum, nullptr, RQ, KD_, MEMN, 1.0f);
    hgemm1<0,2><<<dim3(KD_/TN, RB/128), 128, DYN1_128>>>(
        (__half*)pRV16, (__half*)pWvpT16, bvp, out_read, nullptr,
        nullptr, nullptr, RB, KD_, HH*KD_, 1.0f);

    // ---- join ----
    cudaStreamWaitEvent(0, eJ, 0);
}